// round 12
// baseline (speedup 1.0000x reference)
#include <cuda_runtime.h>
#include <cuda_fp16.h>
#include <cstdint>

#define NBLK 128

// ---------------- device scratch (no allocations allowed) ----------------
__device__ float g_gi [2048 * 1536];   // reused: gi_e0 -> gi_dec_emb
__device__ float g_enc[2048 * 512];    // encoder outputs [b][s][512]
__device__ float g_U  [2048 * 512];    // enc part of attn energy [b][s][512]
__device__ float g_H1 [2048 * 512];    // decoder top hidden per step [t][b][512]
__device__ float g_hA [2 * 32 * 512];  // layer0 / decoder h0 (ping-pong)
__device__ float g_hB [2 * 32 * 512];  // layer1 / decoder h1 (ping-pong)
__device__ float g_q  [32 * 512];
__device__ float g_ctx[32 * 512];
__device__ int   g_idx[2048];
__device__ unsigned g_cnt;             // grid barrier epoch counter
// logits fp16 operand tiles (SW128-swizzled, 16KB per 128x64 tile)
__device__ __half g_W_f16 [32000 * 512];   // W_out single fp16
__device__ __half g_Ah_f16[2048 * 512];    // H1 hi
__device__ __half g_Al_f16[2048 * 512];    // H1 lo
// encoder MMA operands: per-block B (weights, hi/lo) + ping-pong A (state)
__device__ __half g_B0h[128 * 8192],  g_B0l[128 * 8192];   // L0: 16 rows x 512 k
__device__ __half g_B1h[128 * 16384], g_B1l[128 * 16384];  // L1: 16 rows x 1024 k
__device__ __half g_A0h[2 * 16384],   g_A0l[2 * 16384];    // h0: 32 x 512
__device__ __half g_A1h[2 * 32768],   g_A1l[2 * 32768];    // [y0;h1]: 32 x 1024

// ---------------- grid-wide barrier (all NBLK blocks resident) ----------
__device__ __forceinline__ void grid_bar(unsigned &eps) {
    __syncthreads();
    if (threadIdx.x == 0) {
        eps += 1u;
        const unsigned need = eps * NBLK;
        __threadfence();
        atomicAdd(&g_cnt, 1u);
        unsigned v;
        do {
            asm volatile("ld.acquire.gpu.global.u32 %0, [%1];"
                         : "=r"(v) : "l"(&g_cnt));
        } while (v < need);
    }
    __syncthreads();
}

__device__ __forceinline__ float sigm(float x) { return 1.f / (1.f + expf(-x)); }

__device__ __forceinline__ uint32_t smem_u32(const void* p) {
    uint32_t a;
    asm("{ .reg .u64 t; cvta.to.shared.u64 t, %1; cvt.u32.u64 %0, t; }"
        : "=r"(a) : "l"(p));
    return a;
}
#define SWZ128(off) ((off) ^ (((off) >> 3) & 0x70))

__device__ __forceinline__ void ldmx4(uint32_t* t, uint32_t addr) {
    asm volatile("ldmatrix.sync.aligned.m8n8.x4.shared.b16 {%0,%1,%2,%3}, [%4];"
                 : "=r"(t[0]), "=r"(t[1]), "=r"(t[2]), "=r"(t[3]) : "r"(addr));
}
__device__ __forceinline__ void mma_f16(float* d, const uint32_t* a, const uint32_t* b) {
    asm volatile(
        "mma.sync.aligned.m16n8k16.row.col.f32.f16.f16.f32 "
        "{%0,%1,%2,%3}, {%4,%5,%6,%7}, {%8,%9}, {%0,%1,%2,%3};"
        : "+f"(d[0]), "+f"(d[1]), "+f"(d[2]), "+f"(d[3])
        : "r"(a[0]), "r"(a[1]), "r"(a[2]), "r"(a[3]), "r"(b[0]), "r"(b[1]));
}
__device__ __forceinline__ void cp_async16(uint32_t dst, const void* src) {
    asm volatile("cp.async.cg.shared.global [%0], [%1], 16;"
                 :: "r"(dst), "l"(src) : "memory");
}
__device__ __forceinline__ void cp_commit() {
    asm volatile("cp.async.commit_group;" ::: "memory");
}
template <int N>
__device__ __forceinline__ void cp_wait() {
    asm volatile("cp.async.wait_group %0;" :: "n"(N) : "memory");
}

// ---------------- gather index builder ----------------
__global__ void build_idx_kernel(const int* __restrict__ in_seq,
                                 const int* __restrict__ tg_seq,
                                 int* __restrict__ idx, int mode) {
    int m = blockIdx.x * 256 + threadIdx.x;
    if (m >= 2048) return;
    int b = m & 31, t = m >> 5;
    if (mode == 0) idx[m] = in_seq[b * 64 + t];
    else           idx[m] = (t == 0) ? 0 : tg_seq[b * 64 + t - 1];
}

// ------- f32 -> fp16 single into SW128 swizzled 128x64 tiles --------------
__global__ __launch_bounds__(256)
void convert_single_f16_kernel(const float* __restrict__ src,
                               char* __restrict__ dst) {
    const int tid = threadIdx.x;
    const int rb = blockIdx.x * 128;
    const int kc = blockIdx.y * 64;
    const size_t tb = ((size_t)blockIdx.x * 8 + blockIdx.y) * 16384;
#pragma unroll
    for (int it = 0; it < 8; it++) {
        const int idx = tid + it * 256;
        const int r  = idx >> 4;
        const int c4 = idx & 15;
        float4 v = *(const float4*)(src + (size_t)(rb + r) * 512 + kc + c4 * 4);
        __half2 h01 = __floats2half2_rn(v.x, v.y);
        __half2 h23 = __floats2half2_rn(v.z, v.w);
        const uint32_t sw = SWZ128((uint32_t)(r * 128 + (c4 >> 1) * 16)) + (c4 & 1) * 8;
        *(__half2*)(dst + tb + sw)     = h01;
        *(__half2*)(dst + tb + sw + 4) = h23;
    }
}

// ------- f32 -> fp16 hi/lo split into SW128 swizzled 128x64 tiles ---------
__global__ __launch_bounds__(256)
void convert_dual_f16_kernel(const float* __restrict__ src,
                             char* __restrict__ dsthi, char* __restrict__ dstlo) {
    const int tid = threadIdx.x;
    const int rb = blockIdx.x * 128;
    const int kc = blockIdx.y * 64;
    const size_t tb = ((size_t)blockIdx.x * 8 + blockIdx.y) * 16384;
#pragma unroll
    for (int it = 0; it < 8; it++) {
        const int idx = tid + it * 256;
        const int r  = idx >> 4;
        const int c4 = idx & 15;
        float4 v = *(const float4*)(src + (size_t)(rb + r) * 512 + kc + c4 * 4);
        __half2 h01 = __floats2half2_rn(v.x, v.y);
        __half2 h23 = __floats2half2_rn(v.z, v.w);
        __half2 l01 = __floats2half2_rn(v.x - __half2float(h01.x),
                                        v.y - __half2float(h01.y));
        __half2 l23 = __floats2half2_rn(v.z - __half2float(h23.x),
                                        v.w - __half2float(h23.y));
        const uint32_t sw = SWZ128((uint32_t)(r * 128 + (c4 >> 1) * 16)) + (c4 & 1) * 8;
        *(__half2*)(dsthi + tb + sw)     = h01;
        *(__half2*)(dsthi + tb + sw + 4) = h23;
        *(__half2*)(dstlo + tb + sw)     = l01;
        *(__half2*)(dstlo + tb + sw + 4) = l23;
    }
}

// ------- encoder weight conversions: per-block 16-row B tiles --------------
// B0 rows: 0-3 Wh0_r, 4-7 Wh0_z, 8-11 Wh0_n, 12-15 zero. K=512.
__global__ __launch_bounds__(256)
void conv_B0_kernel(const float* __restrict__ Wh0,
                    __half* __restrict__ Bh, __half* __restrict__ Bl) {
    const int blk = blockIdx.x, jbase = blk * 4;
    for (int idx = threadIdx.x; idx < 8192; idx += 256) {
        const int rr = idx >> 9, k = idx & 511;
        float wv = 0.f;
        if (rr < 12)
            wv = Wh0[(size_t)((rr >> 2) * 512 + jbase + (rr & 3)) * 512 + k];
        __half hi = __float2half_rn(wv);
        __half lo = __float2half_rn(wv - __half2float(hi));
        const uint32_t off = (uint32_t)(rr * 128 + (k & 63) * 2);
        const uint32_t sw = SWZ128(off & ~15u) + (off & 15u);
        const size_t d = (size_t)blk * 8192 + (k >> 6) * 1024 + (sw >> 1);
        Bh[d] = hi; Bl[d] = lo;
    }
}

// B1 rows (K=1024, k<512 = x-part from Wx1, k>=512 = h-part from Wh1):
// 0-3 [Wx1_r;Wh1_r], 4-7 [Wx1_z;Wh1_z], 8-11 [Wx1_n;0], 12-15 [0;Wh1_n]
__global__ __launch_bounds__(256)
void conv_B1_kernel(const float* __restrict__ Wx1, const float* __restrict__ Wh1,
                    __half* __restrict__ Bh, __half* __restrict__ Bl) {
    const int blk = blockIdx.x, jbase = blk * 4;
    for (int idx = threadIdx.x; idx < 16384; idx += 256) {
        const int rr = idx >> 10, k = idx & 1023;
        float wv = 0.f;
        if (rr < 4) {
            const int row = jbase + rr;
            wv = (k < 512) ? Wx1[(size_t)row * 512 + k] : Wh1[(size_t)row * 512 + k - 512];
        } else if (rr < 8) {
            const int row = 512 + jbase + (rr - 4);
            wv = (k < 512) ? Wx1[(size_t)row * 512 + k] : Wh1[(size_t)row * 512 + k - 512];
        } else if (rr < 12) {
            const int row = 1024 + jbase + (rr - 8);
            wv = (k < 512) ? Wx1[(size_t)row * 512 + k] : 0.f;
        } else {
            const int row = 1024 + jbase + (rr - 12);
            wv = (k >= 512) ? Wh1[(size_t)row * 512 + k - 512] : 0.f;
        }
        __half hi = __float2half_rn(wv);
        __half lo = __float2half_rn(wv - __half2float(hi));
        const uint32_t off = (uint32_t)(rr * 128 + (k & 63) * 2);
        const uint32_t sw = SWZ128(off & ~15u) + (off & 15u);
        const size_t d = (size_t)blk * 16384 + (k >> 6) * 1024 + (sw >> 1);
        Bh[d] = hi; Bl[d] = lo;
    }
}

// ---------------- SGEMM-NT: C[M,N] = A[M,K] * B[N,K]^T (+bias) ------------
__global__ __launch_bounds__(256)
void gemm_nt_kernel(const float* __restrict__ A, int lda,
                    const float* __restrict__ Bm, int ldb,
                    const float* __restrict__ bias,
                    float* __restrict__ C, int N, int K,
                    const int* __restrict__ gidx, int outmode) {
    const int tid = threadIdx.x;
    const int bn = blockIdx.x * 128;
    const int bm = blockIdx.y * 128;
    __shared__ float As[2][16][132];
    __shared__ float Bs[2][16][132];
    const int tx = tid & 15, ty = tid >> 4;
    float acc[8][8];
#pragma unroll
    for (int i = 0; i < 8; i++)
#pragma unroll
        for (int j = 0; j < 8; j++) acc[i][j] = 0.f;

    const int lrow = tid >> 1;
    const int lk   = (tid & 1) * 8;
    int arow = gidx ? gidx[bm + lrow] : (bm + lrow);
    const float* Ap = A  + (size_t)arow        * lda + lk;
    const float* Bp = Bm + (size_t)(bn + lrow) * ldb + lk;

    {
        float4 a0 = *(const float4*)(Ap);
        float4 a1 = *(const float4*)(Ap + 4);
        float4 b0 = *(const float4*)(Bp);
        float4 b1 = *(const float4*)(Bp + 4);
        As[0][lk+0][lrow]=a0.x; As[0][lk+1][lrow]=a0.y; As[0][lk+2][lrow]=a0.z; As[0][lk+3][lrow]=a0.w;
        As[0][lk+4][lrow]=a1.x; As[0][lk+5][lrow]=a1.y; As[0][lk+6][lrow]=a1.z; As[0][lk+7][lrow]=a1.w;
        Bs[0][lk+0][lrow]=b0.x; Bs[0][lk+1][lrow]=b0.y; Bs[0][lk+2][lrow]=b0.z; Bs[0][lk+3][lrow]=b0.w;
        Bs[0][lk+4][lrow]=b1.x; Bs[0][lk+5][lrow]=b1.y; Bs[0][lk+6][lrow]=b1.z; Bs[0][lk+7][lrow]=b1.w;
    }
    __syncthreads();
    int buf = 0;
    for (int kc = 0; kc < K; kc += 16) {
        if (kc + 16 < K) {
            float4 a0 = *(const float4*)(Ap + kc + 16);
            float4 a1 = *(const float4*)(Ap + kc + 20);
            float4 b0 = *(const float4*)(Bp + kc + 16);
            float4 b1 = *(const float4*)(Bp + kc + 20);
            const int nb = buf ^ 1;
            As[nb][lk+0][lrow]=a0.x; As[nb][lk+1][lrow]=a0.y; As[nb][lk+2][lrow]=a0.z; As[nb][lk+3][lrow]=a0.w;
            As[nb][lk+4][lrow]=a1.x; As[nb][lk+5][lrow]=a1.y; As[nb][lk+6][lrow]=a1.z; As[nb][lk+7][lrow]=a1.w;
            Bs[nb][lk+0][lrow]=b0.x; Bs[nb][lk+1][lrow]=b0.y; Bs[nb][lk+2][lrow]=b0.z; Bs[nb][lk+3][lrow]=b0.w;
            Bs[nb][lk+4][lrow]=b1.x; Bs[nb][lk+5][lrow]=b1.y; Bs[nb][lk+6][lrow]=b1.z; Bs[nb][lk+7][lrow]=b1.w;
        }
#pragma unroll
        for (int kk = 0; kk < 16; kk++) {
            float4 alo = *(const float4*)&As[buf][kk][ty * 4];
            float4 ahi = *(const float4*)&As[buf][kk][64 + ty * 4];
            float4 blo = *(const float4*)&Bs[buf][kk][tx * 4];
            float4 bhi = *(const float4*)&Bs[buf][kk][64 + tx * 4];
            float a[8] = {alo.x, alo.y, alo.z, alo.w, ahi.x, ahi.y, ahi.z, ahi.w};
            float b[8] = {blo.x, blo.y, blo.z, blo.w, bhi.x, bhi.y, bhi.z, bhi.w};
#pragma unroll
            for (int i = 0; i < 8; i++)
#pragma unroll
                for (int j = 0; j < 8; j++)
                    acc[i][j] = fmaf(a[i], b[j], acc[i][j]);
        }
        __syncthreads();
        buf ^= 1;
    }
#pragma unroll
    for (int i = 0; i < 8; i++) {
        const int m = bm + ((i < 4) ? (ty * 4 + i) : (64 + ty * 4 + i - 4));
        const int orow = (outmode == 1) ? ((m & 31) * 64 + (m >> 5)) : m;
        float* crow = C + (size_t)orow * N;
#pragma unroll
        for (int j = 0; j < 8; j++) {
            const int n = bn + ((j < 4) ? (tx * 4 + j) : (64 + tx * 4 + j - 4));
            float v = acc[i][j];
            if (bias) v += bias[n];
            crow[n] = v;
        }
    }
}

// ====== logits GEMM: fp16 mma.sync, A hi/lo split, B single (2-pass) ======
#define LM_TOT 98304

__global__ __launch_bounds__(256, 2)
void logits_mma_kernel(const char* __restrict__ Ah, const char* __restrict__ Al,
                       const char* __restrict__ Bw,
                       const float* __restrict__ bias,
                       float* __restrict__ out) {
    extern __shared__ char smem[];
    const uint32_t sb = smem_u32(smem);
    const int tid  = threadIdx.x;
    const int wid  = tid >> 5;
    const int lane = tid & 31;
    const int mt = blockIdx.y;
    const int nt = blockIdx.x;
    const int bm = mt * 128;
    const int bn = nt * 128;
    const int wm = (wid & 3) * 32;
    const int wn = (wid >> 2) * 64;

    float acc[2][8][4];
#pragma unroll
    for (int mi = 0; mi < 2; mi++)
#pragma unroll
        for (int ni = 0; ni < 8; ni++)
#pragma unroll
            for (int e = 0; e < 4; e++) acc[mi][ni][e] = 0.f;

    const int lrow = lane & 15;
    const int lcol16 = lane >> 4;

    auto prefetch = [&](int ch, int buf) {
        const char* srcs[3] = {
            Ah + ((size_t)mt * 8 + ch) * 16384,
            Al + ((size_t)mt * 8 + ch) * 16384,
            Bw + ((size_t)nt * 8 + ch) * 16384 };
#pragma unroll
        for (int t = 0; t < 3; t++) {
            const char* s = srcs[t] + tid * 16;
            const uint32_t d = sb + buf * 49152 + t * 16384 + tid * 16;
#pragma unroll
            for (int i = 0; i < 4; i++)
                cp_async16(d + i * 4096, s + i * 4096);
        }
        cp_commit();
    };

    prefetch(0, 0);
    int buf = 0;
    for (int ch = 0; ch < 8; ch++) {
        if (ch < 7) {
            prefetch(ch + 1, buf ^ 1);
            cp_wait<1>();
        } else {
            cp_wait<0>();
        }
        __syncthreads();

        const uint32_t base = sb + buf * 49152;
#pragma unroll
        for (int ks = 0; ks < 4; ks++) {
            uint32_t ah[2][4], al[2][4];
#pragma unroll
            for (int mi = 0; mi < 2; mi++) {
                const uint32_t off =
                    SWZ128((uint32_t)((wm + mi * 16 + lrow) * 128 + ks * 32 + lcol16 * 16));
                ldmx4(ah[mi], base + off);
                ldmx4(al[mi], base + 16384 + off);
            }
            uint32_t bw[8][2];
#pragma unroll
            for (int nj = 0; nj < 4; nj++) {
                const uint32_t off =
                    SWZ128((uint32_t)((wn + nj * 16 + lrow) * 128 + ks * 32 + lcol16 * 16));
                uint32_t t[4];
                ldmx4(t, base + 32768 + off);
                bw[nj*2][0] = t[0]; bw[nj*2+1][0] = t[1];
                bw[nj*2][1] = t[2]; bw[nj*2+1][1] = t[3];
            }
#pragma unroll
            for (int mi = 0; mi < 2; mi++)
#pragma unroll
                for (int ni = 0; ni < 8; ni++) {
                    mma_f16(acc[mi][ni], ah[mi], bw[ni]);
                    mma_f16(acc[mi][ni], al[mi], bw[ni]);
                }
        }
        __syncthreads();
        buf ^= 1;
    }

#pragma unroll
    for (int mi = 0; mi < 2; mi++) {
        const int m0 = bm + wm + mi * 16 + (lane >> 2);
        const int m1 = m0 + 8;
        const int or0 = (m0 & 31) * 64 + (m0 >> 5);
        const int or1 = (m1 & 31) * 64 + (m1 >> 5);
#pragma unroll
        for (int ni = 0; ni < 8; ni++) {
            const int n = bn + wn + ni * 8 + (lane & 3) * 2;
            const float b0 = bias[n], b1 = bias[n + 1];
            float2 v0 = make_float2(acc[mi][ni][0] + b0, acc[mi][ni][1] + b1);
            float2 v1 = make_float2(acc[mi][ni][2] + b0, acc[mi][ni][3] + b1);
            *(float2*)(out + (size_t)or0 * 32000 + n) = v0;
            *(float2*)(out + (size_t)or1 * 32000 + n) = v1;
        }
    }
}

// ================= encoder: per-block MMA GRU cells =======================
// smem layout (dynamic):
#define ESM_B0H 0
#define ESM_B0L 16384
#define ESM_B1H 32768
#define ESM_B1L 65536
#define ESM_A   98304
#define ESM_RED 163840
#define ESM_G   165888
#define ESM_TOT 167936

// C[32 b][16 rows] = A[32 x K] @ B[16 x K]^T, K = NT*16.
// 8 warps: tile = w&3 -> (mi, ni), khalf = w>>2. A streamed in 256-k
// chunkpairs (double-buffered cp.async); B resident in smem. Result in
// f32 at smem ESM_G as G[b*16 + row].
template<int NT>
__device__ __forceinline__ void mma_accum(char* smem, uint32_t sb,
                                          uint32_t smBh, uint32_t smBl,
                                          const __half* gAh, const __half* gAl)
{
    const int tid = threadIdx.x;
    const int w = tid >> 5, lane = tid & 31;
    const int tile = w & 3, kh = w >> 2;
    const int mi = tile >> 1, ni = tile & 1;
    const int lrow = lane & 15, lc16 = lane >> 4;
    const uint32_t smA = sb + ESM_A;
    float acc[4] = {0.f, 0.f, 0.f, 0.f};
    constexpr int NCP = NT / 4;

    auto loadA = [&](int cp, int abuf) {
        const char* sh = (const char*)(gAh + (size_t)cp * 8192);
        const char* sl = (const char*)(gAl + (size_t)cp * 8192);
        const uint32_t d = smA + abuf * 32768 + tid * 16;
#pragma unroll
        for (int i = 0; i < 4; i++) {
            cp_async16(d + i * 4096,         sh + tid * 16 + i * 4096);
            cp_async16(d + 16384 + i * 4096, sl + tid * 16 + i * 4096);
        }
        cp_commit();
    };

    loadA(0, 0);
    for (int cp = 0; cp < NCP; cp++) {
        if (cp + 1 < NCP) { loadA(cp + 1, (cp + 1) & 1); cp_wait<1>(); }
        else              { cp_wait<0>(); }
        __syncthreads();
        const uint32_t abase = smA + (cp & 1) * 32768;
#pragma unroll
        for (int ks = 0; ks < 8; ks++) {
            const int lt = kh * 2 + (ks >> 2);
            const int gt = cp * 4 + lt;
            const uint32_t aoff =
                SWZ128((uint32_t)((mi * 16 + lrow) * 128 + (ks & 3) * 32 + lc16 * 16));
            uint32_t ah[4], al[4];
            ldmx4(ah, abase + lt * 4096 + aoff);
            ldmx4(al, abase + 16384 + lt * 4096 + aoff);
            const uint32_t boff =
                SWZ128((uint32_t)(lrow * 128 + (ks & 3) * 32 + lc16 * 16));
            uint32_t tbh[4], tbl[4];
            ldmx4(tbh, smBh + gt * 2048 + boff);
            ldmx4(tbl, smBl + gt * 2048 + boff);
            uint32_t bh[2] = {tbh[ni], tbh[ni + 2]};
            uint32_t bl[2] = {tbl[ni], tbl[ni + 2]};
            mma_f16(acc, ah, bh);
            mma_f16(acc, al, bh);
            mma_f16(acc, ah, bl);
        }
        __syncthreads();
    }
    // combine k-halves, then scatter to gate grid
    if (kh == 1)
        *(float4*)(smem + ESM_RED + tile * 512 + lane * 16) =
            make_float4(acc[0], acc[1], acc[2], acc[3]);
    __syncthreads();
    if (kh == 0) {
        float4 o = *(const float4*)(smem + ESM_RED + tile * 512 + lane * 16);
        acc[0] += o.x; acc[1] += o.y; acc[2] += o.z; acc[3] += o.w;
        float* G = (float*)(smem + ESM_G);
        const int row = mi * 16 + (lane >> 2);
        const int col = ni * 8 + (lane & 3) * 2;
        G[row * 16 + col]           = acc[0];
        G[row * 16 + col + 1]       = acc[1];
        G[(row + 8) * 16 + col]     = acc[2];
        G[(row + 8) * 16 + col + 1] = acc[3];
    }
    __syncthreads();
}

__global__ __launch_bounds__(256, 1)
void enc_mma_kernel(const float* __restrict__ bh0,
                    const float* __restrict__ bx1,
                    const float* __restrict__ bh1) {
    extern __shared__ char smem[];
    const uint32_t sb = smem_u32(smem);
    const int tid = threadIdx.x;
    const int blk = blockIdx.x;
    const int jbase = blk * 4;

    // prologue: load this block's weight tiles (96 KB) into smem, once
    {
        const char* s0h = (const char*)(g_B0h + (size_t)blk * 8192);
        const char* s0l = (const char*)(g_B0l + (size_t)blk * 8192);
        const char* s1h = (const char*)(g_B1h + (size_t)blk * 16384);
        const char* s1l = (const char*)(g_B1l + (size_t)blk * 16384);
#pragma unroll
        for (int i = 0; i < 4; i++) {
            cp_async16(sb + ESM_B0H + tid * 16 + i * 4096, s0h + tid * 16 + i * 4096);
            cp_async16(sb + ESM_B0L + tid * 16 + i * 4096, s0l + tid * 16 + i * 4096);
        }
#pragma unroll
        for (int i = 0; i < 8; i++) {
            cp_async16(sb + ESM_B1H + tid * 16 + i * 4096, s1h + tid * 16 + i * 4096);
            cp_async16(sb + ESM_B1L + tid * 16 + i * 4096, s1l + tid * 16 + i * 4096);
        }
        cp_commit(); cp_wait<0>(); __syncthreads();
    }

    unsigned eps = 0;
    for (int s = 0; s < 65; s++) {
        const int q = s & 1, nq = q ^ 1;
        if (s < 64) {
            // layer0 step s: C = h0(s) @ B0^T
            mma_accum<8>(smem, sb, sb + ESM_B0H, sb + ESM_B0L,
                         g_A0h + (size_t)q * 16384, g_A0l + (size_t)q * 16384);
            if (tid < 128) {
                const int b = tid & 31, jl = tid >> 5;
                const int j = jbase + jl;
                const float* G = (const float*)(smem + ESM_G);
                const float Cr = G[b * 16 + jl];
                const float Cz = G[b * 16 + 4 + jl];
                const float Cnh = G[b * 16 + 8 + jl];
                const float* gp = g_gi + (size_t)s * 49152 + b * 1536;
                float r = sigm(gp[j] + Cr + bh0[j]);
                float z = sigm(gp[512 + j] + Cz + bh0[512 + j]);
                float n = tanhf(gp[1024 + j] + r * (Cnh + bh0[1024 + j]));
                float hp = __ldcg(g_hA + q * 16384 + b * 512 + j);
                float hn = (1.f - z) * n + z * hp;
                g_hA[nq * 16384 + b * 512 + j] = hn;
                __half hi = __float2half_rn(hn);
                __half lo = __float2half_rn(hn - __half2float(hi));
                const uint32_t off = (uint32_t)(b * 128 + (j & 63) * 2);
                const uint32_t sw = SWZ128(off & ~15u) + (off & 15u);
                const size_t a0 = (size_t)nq * 16384 + (j >> 6) * 2048 + (sw >> 1);
                g_A0h[a0] = hi; g_A0l[a0] = lo;           // h0 state
                const size_t a1 = (size_t)nq * 32768 + (j >> 6) * 2048 + (sw >> 1);
                g_A1h[a1] = hi; g_A1l[a1] = lo;           // y0[s] (same value)
            }
            __syncthreads();
        }
        if (s >= 1) {
            // layer1 step t1 = s-1: C = [y0(t1); h1(t1)] @ B1^T
            const int t1 = s - 1, p1 = t1 & 1;
            mma_accum<16>(smem, sb, sb + ESM_B1H, sb + ESM_B1L,
                          g_A1h + (size_t)q * 32768, g_A1l + (size_t)q * 32768);
            if (tid < 128) {
                const int b = tid & 31, jl = tid >> 5;
                const int j = jbase + jl;
                const float* G = (const float*)(smem + ESM_G);
                const float Cr  = G[b * 16 + jl];
                const float Cz  = G[b * 16 + 4 + jl];
                const float Cnx = G[b * 16 + 8 + jl];
                const float Cnh = G[b * 16 + 12 + jl];
                float r = sigm(bx1[j] + Cr + bh1[j]);
                float z = sigm(bx1[512 + j] + Cz + bh1[512 + j]);
                float n = tanhf(bx1[1024 + j] + Cnx + r * (Cnh + bh1[1024 + j]));
                float hp = __ldcg(g_hB + p1 * 16384 + b * 512 + j);
                float hn = (1.f - z) * n + z * hp;
                g_hB[(p1 ^ 1) * 16384 + b * 512 + j] = hn;
                g_enc[(size_t)b * 32768 + t1 * 512 + j] = hn;
                __half hi = __float2half_rn(hn);
                __half lo = __float2half_rn(hn - __half2float(hi));
                const uint32_t off = (uint32_t)(b * 128 + (j & 63) * 2);
                const uint32_t sw = SWZ128(off & ~15u) + (off & 15u);
                const size_t a1 = (size_t)nq * 32768 + (8 + (j >> 6)) * 2048 + (sw >> 1);
                g_A1h[a1] = hi; g_A1l[a1] = lo;           // h1 state
            }
            __syncthreads();
        }
        grid_bar(eps);
    }
}

// ---------------- register-blocked GRU machinery (decoder) ----------------
struct Part {
    const float* W;
    int ldW;
    int wco;
    const float* src;
};

template<int NP, bool XSEC>
__device__ __forceinline__ void accum_section(
    float (&acc)[12][4], float (&accx)[4][4],
    Part P, int jbase, int b0, int lane)
{
    const float* Wb = P.W + P.wco;
#pragma unroll
    for (int ps = 0; ps < NP; ps++) {
        const int k = ps * 128 + lane * 4;
        float4 s[4];
#pragma unroll
        for (int bi = 0; bi < 4; bi++)
            s[bi] = __ldcg((const float4*)(P.src + (b0 + bi) * 512 + k));
#pragma unroll
        for (int r = 0; r < 12; r++) {
            const int row = (r >> 2) * 512 + jbase + (r & 3);
            float4 wv = *(const float4*)(Wb + (size_t)row * P.ldW + k);
            float* a = (XSEC && r >= 8) ? accx[r - 8] : acc[r];
#pragma unroll
            for (int bi = 0; bi < 4; bi++) {
                a[bi] = fmaf(s[bi].x, wv.x, a[bi]);
                a[bi] = fmaf(s[bi].y, wv.y, a[bi]);
                a[bi] = fmaf(s[bi].z, wv.z, a[bi]);
                a[bi] = fmaf(s[bi].w, wv.w, a[bi]);
            }
        }
    }
}

template<int NP0, int NP1, int MODE>  // MODE: 1=gi_pre+x, 2=bx+x
__device__ __forceinline__ void gru_phase(
    int jbase, Part p0, Part p1,
    const float* __restrict__ gi_pre, const float* __restrict__ bx,
    const float* __restrict__ bh, const float* __restrict__ hprev,
    float* __restrict__ hnext, float* __restrict__ yout, int yb)
{
    const int lane = threadIdx.x & 31;
    const int w    = threadIdx.x >> 5;
    const int b0   = w * 4;
    float acc[12][4];
    float accx[4][4];
#pragma unroll
    for (int r = 0; r < 12; r++)
#pragma unroll
        for (int bi = 0; bi < 4; bi++) acc[r][bi] = 0.f;
#pragma unroll
    for (int r = 0; r < 4; r++)
#pragma unroll
        for (int bi = 0; bi < 4; bi++) accx[r][bi] = 0.f;

    accum_section<NP0, false>(acc, accx, p0, jbase, b0, lane);
    if (NP1 > 0) accum_section<NP1, true>(acc, accx, p1, jbase, b0, lane);

#pragma unroll
    for (int r = 0; r < 12; r++)
#pragma unroll
        for (int bi = 0; bi < 4; bi++)
#pragma unroll
            for (int o = 16; o; o >>= 1)
                acc[r][bi] += __shfl_xor_sync(0xffffffffu, acc[r][bi], o);
    if (NP1 > 0) {
#pragma unroll
        for (int r = 0; r < 4; r++)
#pragma unroll
            for (int bi = 0; bi < 4; bi++)
#pragma unroll
                for (int o = 16; o; o >>= 1)
                    accx[r][bi] += __shfl_xor_sync(0xffffffffu, accx[r][bi], o);
    }

    if (lane < 4) {
        const int jl = lane, j = jbase + jl;
        const float bh0 = bh[j], bh1 = bh[512 + j], bh2 = bh[1024 + j];
#pragma unroll
        for (int bi = 0; bi < 4; bi++) {
            const int b = b0 + bi;
            float pr, pz, gin, ghn;
            if (MODE == 1) {
                pr  = gi_pre[b * 1536 + j]        + acc[jl][bi]     + bh0;
                pz  = gi_pre[b * 1536 + 512 + j]  + acc[4 + jl][bi] + bh1;
                gin = gi_pre[b * 1536 + 1024 + j] + accx[jl][bi];
                ghn = acc[8 + jl][bi] + bh2;
            } else {
                pr  = bx[j]        + acc[jl][bi]     + bh0;
                pz  = bx[512 + j]  + acc[4 + jl][bi] + bh1;
                gin = bx[1024 + j] + accx[jl][bi];
                ghn = acc[8 + jl][bi] + bh2;
            }
            float r = sigm(pr);
            float z = sigm(pz);
            float n = tanhf(gin + r * ghn);
            float hp = __ldcg(hprev + b * 512 + j);
            float hn = (1.f - z) * n + z * hp;
            hnext[b * 512 + j] = hn;
            if (yout) yout[b * yb + j] = hn;
        }
    }
}

// ---------------- decoder phase A: q = h1 @ W_attn[:, :512]^T ------------
__device__ __forceinline__ void phaseA(const float* __restrict__ h1,
                                       const float* __restrict__ Wa) {
    const int lane = threadIdx.x & 31;
    const int w    = threadIdx.x >> 5;
    const int b0   = w * 4;
    const int nbase = blockIdx.x * 4;
    float acc[4][4];
#pragma unroll
    for (int r = 0; r < 4; r++)
#pragma unroll
        for (int bi = 0; bi < 4; bi++) acc[r][bi] = 0.f;
#pragma unroll
    for (int ps = 0; ps < 4; ps++) {
        const int k = ps * 128 + lane * 4;
        float4 s[4];
#pragma unroll
        for (int bi = 0; bi < 4; bi++)
            s[bi] = __ldcg((const float4*)(h1 + (b0 + bi) * 512 + k));
#pragma unroll
        for (int r = 0; r < 4; r++) {
            float4 wv = *(const float4*)(Wa + (size_t)(nbase + r) * 1024 + k);
#pragma unroll
            for (int bi = 0; bi < 4; bi++) {
                acc[r][bi] = fmaf(s[bi].x, wv.x, acc[r][bi]);
                acc[r][bi] = fmaf(s[bi].y, wv.y, acc[r][bi]);
                acc[r][bi] = fmaf(s[bi].z, wv.z, acc[r][bi]);
                acc[r][bi] = fmaf(s[bi].w, wv.w, acc[r][bi]);
            }
        }
    }
#pragma unroll
    for (int r = 0; r < 4; r++)
#pragma unroll
        for (int bi = 0; bi < 4; bi++)
#pragma unroll
            for (int o = 16; o; o >>= 1)
                acc[r][bi] += __shfl_xor_sync(0xffffffffu, acc[r][bi], o);
    if (lane < 4) {
#pragma unroll
        for (int bi = 0; bi < 4; bi++)
            g_q[(b0 + bi) * 512 + nbase + lane] = acc[lane][bi];
    }
}

// ---------------- decoder phase B: scores -> softmax -> context ----------
__device__ __forceinline__ void phaseB(const float* __restrict__ v_attn) {
    __shared__ float qv[512];
    __shared__ float vv[512];
    __shared__ float sc[64];
    __shared__ float aw[64];
    const int b = blockIdx.x;
    const int tid = threadIdx.x;
    for (int i = tid; i < 512; i += 256) {
        qv[i] = __ldcg(g_q + b * 512 + i);
        vv[i] = v_attn[i];
    }
    __syncthreads();
    const int w = tid >> 5, lane = tid & 31;
    for (int ss = 0; ss < 8; ss++) {
        const int s = w * 8 + ss;
        const float* Urow = g_U + (size_t)(b * 64 + s) * 512;
        float p = 0.f;
        for (int n = lane; n < 512; n += 32)
            p += vv[n] * tanhf(qv[n] + Urow[n]);
#pragma unroll
        for (int o = 16; o; o >>= 1) p += __shfl_xor_sync(0xffffffffu, p, o);
        if (lane == 0) sc[s] = p;
    }
    __syncthreads();
    if (w == 0) {
        float v0 = sc[lane], v1 = sc[lane + 32];
        float mx = fmaxf(v0, v1);
#pragma unroll
        for (int o = 16; o; o >>= 1) mx = fmaxf(mx, __shfl_xor_sync(0xffffffffu, mx, o));
        float e0 = expf(v0 - mx), e1 = expf(v1 - mx);
        float sm = e0 + e1;
#pragma unroll
        for (int o = 16; o; o >>= 1) sm += __shfl_xor_sync(0xffffffffu, sm, o);
        float inv = 1.f / sm;
        aw[lane]      = e0 * inv;
        aw[lane + 32] = e1 * inv;
    }
    __syncthreads();
    for (int n = tid; n < 512; n += 256) {
        const float* erow = g_enc + (size_t)b * 64 * 512 + n;
        float acc = 0.f;
#pragma unroll 8
        for (int s = 0; s < 64; s++) acc = fmaf(aw[s], erow[s * 512], acc);
        g_ctx[b * 512 + n] = acc;
    }
}

// ---------------- persistent decoder (64 steps, 4 phases each) -----------
__global__ __launch_bounds__(256, 1)
void dec_persist_kernel(const float* __restrict__ Wa, const float* __restrict__ v_attn,
                        const float* __restrict__ Wh0, const float* __restrict__ Wx0,
                        const float* __restrict__ bh0,
                        const float* __restrict__ Wh1, const float* __restrict__ Wx1,
                        const float* __restrict__ bx1, const float* __restrict__ bh1) {
    unsigned eps = 0;
    const int jbase = blockIdx.x * 4;
    for (int t = 0; t < 64; t++) {
        const int par = t & 1;
        const float* h0 = g_hA + par * 16384;
        const float* h1 = g_hB + par * 16384;
        float* h0n = g_hA + (par ^ 1) * 16384;
        float* h1n = g_hB + (par ^ 1) * 16384;

        phaseA(h1, Wa);
        grid_bar(eps);

        if (blockIdx.x < 32) phaseB(v_attn);
        grid_bar(eps);

        {   // GRU d0: h-part Wh_d0, x-part ctx via Wx_d0 cols [256,768)
            Part p0{Wh0, 512, 0,   h0};
            Part p1{Wx0, 768, 256, g_ctx};
            gru_phase<4, 4, 1>(jbase, p0, p1, g_gi + (size_t)t * 49152, nullptr, bh0,
                               h0, h0n, nullptr, 0);
        }
        grid_bar(eps);

        {   // GRU d1: h-part Wh_d1, x-part h0' via Wx_d1
            Part p0{Wh1, 512, 0, h1};
            Part p1{Wx1, 512, 0, h0n};
            gru_phase<4, 4, 2>(jbase, p0, p1, nullptr, bx1, bh1,
                               h1, h1n, g_H1 + (size_t)t * 16384, 512);
        }
        grid_bar(eps);
    }
}

// ---------------- host orchestration ----------------
extern "C" void kernel_launch(void* const* d_in, const int* in_sizes, int n_in,
                              void* d_out, int out_size) {
    (void)in_sizes; (void)n_in; (void)out_size;
    const int*   in_seq = (const int*)d_in[0];
    const int*   tg_seq = (const int*)d_in[1];
    const float* E_enc  = (const float*)d_in[2];
    const float* Wx_e0  = (const float*)d_in[3];
    const float* Wh_e0  = (const float*)d_in[4];
    const float* bx_e0  = (const float*)d_in[5];
    const float* bh_e0  = (const float*)d_in[6];
    const float* Wx_e1  = (const float*)d_in[7];
    const float* Wh_e1  = (const float*)d_in[8];
    const float* bx_e1  = (const float*)d_in[9];
    const float* bh_e1  = (const float*)d_in[10];
    const float* E_dec  = (const float*)d_in[11];
    const float* W_attn = (const float*)d_in[12];
    const float* b_attn = (const float*)d_in[13];
    const float* v_attn = (const float*)d_in[14];
    const float* Wx_d0  = (const float*)d_in[15];
    const float* Wh_d0  = (const float*)d_in[16];
    const float* bx_d0  = (const float*)d_in[17];
    const float* bh_d0  = (const float*)d_in[18];
    const float* Wx_d1  = (const float*)d_in[19];
    const float* Wh_d1  = (const float*)d_in[20];
    const float* bx_d1  = (const float*)d_in[21];
    const float* bh_d1  = (const float*)d_in[22];
    const float* W_out  = (const float*)d_in[23];
    const float* b_out  = (const float*)d_in[24];
    float* out = (float*)d_out;

    float *gi, *enc, *U, *H1, *hA, *hB;
    int* idx;
    unsigned* bar;
    char *wf, *ah, *al;
    void *b0h, *b0l, *b1h, *b1l, *a0h, *a0l, *a1h, *a1l;
    cudaGetSymbolAddress((void**)&gi,  g_gi);
    cudaGetSymbolAddress((void**)&enc, g_enc);
    cudaGetSymbolAddress((void**)&U,   g_U);
    cudaGetSymbolAddress((void**)&H1,  g_H1);
    cudaGetSymbolAddress((void**)&hA,  g_hA);
    cudaGetSymbolAddress((void**)&hB,  g_hB);
    cudaGetSymbolAddress((void**)&idx, g_idx);
    cudaGetSymbolAddress((void**)&bar, g_cnt);
    cudaGetSymbolAddress((void**)&wf,  g_W_f16);
    cudaGetSymbolAddress((void**)&ah,  g_Ah_f16);
    cudaGetSymbolAddress((void**)&al,  g_Al_f16);
    cudaGetSymbolAddress(&b0h, g_B0h); cudaGetSymbolAddress(&b0l, g_B0l);
    cudaGetSymbolAddress(&b1h, g_B1h); cudaGetSymbolAddress(&b1l, g_B1l);
    cudaGetSymbolAddress(&a0h, g_A0h); cudaGetSymbolAddress(&a0l, g_A0l);
    cudaGetSymbolAddress(&a1h, g_A1h); cudaGetSymbolAddress(&a1l, g_A1l);

    cudaFuncSetAttribute(logits_mma_kernel,
                         cudaFuncAttributeMaxDynamicSharedMemorySize, LM_TOT);
    cudaFuncSetAttribute(enc_mma_kernel,
                         cudaFuncAttributeMaxDynamicSharedMemorySize, ESM_TOT);

    cudaMemsetAsync(hA, 0, 2 * 32 * 512 * sizeof(float));
    cudaMemsetAsync(hB, 0, 2 * 32 * 512 * sizeof(float));
    cudaMemsetAsync(a0h, 0, 2 * 16384 * sizeof(__half));
    cudaMemsetAsync(a0l, 0, 2 * 16384 * sizeof(__half));
    cudaMemsetAsync(a1h, 0, 2 * 32768 * sizeof(__half));
    cudaMemsetAsync(a1l, 0, 2 * 32768 * sizeof(__half));

    // ---- one-time conversions ----
    convert_single_f16_kernel<<<dim3(250, 8), 256>>>(W_out, wf);
    conv_B0_kernel<<<128, 256>>>(Wh_e0, (__half*)b0h, (__half*)b0l);
    conv_B1_kernel<<<128, 256>>>(Wx_e1, Wh_e1, (__half*)b1h, (__half*)b1l);

    // ---- encoder: gi_e0 GEMM, then fused 2-layer MMA persistent kernel ----
    build_idx_kernel<<<8, 256>>>(in_seq, tg_seq, idx, 0);
    gemm_nt_kernel<<<dim3(12, 16), 256>>>(E_enc, 256, Wx_e0, 256, bx_e0,
                                          gi, 1536, 256, idx, 0);
    cudaMemsetAsync(bar, 0, sizeof(unsigned));
    enc_mma_kernel<<<NBLK, 256, ESM_TOT>>>(bh_e0, bx_e1, bh_e1);

    // U = enc_out @ W_attn[:, 512:]^T + b_attn
    gemm_nt_kernel<<<dim3(4, 16), 256>>>(enc, 512, W_attn + 512, 1024, b_attn,
                                         U, 512, 512, nullptr, 0);
    build_idx_kernel<<<8, 256>>>(in_seq, tg_seq, idx, 1);
    gemm_nt_kernel<<<dim3(12, 16), 256>>>(E_dec, 256, Wx_d0, 768, bx_d0,
                                          gi, 1536, 256, idx, 0);

    // ---- decoder persistent loop ----
    cudaMemsetAsync(bar, 0, sizeof(unsigned));
    dec_persist_kernel<<<NBLK, 256>>>(W_attn, v_attn,
                                      Wh_d0, Wx_d0, bh_d0,
                                      Wh_d1, Wx_d1, bx_d1, bh_d1);

    // ---- convert H1 to fp16 hi/lo tiles, then logits (2-pass fp16) ----
    convert_dual_f16_kernel<<<dim3(16, 8), 256>>>(H1, ah, al);
    logits_mma_kernel<<<dim3(250, 16), 256, LM_TOT>>>(ah, al, wf, b_out, out);
}

// round 13
// speedup vs baseline: 1.0820x; 1.0820x over previous
#include <cuda_runtime.h>
#include <cuda_fp16.h>
#include <cstdint>

#define NBLK 128

// ---------------- device scratch (no allocations allowed) ----------------
__device__ float g_gi [2048 * 1536];   // reused: gi_e0 -> gi_dec_emb
__device__ float g_y0 [2048 * 512];    // encoder layer0 outputs [s][b][512]
__device__ float g_enc[2048 * 512];    // encoder outputs [b][s][512]
__device__ float g_U  [2048 * 512];    // enc part of attn energy [b][s][512]
__device__ float g_H1 [2048 * 512];    // decoder top hidden per step [t][b][512]
__device__ float g_hA [2 * 32 * 512];  // layer0 / decoder h0 (ping-pong)
__device__ float g_hB [2 * 32 * 512];  // layer1 / decoder h1 (ping-pong)
__device__ float g_q  [32 * 512];
__device__ float g_ctx[32 * 512];
__device__ float g_gh [2 * 3 * 32 * 512]; // decoder recurrent gates (+bh): [layer][gate][b][j]
__device__ int   g_idx[2048];
__device__ unsigned g_cnt;             // grid barrier epoch counter
// pre-converted fp16 operand tiles (SW128-swizzled, 16KB per 128x64 tile)
__device__ __half g_W_f16 [32000 * 512];   // W_out single fp16
__device__ __half g_Ah_f16[2048 * 512];    // H1 hi
__device__ __half g_Al_f16[2048 * 512];    // H1 lo

// ---------------- grid-wide barrier (all NBLK blocks resident) ----------
__device__ __forceinline__ void grid_bar(unsigned &eps) {
    __syncthreads();
    if (threadIdx.x == 0) {
        eps += 1u;
        const unsigned need = eps * NBLK;
        __threadfence();
        atomicAdd(&g_cnt, 1u);
        unsigned v;
        do {
            asm volatile("ld.acquire.gpu.global.u32 %0, [%1];"
                         : "=r"(v) : "l"(&g_cnt));
        } while (v < need);
    }
    __syncthreads();
}

__device__ __forceinline__ float sigm(float x) { return 1.f / (1.f + expf(-x)); }

__device__ __forceinline__ uint32_t smem_u32(const void* p) {
    uint32_t a;
    asm("{ .reg .u64 t; cvta.to.shared.u64 t, %1; cvt.u32.u64 %0, t; }"
        : "=r"(a) : "l"(p));
    return a;
}
#define SWZ128(off) ((off) ^ (((off) >> 3) & 0x70))

__device__ __forceinline__ void ldmx4(uint32_t* t, uint32_t addr) {
    asm volatile("ldmatrix.sync.aligned.m8n8.x4.shared.b16 {%0,%1,%2,%3}, [%4];"
                 : "=r"(t[0]), "=r"(t[1]), "=r"(t[2]), "=r"(t[3]) : "r"(addr));
}
__device__ __forceinline__ void mma_f16(float* d, const uint32_t* a, const uint32_t* b) {
    asm volatile(
        "mma.sync.aligned.m16n8k16.row.col.f32.f16.f16.f32 "
        "{%0,%1,%2,%3}, {%4,%5,%6,%7}, {%8,%9}, {%0,%1,%2,%3};"
        : "+f"(d[0]), "+f"(d[1]), "+f"(d[2]), "+f"(d[3])
        : "r"(a[0]), "r"(a[1]), "r"(a[2]), "r"(a[3]), "r"(b[0]), "r"(b[1]));
}
__device__ __forceinline__ void cp_async16(uint32_t dst, const void* src) {
    asm volatile("cp.async.cg.shared.global [%0], [%1], 16;"
                 :: "r"(dst), "l"(src) : "memory");
}
__device__ __forceinline__ void cp_commit() {
    asm volatile("cp.async.commit_group;" ::: "memory");
}
template <int N>
__device__ __forceinline__ void cp_wait() {
    asm volatile("cp.async.wait_group %0;" :: "n"(N) : "memory");
}

// ---------------- gather index builder ----------------
__global__ void build_idx_kernel(const int* __restrict__ in_seq,
                                 const int* __restrict__ tg_seq,
                                 int* __restrict__ idx, int mode) {
    int m = blockIdx.x * 256 + threadIdx.x;
    if (m >= 2048) return;
    int b = m & 31, t = m >> 5;
    if (mode == 0) idx[m] = in_seq[b * 64 + t];
    else           idx[m] = (t == 0) ? 0 : tg_seq[b * 64 + t - 1];
}

// ------- f32 -> fp16 single into SW128 swizzled 128x64 tiles --------------
__global__ __launch_bounds__(256)
void convert_single_f16_kernel(const float* __restrict__ src,
                               char* __restrict__ dst) {
    const int tid = threadIdx.x;
    const int rb = blockIdx.x * 128;
    const int kc = blockIdx.y * 64;
    const size_t tb = ((size_t)blockIdx.x * 8 + blockIdx.y) * 16384;
#pragma unroll
    for (int it = 0; it < 8; it++) {
        const int idx = tid + it * 256;
        const int r  = idx >> 4;
        const int c4 = idx & 15;
        float4 v = *(const float4*)(src + (size_t)(rb + r) * 512 + kc + c4 * 4);
        __half2 h01 = __floats2half2_rn(v.x, v.y);
        __half2 h23 = __floats2half2_rn(v.z, v.w);
        const uint32_t sw = SWZ128((uint32_t)(r * 128 + (c4 >> 1) * 16)) + (c4 & 1) * 8;
        *(__half2*)(dst + tb + sw)     = h01;
        *(__half2*)(dst + tb + sw + 4) = h23;
    }
}

// ------- f32 -> fp16 hi/lo split into SW128 swizzled 128x64 tiles ---------
__global__ __launch_bounds__(256)
void convert_dual_f16_kernel(const float* __restrict__ src,
                             char* __restrict__ dsthi, char* __restrict__ dstlo) {
    const int tid = threadIdx.x;
    const int rb = blockIdx.x * 128;
    const int kc = blockIdx.y * 64;
    const size_t tb = ((size_t)blockIdx.x * 8 + blockIdx.y) * 16384;
#pragma unroll
    for (int it = 0; it < 8; it++) {
        const int idx = tid + it * 256;
        const int r  = idx >> 4;
        const int c4 = idx & 15;
        float4 v = *(const float4*)(src + (size_t)(rb + r) * 512 + kc + c4 * 4);
        __half2 h01 = __floats2half2_rn(v.x, v.y);
        __half2 h23 = __floats2half2_rn(v.z, v.w);
        __half2 l01 = __floats2half2_rn(v.x - __half2float(h01.x),
                                        v.y - __half2float(h01.y));
        __half2 l23 = __floats2half2_rn(v.z - __half2float(h23.x),
                                        v.w - __half2float(h23.y));
        const uint32_t sw = SWZ128((uint32_t)(r * 128 + (c4 >> 1) * 16)) + (c4 & 1) * 8;
        *(__half2*)(dsthi + tb + sw)     = h01;
        *(__half2*)(dsthi + tb + sw + 4) = h23;
        *(__half2*)(dstlo + tb + sw)     = l01;
        *(__half2*)(dstlo + tb + sw + 4) = l23;
    }
}

// ---------------- SGEMM-NT: C[M,N] = A[M,K] * B[N,K]^T (+bias) ------------
__global__ __launch_bounds__(256)
void gemm_nt_kernel(const float* __restrict__ A, int lda,
                    const float* __restrict__ Bm, int ldb,
                    const float* __restrict__ bias,
                    float* __restrict__ C, int N, int K,
                    const int* __restrict__ gidx, int outmode) {
    const int tid = threadIdx.x;
    const int bn = blockIdx.x * 128;
    const int bm = blockIdx.y * 128;
    __shared__ float As[2][16][132];
    __shared__ float Bs[2][16][132];
    const int tx = tid & 15, ty = tid >> 4;
    float acc[8][8];
#pragma unroll
    for (int i = 0; i < 8; i++)
#pragma unroll
        for (int j = 0; j < 8; j++) acc[i][j] = 0.f;

    const int lrow = tid >> 1;
    const int lk   = (tid & 1) * 8;
    int arow = gidx ? gidx[bm + lrow] : (bm + lrow);
    const float* Ap = A  + (size_t)arow        * lda + lk;
    const float* Bp = Bm + (size_t)(bn + lrow) * ldb + lk;

    {
        float4 a0 = *(const float4*)(Ap);
        float4 a1 = *(const float4*)(Ap + 4);
        float4 b0 = *(const float4*)(Bp);
        float4 b1 = *(const float4*)(Bp + 4);
        As[0][lk+0][lrow]=a0.x; As[0][lk+1][lrow]=a0.y; As[0][lk+2][lrow]=a0.z; As[0][lk+3][lrow]=a0.w;
        As[0][lk+4][lrow]=a1.x; As[0][lk+5][lrow]=a1.y; As[0][lk+6][lrow]=a1.z; As[0][lk+7][lrow]=a1.w;
        Bs[0][lk+0][lrow]=b0.x; Bs[0][lk+1][lrow]=b0.y; Bs[0][lk+2][lrow]=b0.z; Bs[0][lk+3][lrow]=b0.w;
        Bs[0][lk+4][lrow]=b1.x; Bs[0][lk+5][lrow]=b1.y; Bs[0][lk+6][lrow]=b1.z; Bs[0][lk+7][lrow]=b1.w;
    }
    __syncthreads();
    int buf = 0;
    for (int kc = 0; kc < K; kc += 16) {
        if (kc + 16 < K) {
            float4 a0 = *(const float4*)(Ap + kc + 16);
            float4 a1 = *(const float4*)(Ap + kc + 20);
            float4 b0 = *(const float4*)(Bp + kc + 16);
            float4 b1 = *(const float4*)(Bp + kc + 20);
            const int nb = buf ^ 1;
            As[nb][lk+0][lrow]=a0.x; As[nb][lk+1][lrow]=a0.y; As[nb][lk+2][lrow]=a0.z; As[nb][lk+3][lrow]=a0.w;
            As[nb][lk+4][lrow]=a1.x; As[nb][lk+5][lrow]=a1.y; As[nb][lk+6][lrow]=a1.z; As[nb][lk+7][lrow]=a1.w;
            Bs[nb][lk+0][lrow]=b0.x; Bs[nb][lk+1][lrow]=b0.y; Bs[nb][lk+2][lrow]=b0.z; Bs[nb][lk+3][lrow]=b0.w;
            Bs[nb][lk+4][lrow]=b1.x; Bs[nb][lk+5][lrow]=b1.y; Bs[nb][lk+6][lrow]=b1.z; Bs[nb][lk+7][lrow]=b1.w;
        }
#pragma unroll
        for (int kk = 0; kk < 16; kk++) {
            float4 alo = *(const float4*)&As[buf][kk][ty * 4];
            float4 ahi = *(const float4*)&As[buf][kk][64 + ty * 4];
            float4 blo = *(const float4*)&Bs[buf][kk][tx * 4];
            float4 bhi = *(const float4*)&Bs[buf][kk][64 + tx * 4];
            float a[8] = {alo.x, alo.y, alo.z, alo.w, ahi.x, ahi.y, ahi.z, ahi.w};
            float b[8] = {blo.x, blo.y, blo.z, blo.w, bhi.x, bhi.y, bhi.z, bhi.w};
#pragma unroll
            for (int i = 0; i < 8; i++)
#pragma unroll
                for (int j = 0; j < 8; j++)
                    acc[i][j] = fmaf(a[i], b[j], acc[i][j]);
        }
        __syncthreads();
        buf ^= 1;
    }
#pragma unroll
    for (int i = 0; i < 8; i++) {
        const int m = bm + ((i < 4) ? (ty * 4 + i) : (64 + ty * 4 + i - 4));
        const int orow = (outmode == 1) ? ((m & 31) * 64 + (m >> 5)) : m;
        float* crow = C + (size_t)orow * N;
#pragma unroll
        for (int j = 0; j < 8; j++) {
            const int n = bn + ((j < 4) ? (tx * 4 + j) : (64 + tx * 4 + j - 4));
            float v = acc[i][j];
            if (bias) v += bias[n];
            crow[n] = v;
        }
    }
}

// ====== logits GEMM: fp16 mma.sync, A hi/lo split, B single (2-pass) ======
#define LM_TOT 98304

__global__ __launch_bounds__(256, 2)
void logits_mma_kernel(const char* __restrict__ Ah, const char* __restrict__ Al,
                       const char* __restrict__ Bw,
                       const float* __restrict__ bias,
                       float* __restrict__ out) {
    extern __shared__ char smem[];
    const uint32_t sb = smem_u32(smem);
    const int tid  = threadIdx.x;
    const int wid  = tid >> 5;
    const int lane = tid & 31;
    const int mt = blockIdx.y;
    const int nt = blockIdx.x;
    const int bm = mt * 128;
    const int bn = nt * 128;
    const int wm = (wid & 3) * 32;
    const int wn = (wid >> 2) * 64;

    float acc[2][8][4];
#pragma unroll
    for (int mi = 0; mi < 2; mi++)
#pragma unroll
        for (int ni = 0; ni < 8; ni++)
#pragma unroll
            for (int e = 0; e < 4; e++) acc[mi][ni][e] = 0.f;

    const int lrow = lane & 15;
    const int lcol16 = lane >> 4;

    auto prefetch = [&](int ch, int buf) {
        const char* srcs[3] = {
            Ah + ((size_t)mt * 8 + ch) * 16384,
            Al + ((size_t)mt * 8 + ch) * 16384,
            Bw + ((size_t)nt * 8 + ch) * 16384 };
#pragma unroll
        for (int t = 0; t < 3; t++) {
            const char* s = srcs[t] + tid * 16;
            const uint32_t d = sb + buf * 49152 + t * 16384 + tid * 16;
#pragma unroll
            for (int i = 0; i < 4; i++)
                cp_async16(d + i * 4096, s + i * 4096);
        }
        cp_commit();
    };

    prefetch(0, 0);
    int buf = 0;
    for (int ch = 0; ch < 8; ch++) {
        if (ch < 7) {
            prefetch(ch + 1, buf ^ 1);
            cp_wait<1>();
        } else {
            cp_wait<0>();
        }
        __syncthreads();

        const uint32_t base = sb + buf * 49152;
#pragma unroll
        for (int ks = 0; ks < 4; ks++) {
            uint32_t ah[2][4], al[2][4];
#pragma unroll
            for (int mi = 0; mi < 2; mi++) {
                const uint32_t off =
                    SWZ128((uint32_t)((wm + mi * 16 + lrow) * 128 + ks * 32 + lcol16 * 16));
                ldmx4(ah[mi], base + off);
                ldmx4(al[mi], base + 16384 + off);
            }
            uint32_t bw[8][2];
#pragma unroll
            for (int nj = 0; nj < 4; nj++) {
                const uint32_t off =
                    SWZ128((uint32_t)((wn + nj * 16 + lrow) * 128 + ks * 32 + lcol16 * 16));
                uint32_t t[4];
                ldmx4(t, base + 32768 + off);
                bw[nj*2][0] = t[0]; bw[nj*2+1][0] = t[1];
                bw[nj*2][1] = t[2]; bw[nj*2+1][1] = t[3];
            }
#pragma unroll
            for (int mi = 0; mi < 2; mi++)
#pragma unroll
                for (int ni = 0; ni < 8; ni++) {
                    mma_f16(acc[mi][ni], ah[mi], bw[ni]);
                    mma_f16(acc[mi][ni], al[mi], bw[ni]);
                }
        }
        __syncthreads();
        buf ^= 1;
    }

#pragma unroll
    for (int mi = 0; mi < 2; mi++) {
        const int m0 = bm + wm + mi * 16 + (lane >> 2);
        const int m1 = m0 + 8;
        const int or0 = (m0 & 31) * 64 + (m0 >> 5);
        const int or1 = (m1 & 31) * 64 + (m1 >> 5);
#pragma unroll
        for (int ni = 0; ni < 8; ni++) {
            const int n = bn + wn + ni * 8 + (lane & 3) * 2;
            const float b0 = bias[n], b1 = bias[n + 1];
            float2 v0 = make_float2(acc[mi][ni][0] + b0, acc[mi][ni][1] + b1);
            float2 v1 = make_float2(acc[mi][ni][2] + b0, acc[mi][ni][3] + b1);
            *(float2*)(out + (size_t)or0 * 32000 + n) = v0;
            *(float2*)(out + (size_t)or1 * 32000 + n) = v1;
        }
    }
}

// ---------------- register-blocked GRU machinery ----------------
struct Part {
    const float* W;
    int ldW;
    int wco;
    const float* src;
};

template<int NP, bool XSEC>
__device__ __forceinline__ void accum_section(
    float (&acc)[12][4], float (&accx)[4][4],
    Part P, int jbase, int b0, int lane)
{
    const float* Wb = P.W + P.wco;
#pragma unroll
    for (int ps = 0; ps < NP; ps++) {
        const int k = ps * 128 + lane * 4;
        float4 s[4];
#pragma unroll
        for (int bi = 0; bi < 4; bi++)
            s[bi] = __ldcg((const float4*)(P.src + (b0 + bi) * 512 + k));
#pragma unroll
        for (int r = 0; r < 12; r++) {
            const int row = (r >> 2) * 512 + jbase + (r & 3);
            float4 wv = *(const float4*)(Wb + (size_t)row * P.ldW + k);
            float* a = (XSEC && r >= 8) ? accx[r - 8] : acc[r];
#pragma unroll
            for (int bi = 0; bi < 4; bi++) {
                a[bi] = fmaf(s[bi].x, wv.x, a[bi]);
                a[bi] = fmaf(s[bi].y, wv.y, a[bi]);
                a[bi] = fmaf(s[bi].z, wv.z, a[bi]);
                a[bi] = fmaf(s[bi].w, wv.w, a[bi]);
            }
        }
    }
}

template<int NP0, int NP1, int MODE>  // MODE: 0=enc(gi_pre), 2=bx+x
__device__ __forceinline__ void gru_phase(
    int jbase, Part p0, Part p1,
    const float* __restrict__ gi_pre, const float* __restrict__ bx,
    const float* __restrict__ bh, const float* __restrict__ hprev,
    float* __restrict__ hnext, float* __restrict__ yout, int yb)
{
    const int lane = threadIdx.x & 31;
    const int w    = threadIdx.x >> 5;
    const int b0   = w * 4;
    float acc[12][4];
    float accx[4][4];
#pragma unroll
    for (int r = 0; r < 12; r++)
#pragma unroll
        for (int bi = 0; bi < 4; bi++) acc[r][bi] = 0.f;
#pragma unroll
    for (int r = 0; r < 4; r++)
#pragma unroll
        for (int bi = 0; bi < 4; bi++) accx[r][bi] = 0.f;

    accum_section<NP0, false>(acc, accx, p0, jbase, b0, lane);
    if (NP1 > 0) accum_section<NP1, true>(acc, accx, p1, jbase, b0, lane);

#pragma unroll
    for (int r = 0; r < 12; r++)
#pragma unroll
        for (int bi = 0; bi < 4; bi++)
#pragma unroll
            for (int o = 16; o; o >>= 1)
                acc[r][bi] += __shfl_xor_sync(0xffffffffu, acc[r][bi], o);
    if (NP1 > 0) {
#pragma unroll
        for (int r = 0; r < 4; r++)
#pragma unroll
            for (int bi = 0; bi < 4; bi++)
#pragma unroll
                for (int o = 16; o; o >>= 1)
                    accx[r][bi] += __shfl_xor_sync(0xffffffffu, accx[r][bi], o);
    }

    if (lane < 4) {
        const int jl = lane, j = jbase + jl;
        const float bh0 = bh[j], bh1 = bh[512 + j], bh2 = bh[1024 + j];
#pragma unroll
        for (int bi = 0; bi < 4; bi++) {
            const int b = b0 + bi;
            float pr, pz, gin, ghn;
            if (MODE == 0) {
                pr  = gi_pre[b * 1536 + j]        + acc[jl][bi]     + bh0;
                pz  = gi_pre[b * 1536 + 512 + j]  + acc[4 + jl][bi] + bh1;
                gin = gi_pre[b * 1536 + 1024 + j];
                ghn = acc[8 + jl][bi] + bh2;
            } else {
                pr  = bx[j]        + acc[jl][bi]     + bh0;
                pz  = bx[512 + j]  + acc[4 + jl][bi] + bh1;
                gin = bx[1024 + j] + accx[jl][bi];
                ghn = acc[8 + jl][bi] + bh2;
            }
            float r = sigm(pr);
            float z = sigm(pz);
            float n = tanhf(gin + r * ghn);
            float hp = __ldcg(hprev + b * 512 + j);
            float hn = (1.f - z) * n + z * hp;
            hnext[b * 512 + j] = hn;
            if (yout) yout[b * yb + j] = hn;
        }
    }
}

// ---- gh pass + store: 12 recurrent gate dots (+bh) -> g_gh slice ---------
__device__ __forceinline__ void ghpass_store(
    int jbase, const float* __restrict__ Wh, const float* __restrict__ bh,
    const float* __restrict__ h, float* __restrict__ dst /* [3][32][512] */)
{
    const int lane = threadIdx.x & 31;
    const int w    = threadIdx.x >> 5;
    const int b0   = w * 4;
    float acc[12][4];
    float dummy[4][4];
#pragma unroll
    for (int r = 0; r < 12; r++)
#pragma unroll
        for (int bi = 0; bi < 4; bi++) acc[r][bi] = 0.f;
    Part p{Wh, 512, 0, h};
    accum_section<4, false>(acc, dummy, p, jbase, b0, lane);
#pragma unroll
    for (int r = 0; r < 12; r++)
#pragma unroll
        for (int bi = 0; bi < 4; bi++)
#pragma unroll
            for (int o = 16; o; o >>= 1)
                acc[r][bi] += __shfl_xor_sync(0xffffffffu, acc[r][bi], o);
    if (lane < 4) {
        const int jl = lane, j = jbase + jl;
#pragma unroll
        for (int g = 0; g < 3; g++) {
            const float bb = bh[g * 512 + j];
#pragma unroll
            for (int bi = 0; bi < 4; bi++)
                dst[g * 16384 + (b0 + bi) * 512 + j] = acc[g * 4 + jl][bi] + bb;
        }
    }
}

// ---- x-only GRU phase: x-part accum + gates using precomputed gh ---------
template<int MODE>  // 3: gi_pre + gh ; 4: bx + gh
__device__ __forceinline__ void gru_x_phase(
    int jbase, Part p1,
    const float* __restrict__ gi_pre, const float* __restrict__ bx,
    const float* __restrict__ gh /* [3][32][512] */,
    const float* __restrict__ hprev, float* __restrict__ hnext,
    float* __restrict__ yout, int yb)
{
    const int lane = threadIdx.x & 31;
    const int w    = threadIdx.x >> 5;
    const int b0   = w * 4;
    float acc[12][4];
    float accx[4][4];
#pragma unroll
    for (int r = 0; r < 12; r++)
#pragma unroll
        for (int bi = 0; bi < 4; bi++) acc[r][bi] = 0.f;
#pragma unroll
    for (int r = 0; r < 4; r++)
#pragma unroll
        for (int bi = 0; bi < 4; bi++) accx[r][bi] = 0.f;

    accum_section<4, true>(acc, accx, p1, jbase, b0, lane);

#pragma unroll
    for (int r = 0; r < 8; r++)
#pragma unroll
        for (int bi = 0; bi < 4; bi++)
#pragma unroll
            for (int o = 16; o; o >>= 1)
                acc[r][bi] += __shfl_xor_sync(0xffffffffu, acc[r][bi], o);
#pragma unroll
    for (int r = 0; r < 4; r++)
#pragma unroll
        for (int bi = 0; bi < 4; bi++)
#pragma unroll
            for (int o = 16; o; o >>= 1)
                accx[r][bi] += __shfl_xor_sync(0xffffffffu, accx[r][bi], o);

    if (lane < 4) {
        const int jl = lane, j = jbase + jl;
#pragma unroll
        for (int bi = 0; bi < 4; bi++) {
            const int b = b0 + bi;
            const float ghr = __ldcg(gh + b * 512 + j);
            const float ghz = __ldcg(gh + 16384 + b * 512 + j);
            const float ghn = __ldcg(gh + 32768 + b * 512 + j);
            float pr, pz, gin;
            if (MODE == 3) {
                pr  = gi_pre[b * 1536 + j]        + acc[jl][bi]     + ghr;
                pz  = gi_pre[b * 1536 + 512 + j]  + acc[4 + jl][bi] + ghz;
                gin = gi_pre[b * 1536 + 1024 + j] + accx[jl][bi];
            } else {
                pr  = bx[j]        + acc[jl][bi]     + ghr;
                pz  = bx[512 + j]  + acc[4 + jl][bi] + ghz;
                gin = bx[1024 + j] + accx[jl][bi];
            }
            float r = sigm(pr);
            float z = sigm(pz);
            float n = tanhf(gin + r * ghn);
            float hp = __ldcg(hprev + b * 512 + j);
            float hn = (1.f - z) * n + z * hp;
            hnext[b * 512 + j] = hn;
            if (yout) yout[b * yb + j] = hn;
        }
    }
}

// ---------------- fused encoder: layer0 step s + layer1 step s-1 ---------
__global__ __launch_bounds__(256, 1)
void enc_fused_kernel(const float* __restrict__ Wh0, const float* __restrict__ bh0,
                      const float* __restrict__ gi0,
                      const float* __restrict__ Wh1, const float* __restrict__ Wx1,
                      const float* __restrict__ bx1, const float* __restrict__ bh1) {
    unsigned eps = 0;
    const int jbase = blockIdx.x * 4;
    Part pd{nullptr, 0, 0, nullptr};
    for (int s = 0; s < 65; s++) {
        if (s < 64) {
            const int p0 = s & 1;
            Part ph{Wh0, 512, 0, g_hA + p0 * 16384};
            gru_phase<4, 0, 0>(jbase, ph, pd, gi0 + (size_t)s * 49152, nullptr, bh0,
                               g_hA + p0 * 16384, g_hA + (p0 ^ 1) * 16384,
                               g_y0 + (size_t)s * 16384, 512);
        }
        if (s >= 1) {
            const int t1 = s - 1;
            const int p1 = t1 & 1;
            Part ph{Wh1, 512, 0, g_hB + p1 * 16384};
            Part px{Wx1, 512, 0, g_y0 + (size_t)t1 * 16384};
            gru_phase<4, 4, 2>(jbase, ph, px, nullptr, bx1, bh1,
                               g_hB + p1 * 16384, g_hB + (p1 ^ 1) * 16384,
                               g_enc + (size_t)t1 * 512, 32768);
        }
        grid_bar(eps);
    }
}

// ---------------- decoder phase A: q = h1 @ W_attn[:, :512]^T ------------
__device__ __forceinline__ void phaseA(const float* __restrict__ h1,
                                       const float* __restrict__ Wa) {
    const int lane = threadIdx.x & 31;
    const int w    = threadIdx.x >> 5;
    const int b0   = w * 4;
    const int nbase = blockIdx.x * 4;
    float acc[4][4];
#pragma unroll
    for (int r = 0; r < 4; r++)
#pragma unroll
        for (int bi = 0; bi < 4; bi++) acc[r][bi] = 0.f;
#pragma unroll
    for (int ps = 0; ps < 4; ps++) {
        const int k = ps * 128 + lane * 4;
        float4 s[4];
#pragma unroll
        for (int bi = 0; bi < 4; bi++)
            s[bi] = __ldcg((const float4*)(h1 + (b0 + bi) * 512 + k));
#pragma unroll
        for (int r = 0; r < 4; r++) {
            float4 wv = *(const float4*)(Wa + (size_t)(nbase + r) * 1024 + k);
#pragma unroll
            for (int bi = 0; bi < 4; bi++) {
                acc[r][bi] = fmaf(s[bi].x, wv.x, acc[r][bi]);
                acc[r][bi] = fmaf(s[bi].y, wv.y, acc[r][bi]);
                acc[r][bi] = fmaf(s[bi].z, wv.z, acc[r][bi]);
                acc[r][bi] = fmaf(s[bi].w, wv.w, acc[r][bi]);
            }
        }
    }
#pragma unroll
    for (int r = 0; r < 4; r++)
#pragma unroll
        for (int bi = 0; bi < 4; bi++)
#pragma unroll
            for (int o = 16; o; o >>= 1)
                acc[r][bi] += __shfl_xor_sync(0xffffffffu, acc[r][bi], o);
    if (lane < 4) {
#pragma unroll
        for (int bi = 0; bi < 4; bi++)
            g_q[(b0 + bi) * 512 + nbase + lane] = acc[lane][bi];
    }
}

// ---------------- decoder phase B: scores -> softmax -> context ----------
__device__ __forceinline__ void phaseB(const float* __restrict__ v_attn) {
    __shared__ float qv[512];
    __shared__ float vv[512];
    __shared__ float sc[64];
    __shared__ float aw[64];
    const int b = blockIdx.x;
    const int tid = threadIdx.x;
    for (int i = tid; i < 512; i += 256) {
        qv[i] = __ldcg(g_q + b * 512 + i);
        vv[i] = v_attn[i];
    }
    __syncthreads();
    const int w = tid >> 5, lane = tid & 31;
    for (int ss = 0; ss < 8; ss++) {
        const int s = w * 8 + ss;
        const float* Urow = g_U + (size_t)(b * 64 + s) * 512;
        float p = 0.f;
        for (int n = lane; n < 512; n += 32)
            p += vv[n] * tanhf(qv[n] + Urow[n]);
#pragma unroll
        for (int o = 16; o; o >>= 1) p += __shfl_xor_sync(0xffffffffu, p, o);
        if (lane == 0) sc[s] = p;
    }
    __syncthreads();
    if (w == 0) {
        float v0 = sc[lane], v1 = sc[lane + 32];
        float mx = fmaxf(v0, v1);
#pragma unroll
        for (int o = 16; o; o >>= 1) mx = fmaxf(mx, __shfl_xor_sync(0xffffffffu, mx, o));
        float e0 = expf(v0 - mx), e1 = expf(v1 - mx);
        float sm = e0 + e1;
#pragma unroll
        for (int o = 16; o; o >>= 1) sm += __shfl_xor_sync(0xffffffffu, sm, o);
        float inv = 1.f / sm;
        aw[lane]      = e0 * inv;
        aw[lane + 32] = e1 * inv;
    }
    __syncthreads();
    for (int n = tid; n < 512; n += 256) {
        const float* erow = g_enc + (size_t)b * 64 * 512 + n;
        float acc = 0.f;
#pragma unroll 8
        for (int s = 0; s < 64; s++) acc = fmaf(aw[s], erow[s * 512], acc);
        g_ctx[b * 512 + n] = acc;
    }
}

// ---------------- persistent decoder (64 steps, 4 phases each) -----------
// Interval 2: blocks 0-31 run phaseB; blocks 32-127 compute all 1024
// recurrent gate rows (gh for d0 and d1) into g_gh. Phases C/D are x-only.
__global__ __launch_bounds__(256, 1)
void dec_persist_kernel(const float* __restrict__ Wa, const float* __restrict__ v_attn,
                        const float* __restrict__ Wh0, const float* __restrict__ Wx0,
                        const float* __restrict__ bh0,
                        const float* __restrict__ Wh1, const float* __restrict__ Wx1,
                        const float* __restrict__ bx1, const float* __restrict__ bh1) {
    unsigned eps = 0;
    const int jbase = blockIdx.x * 4;
    for (int t = 0; t < 64; t++) {
        const int par = t & 1;
        const float* h0 = g_hA + par * 16384;
        const float* h1 = g_hB + par * 16384;
        float* h0n = g_hA + (par ^ 1) * 16384;
        float* h1n = g_hB + (par ^ 1) * 16384;

        phaseA(h1, Wa);
        grid_bar(eps);

        if (blockIdx.x < 32) {
            phaseB(v_attn);
        } else {
            // 256 gh units (layer, jgroup) over 96 blocks
            for (int u = blockIdx.x - 32; u < 256; u += 96) {
                const int layer = u >> 7;
                const int jb = (u & 127) * 4;
                if (layer == 0)
                    ghpass_store(jb, Wh0, bh0, h0, g_gh);
                else
                    ghpass_store(jb, Wh1, bh1, h1, g_gh + 49152);
            }
        }
        grid_bar(eps);

        {   // GRU d0 (x-only): ctx via Wx_d0 cols [256,768), gh from g_gh[0]
            Part px{Wx0, 768, 256, g_ctx};
            gru_x_phase<3>(jbase, px, g_gi + (size_t)t * 49152, nullptr,
                           g_gh, h0, h0n, nullptr, 0);
        }
        grid_bar(eps);

        {   // GRU d1 (x-only): h0' via Wx_d1, gh from g_gh[1]
            Part px{Wx1, 512, 0, h0n};
            gru_x_phase<4>(jbase, px, nullptr, bx1,
                           g_gh + 49152, h1, h1n, g_H1 + (size_t)t * 16384, 512);
        }
        grid_bar(eps);
    }
}

// ---------------- host orchestration ----------------
extern "C" void kernel_launch(void* const* d_in, const int* in_sizes, int n_in,
                              void* d_out, int out_size) {
    (void)in_sizes; (void)n_in; (void)out_size;
    const int*   in_seq = (const int*)d_in[0];
    const int*   tg_seq = (const int*)d_in[1];
    const float* E_enc  = (const float*)d_in[2];
    const float* Wx_e0  = (const float*)d_in[3];
    const float* Wh_e0  = (const float*)d_in[4];
    const float* bx_e0  = (const float*)d_in[5];
    const float* bh_e0  = (const float*)d_in[6];
    const float* Wx_e1  = (const float*)d_in[7];
    const float* Wh_e1  = (const float*)d_in[8];
    const float* bx_e1  = (const float*)d_in[9];
    const float* bh_e1  = (const float*)d_in[10];
    const float* E_dec  = (const float*)d_in[11];
    const float* W_attn = (const float*)d_in[12];
    const float* b_attn = (const float*)d_in[13];
    const float* v_attn = (const float*)d_in[14];
    const float* Wx_d0  = (const float*)d_in[15];
    const float* Wh_d0  = (const float*)d_in[16];
    const float* bx_d0  = (const float*)d_in[17];
    const float* bh_d0  = (const float*)d_in[18];
    const float* Wx_d1  = (const float*)d_in[19];
    const float* Wh_d1  = (const float*)d_in[20];
    const float* bx_d1  = (const float*)d_in[21];
    const float* bh_d1  = (const float*)d_in[22];
    const float* W_out  = (const float*)d_in[23];
    const float* b_out  = (const float*)d_in[24];
    float* out = (float*)d_out;

    float *gi, *y0, *enc, *U, *H1, *hA, *hB;
    int* idx;
    unsigned* bar;
    char *wf, *ah, *al;
    cudaGetSymbolAddress((void**)&gi,  g_gi);
    cudaGetSymbolAddress((void**)&y0,  g_y0);
    cudaGetSymbolAddress((void**)&enc, g_enc);
    cudaGetSymbolAddress((void**)&U,   g_U);
    cudaGetSymbolAddress((void**)&H1,  g_H1);
    cudaGetSymbolAddress((void**)&hA,  g_hA);
    cudaGetSymbolAddress((void**)&hB,  g_hB);
    cudaGetSymbolAddress((void**)&idx, g_idx);
    cudaGetSymbolAddress((void**)&bar, g_cnt);
    cudaGetSymbolAddress((void**)&wf,  g_W_f16);
    cudaGetSymbolAddress((void**)&ah,  g_Ah_f16);
    cudaGetSymbolAddress((void**)&al,  g_Al_f16);

    cudaFuncSetAttribute(logits_mma_kernel,
                         cudaFuncAttributeMaxDynamicSharedMemorySize, LM_TOT);

    cudaMemsetAsync(hA, 0, 2 * 32 * 512 * sizeof(float));
    cudaMemsetAsync(hB, 0, 2 * 32 * 512 * sizeof(float));

    // ---- pre-convert W_out to fp16 swizzled tiles (one-time) ----
    convert_single_f16_kernel<<<dim3(250, 8), 256>>>(W_out, wf);

    // ---- encoder: gi_e0 GEMM, then fused 2-layer persistent kernel ----
    build_idx_kernel<<<8, 256>>>(in_seq, tg_seq, idx, 0);
    gemm_nt_kernel<<<dim3(12, 16), 256>>>(E_enc, 256, Wx_e0, 256, bx_e0,
                                          gi, 1536, 256, idx, 0);
    cudaMemsetAsync(bar, 0, sizeof(unsigned));
    enc_fused_kernel<<<NBLK, 256>>>(Wh_e0, bh_e0, gi,
                                    Wh_e1, Wx_e1, bx_e1, bh_e1);

    // U = enc_out @ W_attn[:, 512:]^T + b_attn
    gemm_nt_kernel<<<dim3(4, 16), 256>>>(enc, 512, W_attn + 512, 1024, b_attn,
                                         U, 512, 512, nullptr, 0);
    build_idx_kernel<<<8, 256>>>(in_seq, tg_seq, idx, 1);
    gemm_nt_kernel<<<dim3(12, 16), 256>>>(E_dec, 256, Wx_d0, 768, bx_d0,
                                          gi, 1536, 256, idx, 0);

    // ---- decoder persistent loop ----
    cudaMemsetAsync(bar, 0, sizeof(unsigned));
    dec_persist_kernel<<<NBLK, 256>>>(W_attn, v_attn,
                                      Wh_d0, Wx_d0, bh_d0,
                                      Wh_d1, Wx_d1, bx_d1, bh_d1);

    // ---- convert H1 to fp16 hi/lo tiles, then logits (2-pass fp16) ----
    convert_dual_f16_kernel<<<dim3(16, 8), 256>>>(H1, ah, al);
    logits_mma_kernel<<<dim3(250, 16), 256, LM_TOT>>>(ah, al, wf, b_out, out);
}

// round 14
// speedup vs baseline: 1.1293x; 1.0437x over previous
#include <cuda_runtime.h>
#include <cuda_fp16.h>
#include <cstdint>

#define NBLK 128

// ---------------- device scratch (no allocations allowed) ----------------
__device__ float g_gi [2048 * 1536];   // reused: gi_e0 -> gi_dec_emb
__device__ float g_y0 [2048 * 512];    // encoder layer0 outputs [s][b][512]
__device__ float g_enc[2048 * 512];    // encoder outputs [b][s][512]
__device__ float g_U  [2048 * 512];    // enc part of attn energy [b][s][512]
__device__ float g_H1 [2048 * 512];    // decoder top hidden per step [t][b][512]
__device__ float g_hA [2 * 32 * 512];  // layer0 / decoder h0 (ping-pong)
__device__ float g_hB [2 * 32 * 512];  // layer1 / decoder h1 (ping-pong)
__device__ float g_q  [32 * 512];
__device__ float g_ctx[32 * 512];
__device__ float g_gh [2 * 3 * 32 * 512]; // decoder recurrent gates (+bh)
__device__ int   g_idx[2048];
__device__ unsigned g_cnt;             // grid barrier epoch counter
// pre-converted fp16 operand tiles (SW128-swizzled, 16KB per 128x64 tile)
__device__ __half g_W_f16[32000 * 512];   // W_out fp16
__device__ __half g_A_f16[2048 * 512];    // H1 fp16

// ---------------- grid-wide barrier (all NBLK blocks resident) ----------
__device__ __forceinline__ void grid_bar(unsigned &eps) {
    __syncthreads();
    if (threadIdx.x == 0) {
        eps += 1u;
        const unsigned need = eps * NBLK;
        __threadfence();
        atomicAdd(&g_cnt, 1u);
        unsigned v;
        do {
            asm volatile("ld.acquire.gpu.global.u32 %0, [%1];"
                         : "=r"(v) : "l"(&g_cnt));
        } while (v < need);
    }
    __syncthreads();
}

__device__ __forceinline__ float sigm(float x) { return 1.f / (1.f + expf(-x)); }

__device__ __forceinline__ uint32_t smem_u32(const void* p) {
    uint32_t a;
    asm("{ .reg .u64 t; cvta.to.shared.u64 t, %1; cvt.u32.u64 %0, t; }"
        : "=r"(a) : "l"(p));
    return a;
}
#define SWZ128(off) ((off) ^ (((off) >> 3) & 0x70))

__device__ __forceinline__ void ldmx4(uint32_t* t, uint32_t addr) {
    asm volatile("ldmatrix.sync.aligned.m8n8.x4.shared.b16 {%0,%1,%2,%3}, [%4];"
                 : "=r"(t[0]), "=r"(t[1]), "=r"(t[2]), "=r"(t[3]) : "r"(addr));
}
__device__ __forceinline__ void mma_f16(float* d, const uint32_t* a, const uint32_t* b) {
    asm volatile(
        "mma.sync.aligned.m16n8k16.row.col.f32.f16.f16.f32 "
        "{%0,%1,%2,%3}, {%4,%5,%6,%7}, {%8,%9}, {%0,%1,%2,%3};"
        : "+f"(d[0]), "+f"(d[1]), "+f"(d[2]), "+f"(d[3])
        : "r"(a[0]), "r"(a[1]), "r"(a[2]), "r"(a[3]), "r"(b[0]), "r"(b[1]));
}
__device__ __forceinline__ void cp_async16(uint32_t dst, const void* src) {
    asm volatile("cp.async.cg.shared.global [%0], [%1], 16;"
                 :: "r"(dst), "l"(src) : "memory");
}
__device__ __forceinline__ void cp_commit() {
    asm volatile("cp.async.commit_group;" ::: "memory");
}
template <int N>
__device__ __forceinline__ void cp_wait() {
    asm volatile("cp.async.wait_group %0;" :: "n"(N) : "memory");
}

// ---------------- gather index builder ----------------
__global__ void build_idx_kernel(const int* __restrict__ in_seq,
                                 const int* __restrict__ tg_seq,
                                 int* __restrict__ idx, int mode) {
    int m = blockIdx.x * 256 + threadIdx.x;
    if (m >= 2048) return;
    int b = m & 31, t = m >> 5;
    if (mode == 0) idx[m] = in_seq[b * 64 + t];
    else           idx[m] = (t == 0) ? 0 : tg_seq[b * 64 + t - 1];
}

// ------- f32 -> fp16 single into SW128 swizzled 128x64 tiles --------------
__global__ __launch_bounds__(256)
void convert_single_f16_kernel(const float* __restrict__ src,
                               char* __restrict__ dst) {
    const int tid = threadIdx.x;
    const int rb = blockIdx.x * 128;
    const int kc = blockIdx.y * 64;
    const size_t tb = ((size_t)blockIdx.x * 8 + blockIdx.y) * 16384;
#pragma unroll
    for (int it = 0; it < 8; it++) {
        const int idx = tid + it * 256;
        const int r  = idx >> 4;
        const int c4 = idx & 15;
        float4 v = *(const float4*)(src + (size_t)(rb + r) * 512 + kc + c4 * 4);
        __half2 h01 = __floats2half2_rn(v.x, v.y);
        __half2 h23 = __floats2half2_rn(v.z, v.w);
        const uint32_t sw = SWZ128((uint32_t)(r * 128 + (c4 >> 1) * 16)) + (c4 & 1) * 8;
        *(__half2*)(dst + tb + sw)     = h01;
        *(__half2*)(dst + tb + sw + 4) = h23;
    }
}

// ---------------- SGEMM-NT: C[M,N] = A[M,K] * B[N,K]^T (+bias) ------------
__global__ __launch_bounds__(256)
void gemm_nt_kernel(const float* __restrict__ A, int lda,
                    const float* __restrict__ Bm, int ldb,
                    const float* __restrict__ bias,
                    float* __restrict__ C, int N, int K,
                    const int* __restrict__ gidx, int outmode) {
    const int tid = threadIdx.x;
    const int bn = blockIdx.x * 128;
    const int bm = blockIdx.y * 128;
    __shared__ float As[2][16][132];
    __shared__ float Bs[2][16][132];
    const int tx = tid & 15, ty = tid >> 4;
    float acc[8][8];
#pragma unroll
    for (int i = 0; i < 8; i++)
#pragma unroll
        for (int j = 0; j < 8; j++) acc[i][j] = 0.f;

    const int lrow = tid >> 1;
    const int lk   = (tid & 1) * 8;
    int arow = gidx ? gidx[bm + lrow] : (bm + lrow);
    const float* Ap = A  + (size_t)arow        * lda + lk;
    const float* Bp = Bm + (size_t)(bn + lrow) * ldb + lk;

    {
        float4 a0 = *(const float4*)(Ap);
        float4 a1 = *(const float4*)(Ap + 4);
        float4 b0 = *(const float4*)(Bp);
        float4 b1 = *(const float4*)(Bp + 4);
        As[0][lk+0][lrow]=a0.x; As[0][lk+1][lrow]=a0.y; As[0][lk+2][lrow]=a0.z; As[0][lk+3][lrow]=a0.w;
        As[0][lk+4][lrow]=a1.x; As[0][lk+5][lrow]=a1.y; As[0][lk+6][lrow]=a1.z; As[0][lk+7][lrow]=a1.w;
        Bs[0][lk+0][lrow]=b0.x; Bs[0][lk+1][lrow]=b0.y; Bs[0][lk+2][lrow]=b0.z; Bs[0][lk+3][lrow]=b0.w;
        Bs[0][lk+4][lrow]=b1.x; Bs[0][lk+5][lrow]=b1.y; Bs[0][lk+6][lrow]=b1.z; Bs[0][lk+7][lrow]=b1.w;
    }
    __syncthreads();
    int buf = 0;
    for (int kc = 0; kc < K; kc += 16) {
        if (kc + 16 < K) {
            float4 a0 = *(const float4*)(Ap + kc + 16);
            float4 a1 = *(const float4*)(Ap + kc + 20);
            float4 b0 = *(const float4*)(Bp + kc + 16);
            float4 b1 = *(const float4*)(Bp + kc + 20);
            const int nb = buf ^ 1;
            As[nb][lk+0][lrow]=a0.x; As[nb][lk+1][lrow]=a0.y; As[nb][lk+2][lrow]=a0.z; As[nb][lk+3][lrow]=a0.w;
            As[nb][lk+4][lrow]=a1.x; As[nb][lk+5][lrow]=a1.y; As[nb][lk+6][lrow]=a1.z; As[nb][lk+7][lrow]=a1.w;
            Bs[nb][lk+0][lrow]=b0.x; Bs[nb][lk+1][lrow]=b0.y; Bs[nb][lk+2][lrow]=b0.z; Bs[nb][lk+3][lrow]=b0.w;
            Bs[nb][lk+4][lrow]=b1.x; Bs[nb][lk+5][lrow]=b1.y; Bs[nb][lk+6][lrow]=b1.z; Bs[nb][lk+7][lrow]=b1.w;
        }
#pragma unroll
        for (int kk = 0; kk < 16; kk++) {
            float4 alo = *(const float4*)&As[buf][kk][ty * 4];
            float4 ahi = *(const float4*)&As[buf][kk][64 + ty * 4];
            float4 blo = *(const float4*)&Bs[buf][kk][tx * 4];
            float4 bhi = *(const float4*)&Bs[buf][kk][64 + tx * 4];
            float a[8] = {alo.x, alo.y, alo.z, alo.w, ahi.x, ahi.y, ahi.z, ahi.w};
            float b[8] = {blo.x, blo.y, blo.z, blo.w, bhi.x, bhi.y, bhi.z, bhi.w};
#pragma unroll
            for (int i = 0; i < 8; i++)
#pragma unroll
                for (int j = 0; j < 8; j++)
                    acc[i][j] = fmaf(a[i], b[j], acc[i][j]);
        }
        __syncthreads();
        buf ^= 1;
    }
#pragma unroll
    for (int i = 0; i < 8; i++) {
        const int m = bm + ((i < 4) ? (ty * 4 + i) : (64 + ty * 4 + i - 4));
        const int orow = (outmode == 1) ? ((m & 31) * 64 + (m >> 5)) : m;
        float* crow = C + (size_t)orow * N;
#pragma unroll
        for (int j = 0; j < 8; j++) {
            const int n = bn + ((j < 4) ? (tx * 4 + j) : (64 + tx * 4 + j - 4));
            float v = acc[i][j];
            if (bias) v += bias[n];
            crow[n] = v;
        }
    }
}

// ====== logits GEMM: single-pass fp16 mma.sync ======
// smem per buf: A 16KB + B 16KB = 32KB; double-buffered = 64KB. 2 CTAs/SM.
#define LM_TOT 65536

__global__ __launch_bounds__(256, 2)
void logits_mma_kernel(const char* __restrict__ Aw,
                       const char* __restrict__ Bw,
                       const float* __restrict__ bias,
                       float* __restrict__ out) {
    extern __shared__ char smem[];
    const uint32_t sb = smem_u32(smem);
    const int tid  = threadIdx.x;
    const int wid  = tid >> 5;
    const int lane = tid & 31;
    const int mt = blockIdx.y;
    const int nt = blockIdx.x;
    const int bm = mt * 128;
    const int bn = nt * 128;
    const int wm = (wid & 3) * 32;
    const int wn = (wid >> 2) * 64;

    float acc[2][8][4];
#pragma unroll
    for (int mi = 0; mi < 2; mi++)
#pragma unroll
        for (int ni = 0; ni < 8; ni++)
#pragma unroll
            for (int e = 0; e < 4; e++) acc[mi][ni][e] = 0.f;

    const int lrow = lane & 15;
    const int lcol16 = lane >> 4;

    auto prefetch = [&](int ch, int buf) {
        const char* srcs[2] = {
            Aw + ((size_t)mt * 8 + ch) * 16384,
            Bw + ((size_t)nt * 8 + ch) * 16384 };
#pragma unroll
        for (int t = 0; t < 2; t++) {
            const char* s = srcs[t] + tid * 16;
            const uint32_t d = sb + buf * 32768 + t * 16384 + tid * 16;
#pragma unroll
            for (int i = 0; i < 4; i++)
                cp_async16(d + i * 4096, s + i * 4096);
        }
        cp_commit();
    };

    prefetch(0, 0);
    int buf = 0;
    for (int ch = 0; ch < 8; ch++) {
        if (ch < 7) {
            prefetch(ch + 1, buf ^ 1);
            cp_wait<1>();
        } else {
            cp_wait<0>();
        }
        __syncthreads();

        const uint32_t base = sb + buf * 32768;
#pragma unroll
        for (int ks = 0; ks < 4; ks++) {
            uint32_t aw[2][4];
#pragma unroll
            for (int mi = 0; mi < 2; mi++) {
                const uint32_t off =
                    SWZ128((uint32_t)((wm + mi * 16 + lrow) * 128 + ks * 32 + lcol16 * 16));
                ldmx4(aw[mi], base + off);
            }
            uint32_t bw[8][2];
#pragma unroll
            for (int nj = 0; nj < 4; nj++) {
                const uint32_t off =
                    SWZ128((uint32_t)((wn + nj * 16 + lrow) * 128 + ks * 32 + lcol16 * 16));
                uint32_t t[4];
                ldmx4(t, base + 16384 + off);
                bw[nj*2][0] = t[0]; bw[nj*2+1][0] = t[1];
                bw[nj*2][1] = t[2]; bw[nj*2+1][1] = t[3];
            }
#pragma unroll
            for (int mi = 0; mi < 2; mi++)
#pragma unroll
                for (int ni = 0; ni < 8; ni++)
                    mma_f16(acc[mi][ni], aw[mi], bw[ni]);
        }
        __syncthreads();
        buf ^= 1;
    }

#pragma unroll
    for (int mi = 0; mi < 2; mi++) {
        const int m0 = bm + wm + mi * 16 + (lane >> 2);
        const int m1 = m0 + 8;
        const int or0 = (m0 & 31) * 64 + (m0 >> 5);
        const int or1 = (m1 & 31) * 64 + (m1 >> 5);
#pragma unroll
        for (int ni = 0; ni < 8; ni++) {
            const int n = bn + wn + ni * 8 + (lane & 3) * 2;
            const float b0 = bias[n], b1 = bias[n + 1];
            float2 v0 = make_float2(acc[mi][ni][0] + b0, acc[mi][ni][1] + b1);
            float2 v1 = make_float2(acc[mi][ni][2] + b0, acc[mi][ni][3] + b1);
            *(float2*)(out + (size_t)or0 * 32000 + n) = v0;
            *(float2*)(out + (size_t)or1 * 32000 + n) = v1;
        }
    }
}

// ---------------- register-blocked GRU machinery ----------------
struct Part {
    const float* W;
    int ldW;
    int wco;
    const float* src;
};

template<int NP, bool XSEC>
__device__ __forceinline__ void accum_section(
    float (&acc)[12][4], float (&accx)[4][4],
    Part P, int jbase, int b0, int lane)
{
    const float* Wb = P.W + P.wco;
#pragma unroll
    for (int ps = 0; ps < NP; ps++) {
        const int k = ps * 128 + lane * 4;
        float4 s[4];
#pragma unroll
        for (int bi = 0; bi < 4; bi++)
            s[bi] = __ldcg((const float4*)(P.src + (b0 + bi) * 512 + k));
#pragma unroll
        for (int r = 0; r < 12; r++) {
            const int row = (r >> 2) * 512 + jbase + (r & 3);
            float4 wv = *(const float4*)(Wb + (size_t)row * P.ldW + k);
            float* a = (XSEC && r >= 8) ? accx[r - 8] : acc[r];
#pragma unroll
            for (int bi = 0; bi < 4; bi++) {
                a[bi] = fmaf(s[bi].x, wv.x, a[bi]);
                a[bi] = fmaf(s[bi].y, wv.y, a[bi]);
                a[bi] = fmaf(s[bi].z, wv.z, a[bi]);
                a[bi] = fmaf(s[bi].w, wv.w, a[bi]);
            }
        }
    }
}

template<int NP0, int NP1, int MODE>  // MODE: 0=enc(gi_pre), 2=bx+x
__device__ __forceinline__ void gru_phase(
    int jbase, Part p0, Part p1,
    const float* __restrict__ gi_pre, const float* __restrict__ bx,
    const float* __restrict__ bh, const float* __restrict__ hprev,
    float* __restrict__ hnext, float* __restrict__ yout, int yb)
{
    const int lane = threadIdx.x & 31;
    const int w    = threadIdx.x >> 5;
    const int b0   = w * 4;
    float acc[12][4];
    float accx[4][4];
#pragma unroll
    for (int r = 0; r < 12; r++)
#pragma unroll
        for (int bi = 0; bi < 4; bi++) acc[r][bi] = 0.f;
#pragma unroll
    for (int r = 0; r < 4; r++)
#pragma unroll
        for (int bi = 0; bi < 4; bi++) accx[r][bi] = 0.f;

    accum_section<NP0, false>(acc, accx, p0, jbase, b0, lane);
    if (NP1 > 0) accum_section<NP1, true>(acc, accx, p1, jbase, b0, lane);

#pragma unroll
    for (int r = 0; r < 12; r++)
#pragma unroll
        for (int bi = 0; bi < 4; bi++)
#pragma unroll
            for (int o = 16; o; o >>= 1)
                acc[r][bi] += __shfl_xor_sync(0xffffffffu, acc[r][bi], o);
    if (NP1 > 0) {
#pragma unroll
        for (int r = 0; r < 4; r++)
#pragma unroll
            for (int bi = 0; bi < 4; bi++)
#pragma unroll
                for (int o = 16; o; o >>= 1)
                    accx[r][bi] += __shfl_xor_sync(0xffffffffu, accx[r][bi], o);
    }

    if (lane < 4) {
        const int jl = lane, j = jbase + jl;
        const float bh0 = bh[j], bh1 = bh[512 + j], bh2 = bh[1024 + j];
#pragma unroll
        for (int bi = 0; bi < 4; bi++) {
            const int b = b0 + bi;
            float pr, pz, gin, ghn;
            if (MODE == 0) {
                pr  = gi_pre[b * 1536 + j]        + acc[jl][bi]     + bh0;
                pz  = gi_pre[b * 1536 + 512 + j]  + acc[4 + jl][bi] + bh1;
                gin = gi_pre[b * 1536 + 1024 + j];
                ghn = acc[8 + jl][bi] + bh2;
            } else {
                pr  = bx[j]        + acc[jl][bi]     + bh0;
                pz  = bx[512 + j]  + acc[4 + jl][bi] + bh1;
                gin = bx[1024 + j] + accx[jl][bi];
                ghn = acc[8 + jl][bi] + bh2;
            }
            float r = sigm(pr);
            float z = sigm(pz);
            float n = tanhf(gin + r * ghn);
            float hp = __ldcg(hprev + b * 512 + j);
            float hn = (1.f - z) * n + z * hp;
            hnext[b * 512 + j] = hn;
            if (yout) yout[b * yb + j] = hn;
        }
    }
}

// ---- gh pass + store: 12 recurrent gate dots (+bh) -> g_gh slice ---------
__device__ __forceinline__ void ghpass_store(
    int jbase, const float* __restrict__ Wh, const float* __restrict__ bh,
    const float* __restrict__ h, float* __restrict__ dst /* [3][32][512] */)
{
    const int lane = threadIdx.x & 31;
    const int w    = threadIdx.x >> 5;
    const int b0   = w * 4;
    float acc[12][4];
    float dummy[4][4];
#pragma unroll
    for (int r = 0; r < 12; r++)
#pragma unroll
        for (int bi = 0; bi < 4; bi++) acc[r][bi] = 0.f;
    Part p{Wh, 512, 0, h};
    accum_section<4, false>(acc, dummy, p, jbase, b0, lane);
#pragma unroll
    for (int r = 0; r < 12; r++)
#pragma unroll
        for (int bi = 0; bi < 4; bi++)
#pragma unroll
            for (int o = 16; o; o >>= 1)
                acc[r][bi] += __shfl_xor_sync(0xffffffffu, acc[r][bi], o);
    if (lane < 4) {
        const int jl = lane, j = jbase + jl;
#pragma unroll
        for (int g = 0; g < 3; g++) {
            const float bb = bh[g * 512 + j];
#pragma unroll
            for (int bi = 0; bi < 4; bi++)
                dst[g * 16384 + (b0 + bi) * 512 + j] = acc[g * 4 + jl][bi] + bb;
        }
    }
}

// ---- x-only GRU phase: x-part accum + gates using precomputed gh ---------
template<int MODE>  // 3: gi_pre + gh ; 4: bx + gh
__device__ __forceinline__ void gru_x_phase(
    int jbase, Part p1,
    const float* __restrict__ gi_pre, const float* __restrict__ bx,
    const float* __restrict__ gh /* [3][32][512] */,
    const float* __restrict__ hprev, float* __restrict__ hnext,
    float* __restrict__ yout, int yb)
{
    const int lane = threadIdx.x & 31;
    const int w    = threadIdx.x >> 5;
    const int b0   = w * 4;
    float acc[12][4];
    float accx[4][4];
#pragma unroll
    for (int r = 0; r < 12; r++)
#pragma unroll
        for (int bi = 0; bi < 4; bi++) acc[r][bi] = 0.f;
#pragma unroll
    for (int r = 0; r < 4; r++)
#pragma unroll
        for (int bi = 0; bi < 4; bi++) accx[r][bi] = 0.f;

    accum_section<4, true>(acc, accx, p1, jbase, b0, lane);

#pragma unroll
    for (int r = 0; r < 8; r++)
#pragma unroll
        for (int bi = 0; bi < 4; bi++)
#pragma unroll
            for (int o = 16; o; o >>= 1)
                acc[r][bi] += __shfl_xor_sync(0xffffffffu, acc[r][bi], o);
#pragma unroll
    for (int r = 0; r < 4; r++)
#pragma unroll
        for (int bi = 0; bi < 4; bi++)
#pragma unroll
            for (int o = 16; o; o >>= 1)
                accx[r][bi] += __shfl_xor_sync(0xffffffffu, accx[r][bi], o);

    if (lane < 4) {
        const int jl = lane, j = jbase + jl;
#pragma unroll
        for (int bi = 0; bi < 4; bi++) {
            const int b = b0 + bi;
            const float ghr = __ldcg(gh + b * 512 + j);
            const float ghz = __ldcg(gh + 16384 + b * 512 + j);
            const float ghn = __ldcg(gh + 32768 + b * 512 + j);
            float pr, pz, gin;
            if (MODE == 3) {
                pr  = gi_pre[b * 1536 + j]        + acc[jl][bi]     + ghr;
                pz  = gi_pre[b * 1536 + 512 + j]  + acc[4 + jl][bi] + ghz;
                gin = gi_pre[b * 1536 + 1024 + j] + accx[jl][bi];
            } else {
                pr  = bx[j]        + acc[jl][bi]     + ghr;
                pz  = bx[512 + j]  + acc[4 + jl][bi] + ghz;
                gin = bx[1024 + j] + accx[jl][bi];
            }
            float r = sigm(pr);
            float z = sigm(pz);
            float n = tanhf(gin + r * ghn);
            float hp = __ldcg(hprev + b * 512 + j);
            float hn = (1.f - z) * n + z * hp;
            hnext[b * 512 + j] = hn;
            if (yout) yout[b * yb + j] = hn;
        }
    }
}

// ---------------- fused encoder: layer0 step s + layer1 step s-1 ---------
__global__ __launch_bounds__(256, 1)
void enc_fused_kernel(const float* __restrict__ Wh0, const float* __restrict__ bh0,
                      const float* __restrict__ gi0,
                      const float* __restrict__ Wh1, const float* __restrict__ Wx1,
                      const float* __restrict__ bx1, const float* __restrict__ bh1) {
    unsigned eps = 0;
    const int jbase = blockIdx.x * 4;
    Part pd{nullptr, 0, 0, nullptr};
    for (int s = 0; s < 65; s++) {
        if (s < 64) {
            const int p0 = s & 1;
            Part ph{Wh0, 512, 0, g_hA + p0 * 16384};
            gru_phase<4, 0, 0>(jbase, ph, pd, gi0 + (size_t)s * 49152, nullptr, bh0,
                               g_hA + p0 * 16384, g_hA + (p0 ^ 1) * 16384,
                               g_y0 + (size_t)s * 16384, 512);
        }
        if (s >= 1) {
            const int t1 = s - 1;
            const int p1 = t1 & 1;
            Part ph{Wh1, 512, 0, g_hB + p1 * 16384};
            Part px{Wx1, 512, 0, g_y0 + (size_t)t1 * 16384};
            gru_phase<4, 4, 2>(jbase, ph, px, nullptr, bx1, bh1,
                               g_hB + p1 * 16384, g_hB + (p1 ^ 1) * 16384,
                               g_enc + (size_t)t1 * 512, 32768);
        }
        grid_bar(eps);
    }
}

// ---------------- decoder phase A: q = h1 @ W_attn[:, :512]^T ------------
__device__ __forceinline__ void phaseA(const float* __restrict__ h1,
                                       const float* __restrict__ Wa) {
    const int lane = threadIdx.x & 31;
    const int w    = threadIdx.x >> 5;
    const int b0   = w * 4;
    const int nbase = blockIdx.x * 4;
    float acc[4][4];
#pragma unroll
    for (int r = 0; r < 4; r++)
#pragma unroll
        for (int bi = 0; bi < 4; bi++) acc[r][bi] = 0.f;
#pragma unroll
    for (int ps = 0; ps < 4; ps++) {
        const int k = ps * 128 + lane * 4;
        float4 s[4];
#pragma unroll
        for (int bi = 0; bi < 4; bi++)
            s[bi] = __ldcg((const float4*)(h1 + (b0 + bi) * 512 + k));
#pragma unroll
        for (int r = 0; r < 4; r++) {
            float4 wv = *(const float4*)(Wa + (size_t)(nbase + r) * 1024 + k);
#pragma unroll
            for (int bi = 0; bi < 4; bi++) {
                acc[r][bi] = fmaf(s[bi].x, wv.x, acc[r][bi]);
                acc[r][bi] = fmaf(s[bi].y, wv.y, acc[r][bi]);
                acc[r][bi] = fmaf(s[bi].z, wv.z, acc[r][bi]);
                acc[r][bi] = fmaf(s[bi].w, wv.w, acc[r][bi]);
            }
        }
    }
#pragma unroll
    for (int r = 0; r < 4; r++)
#pragma unroll
        for (int bi = 0; bi < 4; bi++)
#pragma unroll
            for (int o = 16; o; o >>= 1)
                acc[r][bi] += __shfl_xor_sync(0xffffffffu, acc[r][bi], o);
    if (lane < 4) {
#pragma unroll
        for (int bi = 0; bi < 4; bi++)
            g_q[(b0 + bi) * 512 + nbase + lane] = acc[lane][bi];
    }
}

// ---------------- decoder phase B: scores -> softmax -> context ----------
__device__ __forceinline__ void phaseB(const float* __restrict__ v_attn) {
    __shared__ float qv[512];
    __shared__ float vv[512];
    __shared__ float sc[64];
    __shared__ float aw[64];
    const int b = blockIdx.x;
    const int tid = threadIdx.x;
    for (int i = tid; i < 512; i += 256) {
        qv[i] = __ldcg(g_q + b * 512 + i);
        vv[i] = v_attn[i];
    }
    __syncthreads();
    const int w = tid >> 5, lane = tid & 31;
    for (int ss = 0; ss < 8; ss++) {
        const int s = w * 8 + ss;
        const float* Urow = g_U + (size_t)(b * 64 + s) * 512;
        float p = 0.f;
        for (int n = lane; n < 512; n += 32)
            p += vv[n] * tanhf(qv[n] + Urow[n]);
#pragma unroll
        for (int o = 16; o; o >>= 1) p += __shfl_xor_sync(0xffffffffu, p, o);
        if (lane == 0) sc[s] = p;
    }
    __syncthreads();
    if (w == 0) {
        float v0 = sc[lane], v1 = sc[lane + 32];
        float mx = fmaxf(v0, v1);
#pragma unroll
        for (int o = 16; o; o >>= 1) mx = fmaxf(mx, __shfl_xor_sync(0xffffffffu, mx, o));
        float e0 = expf(v0 - mx), e1 = expf(v1 - mx);
        float sm = e0 + e1;
#pragma unroll
        for (int o = 16; o; o >>= 1) sm += __shfl_xor_sync(0xffffffffu, sm, o);
        float inv = 1.f / sm;
        aw[lane]      = e0 * inv;
        aw[lane + 32] = e1 * inv;
    }
    __syncthreads();
    for (int n = tid; n < 512; n += 256) {
        const float* erow = g_enc + (size_t)b * 64 * 512 + n;
        float acc = 0.f;
#pragma unroll 8
        for (int s = 0; s < 64; s++) acc = fmaf(aw[s], erow[s * 512], acc);
        g_ctx[b * 512 + n] = acc;
    }
}

// ---------------- persistent decoder (64 steps, 4 phases each) -----------
// Interval 2: blocks 0-31 run phaseB; blocks 32-127 compute all 1024
// recurrent gate rows (gh for d0 and d1) into g_gh. Phases C/D are x-only.
__global__ __launch_bounds__(256, 1)
void dec_persist_kernel(const float* __restrict__ Wa, const float* __restrict__ v_attn,
                        const float* __restrict__ Wh0, const float* __restrict__ Wx0,
                        const float* __restrict__ bh0,
                        const float* __restrict__ Wh1, const float* __restrict__ Wx1,
                        const float* __restrict__ bx1, const float* __restrict__ bh1) {
    unsigned eps = 0;
    const int jbase = blockIdx.x * 4;
    for (int t = 0; t < 64; t++) {
        const int par = t & 1;
        const float* h0 = g_hA + par * 16384;
        const float* h1 = g_hB + par * 16384;
        float* h0n = g_hA + (par ^ 1) * 16384;
        float* h1n = g_hB + (par ^ 1) * 16384;

        phaseA(h1, Wa);
        grid_bar(eps);

        if (blockIdx.x < 32) {
            phaseB(v_attn);
        } else {
            for (int u = blockIdx.x - 32; u < 256; u += 96) {
                const int layer = u >> 7;
                const int jb = (u & 127) * 4;
                if (layer == 0)
                    ghpass_store(jb, Wh0, bh0, h0, g_gh);
                else
                    ghpass_store(jb, Wh1, bh1, h1, g_gh + 49152);
            }
        }
        grid_bar(eps);

        {   // GRU d0 (x-only): ctx via Wx_d0 cols [256,768), gh from g_gh[0]
            Part px{Wx0, 768, 256, g_ctx};
            gru_x_phase<3>(jbase, px, g_gi + (size_t)t * 49152, nullptr,
                           g_gh, h0, h0n, nullptr, 0);
        }
        grid_bar(eps);

        {   // GRU d1 (x-only): h0' via Wx_d1, gh from g_gh[1]
            Part px{Wx1, 512, 0, h0n};
            gru_x_phase<4>(jbase, px, nullptr, bx1,
                           g_gh + 49152, h1, h1n, g_H1 + (size_t)t * 16384, 512);
        }
        grid_bar(eps);
    }
}

// ---------------- host orchestration ----------------
extern "C" void kernel_launch(void* const* d_in, const int* in_sizes, int n_in,
                              void* d_out, int out_size) {
    (void)in_sizes; (void)n_in; (void)out_size;
    const int*   in_seq = (const int*)d_in[0];
    const int*   tg_seq = (const int*)d_in[1];
    const float* E_enc  = (const float*)d_in[2];
    const float* Wx_e0  = (const float*)d_in[3];
    const float* Wh_e0  = (const float*)d_in[4];
    const float* bx_e0  = (const float*)d_in[5];
    const float* bh_e0  = (const float*)d_in[6];
    const float* Wx_e1  = (const float*)d_in[7];
    const float* Wh_e1  = (const float*)d_in[8];
    const float* bx_e1  = (const float*)d_in[9];
    const float* bh_e1  = (const float*)d_in[10];
    const float* E_dec  = (const float*)d_in[11];
    const float* W_attn = (const float*)d_in[12];
    const float* b_attn = (const float*)d_in[13];
    const float* v_attn = (const float*)d_in[14];
    const float* Wx_d0  = (const float*)d_in[15];
    const float* Wh_d0  = (const float*)d_in[16];
    const float* bx_d0  = (const float*)d_in[17];
    const float* bh_d0  = (const float*)d_in[18];
    const float* Wx_d1  = (const float*)d_in[19];
    const float* Wh_d1  = (const float*)d_in[20];
    const float* bx_d1  = (const float*)d_in[21];
    const float* bh_d1  = (const float*)d_in[22];
    const float* W_out  = (const float*)d_in[23];
    const float* b_out  = (const float*)d_in[24];
    float* out = (float*)d_out;

    float *gi, *y0, *enc, *U, *H1, *hA, *hB;
    int* idx;
    unsigned* bar;
    char *wf, *af;
    cudaGetSymbolAddress((void**)&gi,  g_gi);
    cudaGetSymbolAddress((void**)&y0,  g_y0);
    cudaGetSymbolAddress((void**)&enc, g_enc);
    cudaGetSymbolAddress((void**)&U,   g_U);
    cudaGetSymbolAddress((void**)&H1,  g_H1);
    cudaGetSymbolAddress((void**)&hA,  g_hA);
    cudaGetSymbolAddress((void**)&hB,  g_hB);
    cudaGetSymbolAddress((void**)&idx, g_idx);
    cudaGetSymbolAddress((void**)&bar, g_cnt);
    cudaGetSymbolAddress((void**)&wf,  g_W_f16);
    cudaGetSymbolAddress((void**)&af,  g_A_f16);

    cudaFuncSetAttribute(logits_mma_kernel,
                         cudaFuncAttributeMaxDynamicSharedMemorySize, LM_TOT);

    cudaMemsetAsync(hA, 0, 2 * 32 * 512 * sizeof(float));
    cudaMemsetAsync(hB, 0, 2 * 32 * 512 * sizeof(float));

    // ---- pre-convert W_out to fp16 swizzled tiles (one-time) ----
    convert_single_f16_kernel<<<dim3(250, 8), 256>>>(W_out, wf);

    // ---- encoder: gi_e0 GEMM, then fused 2-layer persistent kernel ----
    build_idx_kernel<<<8, 256>>>(in_seq, tg_seq, idx, 0);
    gemm_nt_kernel<<<dim3(12, 16), 256>>>(E_enc, 256, Wx_e0, 256, bx_e0,
                                          gi, 1536, 256, idx, 0);
    cudaMemsetAsync(bar, 0, sizeof(unsigned));
    enc_fused_kernel<<<NBLK, 256>>>(Wh_e0, bh_e0, gi,
                                    Wh_e1, Wx_e1, bx_e1, bh_e1);

    // U = enc_out @ W_attn[:, 512:]^T + b_attn
    gemm_nt_kernel<<<dim3(4, 16), 256>>>(enc, 512, W_attn + 512, 1024, b_attn,
                                         U, 512, 512, nullptr, 0);
    build_idx_kernel<<<8, 256>>>(in_seq, tg_seq, idx, 1);
    gemm_nt_kernel<<<dim3(12, 16), 256>>>(E_dec, 256, Wx_d0, 768, bx_d0,
                                          gi, 1536, 256, idx, 0);

    // ---- decoder persistent loop ----
    cudaMemsetAsync(bar, 0, sizeof(unsigned));
    dec_persist_kernel<<<NBLK, 256>>>(W_attn, v_attn,
                                      Wh_d0, Wx_d0, bh_d0,
                                      Wh_d1, Wx_d1, bx_d1, bh_d1);

    // ---- convert H1 to fp16 tiles, then logits (single-pass fp16) ----
    convert_single_f16_kernel<<<dim3(16, 8), 256>>>(H1, af);
    logits_mma_kernel<<<dim3(250, 16), 256, LM_TOT>>>(af, wf, b_out, out);
}

// round 15
// speedup vs baseline: 1.1735x; 1.0391x over previous
#include <cuda_runtime.h>
#include <cuda_fp16.h>
#include <cstdint>

#define NBLK 128
#define TPB  512

// ---------------- device scratch (no allocations allowed) ----------------
__device__ float g_gi [2048 * 1536];   // reused: gi_e0 -> gi_dec_emb
__device__ float g_y0 [2048 * 512];    // encoder layer0 outputs [s][b][512]
__device__ float g_enc[2048 * 512];    // encoder outputs [b][s][512]
__device__ float g_U  [2048 * 512];    // enc part of attn energy [b][s][512]
__device__ float g_H1 [2048 * 512];    // decoder top hidden per step [t][b][512]
__device__ float g_hA [2 * 32 * 512];  // layer0 / decoder h0 (ping-pong)
__device__ float g_hB [2 * 32 * 512];  // layer1 / decoder h1 (ping-pong)
__device__ float g_q  [32 * 512];
__device__ float g_ctx[32 * 512];
__device__ float g_gh [2 * 3 * 32 * 512]; // decoder recurrent gates (+bh)
__device__ int   g_idx[2048];
__device__ unsigned g_cnt;             // grid barrier epoch counter
// pre-converted fp16 operand tiles (SW128-swizzled, 16KB per 128x64 tile)
__device__ __half g_W_f16[32000 * 512];   // W_out fp16
__device__ __half g_A_f16[2048 * 512];    // H1 fp16

// ---------------- grid-wide barrier (all NBLK blocks resident) ----------
__device__ __forceinline__ void grid_bar(unsigned &eps) {
    __syncthreads();
    if (threadIdx.x == 0) {
        eps += 1u;
        const unsigned need = eps * NBLK;
        __threadfence();
        atomicAdd(&g_cnt, 1u);
        unsigned v;
        do {
            asm volatile("ld.acquire.gpu.global.u32 %0, [%1];"
                         : "=r"(v) : "l"(&g_cnt));
        } while (v < need);
    }
    __syncthreads();
}

__device__ __forceinline__ float sigm(float x) { return 1.f / (1.f + expf(-x)); }

__device__ __forceinline__ uint32_t smem_u32(const void* p) {
    uint32_t a;
    asm("{ .reg .u64 t; cvta.to.shared.u64 t, %1; cvt.u32.u64 %0, t; }"
        : "=r"(a) : "l"(p));
    return a;
}
#define SWZ128(off) ((off) ^ (((off) >> 3) & 0x70))

__device__ __forceinline__ void ldmx4(uint32_t* t, uint32_t addr) {
    asm volatile("ldmatrix.sync.aligned.m8n8.x4.shared.b16 {%0,%1,%2,%3}, [%4];"
                 : "=r"(t[0]), "=r"(t[1]), "=r"(t[2]), "=r"(t[3]) : "r"(addr));
}
__device__ __forceinline__ void mma_f16(float* d, const uint32_t* a, const uint32_t* b) {
    asm volatile(
        "mma.sync.aligned.m16n8k16.row.col.f32.f16.f16.f32 "
        "{%0,%1,%2,%3}, {%4,%5,%6,%7}, {%8,%9}, {%0,%1,%2,%3};"
        : "+f"(d[0]), "+f"(d[1]), "+f"(d[2]), "+f"(d[3])
        : "r"(a[0]), "r"(a[1]), "r"(a[2]), "r"(a[3]), "r"(b[0]), "r"(b[1]));
}
__device__ __forceinline__ void cp_async16(uint32_t dst, const void* src) {
    asm volatile("cp.async.cg.shared.global [%0], [%1], 16;"
                 :: "r"(dst), "l"(src) : "memory");
}
__device__ __forceinline__ void cp_commit() {
    asm volatile("cp.async.commit_group;" ::: "memory");
}
template <int N>
__device__ __forceinline__ void cp_wait() {
    asm volatile("cp.async.wait_group %0;" :: "n"(N) : "memory");
}

// ---------------- gather index builder ----------------
__global__ void build_idx_kernel(const int* __restrict__ in_seq,
                                 const int* __restrict__ tg_seq,
                                 int* __restrict__ idx, int mode) {
    int m = blockIdx.x * 256 + threadIdx.x;
    if (m >= 2048) return;
    int b = m & 31, t = m >> 5;
    if (mode == 0) idx[m] = in_seq[b * 64 + t];
    else           idx[m] = (t == 0) ? 0 : tg_seq[b * 64 + t - 1];
}

// ------- f32 -> fp16 single into SW128 swizzled 128x64 tiles --------------
__global__ __launch_bounds__(256)
void convert_single_f16_kernel(const float* __restrict__ src,
                               char* __restrict__ dst) {
    const int tid = threadIdx.x;
    const int rb = blockIdx.x * 128;
    const int kc = blockIdx.y * 64;
    const size_t tb = ((size_t)blockIdx.x * 8 + blockIdx.y) * 16384;
#pragma unroll
    for (int it = 0; it < 8; it++) {
        const int idx = tid + it * 256;
        const int r  = idx >> 4;
        const int c4 = idx & 15;
        float4 v = *(const float4*)(src + (size_t)(rb + r) * 512 + kc + c4 * 4);
        __half2 h01 = __floats2half2_rn(v.x, v.y);
        __half2 h23 = __floats2half2_rn(v.z, v.w);
        const uint32_t sw = SWZ128((uint32_t)(r * 128 + (c4 >> 1) * 16)) + (c4 & 1) * 8;
        *(__half2*)(dst + tb + sw)     = h01;
        *(__half2*)(dst + tb + sw + 4) = h23;
    }
}

// ---------------- SGEMM-NT: C[M,N] = A[M,K] * B[N,K]^T (+bias) ------------
__global__ __launch_bounds__(256)
void gemm_nt_kernel(const float* __restrict__ A, int lda,
                    const float* __restrict__ Bm, int ldb,
                    const float* __restrict__ bias,
                    float* __restrict__ C, int N, int K,
                    const int* __restrict__ gidx, int outmode) {
    const int tid = threadIdx.x;
    const int bn = blockIdx.x * 128;
    const int bm = blockIdx.y * 128;
    __shared__ float As[2][16][132];
    __shared__ float Bs[2][16][132];
    const int tx = tid & 15, ty = tid >> 4;
    float acc[8][8];
#pragma unroll
    for (int i = 0; i < 8; i++)
#pragma unroll
        for (int j = 0; j < 8; j++) acc[i][j] = 0.f;

    const int lrow = tid >> 1;
    const int lk   = (tid & 1) * 8;
    int arow = gidx ? gidx[bm + lrow] : (bm + lrow);
    const float* Ap = A  + (size_t)arow        * lda + lk;
    const float* Bp = Bm + (size_t)(bn + lrow) * ldb + lk;

    {
        float4 a0 = *(const float4*)(Ap);
        float4 a1 = *(const float4*)(Ap + 4);
        float4 b0 = *(const float4*)(Bp);
        float4 b1 = *(const float4*)(Bp + 4);
        As[0][lk+0][lrow]=a0.x; As[0][lk+1][lrow]=a0.y; As[0][lk+2][lrow]=a0.z; As[0][lk+3][lrow]=a0.w;
        As[0][lk+4][lrow]=a1.x; As[0][lk+5][lrow]=a1.y; As[0][lk+6][lrow]=a1.z; As[0][lk+7][lrow]=a1.w;
        Bs[0][lk+0][lrow]=b0.x; Bs[0][lk+1][lrow]=b0.y; Bs[0][lk+2][lrow]=b0.z; Bs[0][lk+3][lrow]=b0.w;
        Bs[0][lk+4][lrow]=b1.x; Bs[0][lk+5][lrow]=b1.y; Bs[0][lk+6][lrow]=b1.z; Bs[0][lk+7][lrow]=b1.w;
    }
    __syncthreads();
    int buf = 0;
    for (int kc = 0; kc < K; kc += 16) {
        if (kc + 16 < K) {
            float4 a0 = *(const float4*)(Ap + kc + 16);
            float4 a1 = *(const float4*)(Ap + kc + 20);
            float4 b0 = *(const float4*)(Bp + kc + 16);
            float4 b1 = *(const float4*)(Bp + kc + 20);
            const int nb = buf ^ 1;
            As[nb][lk+0][lrow]=a0.x; As[nb][lk+1][lrow]=a0.y; As[nb][lk+2][lrow]=a0.z; As[nb][lk+3][lrow]=a0.w;
            As[nb][lk+4][lrow]=a1.x; As[nb][lk+5][lrow]=a1.y; As[nb][lk+6][lrow]=a1.z; As[nb][lk+7][lrow]=a1.w;
            Bs[nb][lk+0][lrow]=b0.x; Bs[nb][lk+1][lrow]=b0.y; Bs[nb][lk+2][lrow]=b0.z; Bs[nb][lk+3][lrow]=b0.w;
            Bs[nb][lk+4][lrow]=b1.x; Bs[nb][lk+5][lrow]=b1.y; Bs[nb][lk+6][lrow]=b1.z; Bs[nb][lk+7][lrow]=b1.w;
        }
#pragma unroll
        for (int kk = 0; kk < 16; kk++) {
            float4 alo = *(const float4*)&As[buf][kk][ty * 4];
            float4 ahi = *(const float4*)&As[buf][kk][64 + ty * 4];
            float4 blo = *(const float4*)&Bs[buf][kk][tx * 4];
            float4 bhi = *(const float4*)&Bs[buf][kk][64 + tx * 4];
            float a[8] = {alo.x, alo.y, alo.z, alo.w, ahi.x, ahi.y, ahi.z, ahi.w};
            float b[8] = {blo.x, blo.y, blo.z, blo.w, bhi.x, bhi.y, bhi.z, bhi.w};
#pragma unroll
            for (int i = 0; i < 8; i++)
#pragma unroll
                for (int j = 0; j < 8; j++)
                    acc[i][j] = fmaf(a[i], b[j], acc[i][j]);
        }
        __syncthreads();
        buf ^= 1;
    }
#pragma unroll
    for (int i = 0; i < 8; i++) {
        const int m = bm + ((i < 4) ? (ty * 4 + i) : (64 + ty * 4 + i - 4));
        const int orow = (outmode == 1) ? ((m & 31) * 64 + (m >> 5)) : m;
        float* crow = C + (size_t)orow * N;
#pragma unroll
        for (int j = 0; j < 8; j++) {
            const int n = bn + ((j < 4) ? (tx * 4 + j) : (64 + tx * 4 + j - 4));
            float v = acc[i][j];
            if (bias) v += bias[n];
            crow[n] = v;
        }
    }
}

// ====== logits GEMM: single-pass fp16 mma.sync ======
#define LM_TOT 65536

__global__ __launch_bounds__(256, 2)
void logits_mma_kernel(const char* __restrict__ Aw,
                       const char* __restrict__ Bw,
                       const float* __restrict__ bias,
                       float* __restrict__ out) {
    extern __shared__ char smem[];
    const uint32_t sb = smem_u32(smem);
    const int tid  = threadIdx.x;
    const int wid  = tid >> 5;
    const int lane = tid & 31;
    const int mt = blockIdx.y;
    const int nt = blockIdx.x;
    const int bm = mt * 128;
    const int bn = nt * 128;
    const int wm = (wid & 3) * 32;
    const int wn = (wid >> 2) * 64;

    float acc[2][8][4];
#pragma unroll
    for (int mi = 0; mi < 2; mi++)
#pragma unroll
        for (int ni = 0; ni < 8; ni++)
#pragma unroll
            for (int e = 0; e < 4; e++) acc[mi][ni][e] = 0.f;

    const int lrow = lane & 15;
    const int lcol16 = lane >> 4;

    auto prefetch = [&](int ch, int buf) {
        const char* srcs[2] = {
            Aw + ((size_t)mt * 8 + ch) * 16384,
            Bw + ((size_t)nt * 8 + ch) * 16384 };
#pragma unroll
        for (int t = 0; t < 2; t++) {
            const char* s = srcs[t] + tid * 16;
            const uint32_t d = sb + buf * 32768 + t * 16384 + tid * 16;
#pragma unroll
            for (int i = 0; i < 4; i++)
                cp_async16(d + i * 4096, s + i * 4096);
        }
        cp_commit();
    };

    prefetch(0, 0);
    int buf = 0;
    for (int ch = 0; ch < 8; ch++) {
        if (ch < 7) {
            prefetch(ch + 1, buf ^ 1);
            cp_wait<1>();
        } else {
            cp_wait<0>();
        }
        __syncthreads();

        const uint32_t base = sb + buf * 32768;
#pragma unroll
        for (int ks = 0; ks < 4; ks++) {
            uint32_t aw[2][4];
#pragma unroll
            for (int mi = 0; mi < 2; mi++) {
                const uint32_t off =
                    SWZ128((uint32_t)((wm + mi * 16 + lrow) * 128 + ks * 32 + lcol16 * 16));
                ldmx4(aw[mi], base + off);
            }
            uint32_t bw[8][2];
#pragma unroll
            for (int nj = 0; nj < 4; nj++) {
                const uint32_t off =
                    SWZ128((uint32_t)((wn + nj * 16 + lrow) * 128 + ks * 32 + lcol16 * 16));
                uint32_t t[4];
                ldmx4(t, base + 16384 + off);
                bw[nj*2][0] = t[0]; bw[nj*2+1][0] = t[1];
                bw[nj*2][1] = t[2]; bw[nj*2+1][1] = t[3];
            }
#pragma unroll
            for (int mi = 0; mi < 2; mi++)
#pragma unroll
                for (int ni = 0; ni < 8; ni++)
                    mma_f16(acc[mi][ni], aw[mi], bw[ni]);
        }
        __syncthreads();
        buf ^= 1;
    }

#pragma unroll
    for (int mi = 0; mi < 2; mi++) {
        const int m0 = bm + wm + mi * 16 + (lane >> 2);
        const int m1 = m0 + 8;
        const int or0 = (m0 & 31) * 64 + (m0 >> 5);
        const int or1 = (m1 & 31) * 64 + (m1 >> 5);
#pragma unroll
        for (int ni = 0; ni < 8; ni++) {
            const int n = bn + wn + ni * 8 + (lane & 3) * 2;
            const float b0 = bias[n], b1 = bias[n + 1];
            float2 v0 = make_float2(acc[mi][ni][0] + b0, acc[mi][ni][1] + b1);
            float2 v1 = make_float2(acc[mi][ni][2] + b0, acc[mi][ni][3] + b1);
            *(float2*)(out + (size_t)or0 * 32000 + n) = v0;
            *(float2*)(out + (size_t)or1 * 32000 + n) = v1;
        }
    }
}

// ---------------- j-split register-blocked GRU machinery ------------------
// 512 threads: warp w -> wg = w&7 (4 batches), jh = w>>3 (2 of 4 j).
// Each warp computes 6 gate rows (3 gates x 2 j) for its 4 batches over
// the full K. No cross-warp combine: j-half warps write disjoint outputs.
struct Part {
    const float* W;
    int ldW;
    int wco;
    const float* src;
};

// acc rows: r = g*2 + jl2 (g in 0..2, jl2 in 0..1). If XSEC, the n-gate
// (g==2) of this section goes to accx[jl2] instead.
template<int NP, bool XSEC>
__device__ __forceinline__ void accum_js(
    float (&acc)[6][4], float (&accx)[2][4],
    Part P, int jb2, int b0, int lane)
{
    const float* Wb = P.W + P.wco;
#pragma unroll
    for (int ps = 0; ps < NP; ps++) {
        const int k = ps * 128 + lane * 4;
        float4 s[4];
#pragma unroll
        for (int bi = 0; bi < 4; bi++)
            s[bi] = __ldcg((const float4*)(P.src + (b0 + bi) * 512 + k));
#pragma unroll
        for (int r = 0; r < 6; r++) {
            const int row = (r >> 1) * 512 + jb2 + (r & 1);
            float4 wv = *(const float4*)(Wb + (size_t)row * P.ldW + k);
            float* a = (XSEC && r >= 4) ? accx[r - 4] : acc[r];
#pragma unroll
            for (int bi = 0; bi < 4; bi++) {
                a[bi] = fmaf(s[bi].x, wv.x, a[bi]);
                a[bi] = fmaf(s[bi].y, wv.y, a[bi]);
                a[bi] = fmaf(s[bi].z, wv.z, a[bi]);
                a[bi] = fmaf(s[bi].w, wv.w, a[bi]);
            }
        }
    }
}

template<int NP0, int NP1, int MODE>  // MODE: 0=enc(gi_pre), 2=bx+x
__device__ __forceinline__ void gru_phase(
    int jbase, Part p0, Part p1,
    const float* __restrict__ gi_pre, const float* __restrict__ bx,
    const float* __restrict__ bh, const float* __restrict__ hprev,
    float* __restrict__ hnext, float* __restrict__ yout, int yb)
{
    const int lane = threadIdx.x & 31;
    const int w    = threadIdx.x >> 5;
    const int wg   = w & 7;
    const int jh   = w >> 3;
    const int b0   = wg * 4;
    const int jb2  = jbase + jh * 2;
    float acc[6][4];
    float accx[2][4];
#pragma unroll
    for (int r = 0; r < 6; r++)
#pragma unroll
        for (int bi = 0; bi < 4; bi++) acc[r][bi] = 0.f;
#pragma unroll
    for (int r = 0; r < 2; r++)
#pragma unroll
        for (int bi = 0; bi < 4; bi++) accx[r][bi] = 0.f;

    accum_js<NP0, false>(acc, accx, p0, jb2, b0, lane);
    if (NP1 > 0) accum_js<NP1, true>(acc, accx, p1, jb2, b0, lane);

#pragma unroll
    for (int r = 0; r < 6; r++)
#pragma unroll
        for (int bi = 0; bi < 4; bi++)
#pragma unroll
            for (int o = 16; o; o >>= 1)
                acc[r][bi] += __shfl_xor_sync(0xffffffffu, acc[r][bi], o);
    if (NP1 > 0) {
#pragma unroll
        for (int r = 0; r < 2; r++)
#pragma unroll
            for (int bi = 0; bi < 4; bi++)
#pragma unroll
                for (int o = 16; o; o >>= 1)
                    accx[r][bi] += __shfl_xor_sync(0xffffffffu, accx[r][bi], o);
    }

    if (lane < 2) {
        const int jl2 = lane, j = jb2 + jl2;
        const float bh0 = bh[j], bh1 = bh[512 + j], bh2 = bh[1024 + j];
#pragma unroll
        for (int bi = 0; bi < 4; bi++) {
            const int b = b0 + bi;
            float pr, pz, gin, ghn;
            if (MODE == 0) {
                pr  = gi_pre[b * 1536 + j]        + acc[jl2][bi]     + bh0;
                pz  = gi_pre[b * 1536 + 512 + j]  + acc[2 + jl2][bi] + bh1;
                gin = gi_pre[b * 1536 + 1024 + j];
                ghn = acc[4 + jl2][bi] + bh2;
            } else {
                pr  = bx[j]        + acc[jl2][bi]     + bh0;
                pz  = bx[512 + j]  + acc[2 + jl2][bi] + bh1;
                gin = bx[1024 + j] + accx[jl2][bi];
                ghn = acc[4 + jl2][bi] + bh2;
            }
            float r = sigm(pr);
            float z = sigm(pz);
            float n = tanhf(gin + r * ghn);
            float hp = __ldcg(hprev + b * 512 + j);
            float hn = (1.f - z) * n + z * hp;
            hnext[b * 512 + j] = hn;
            if (yout) yout[b * yb + j] = hn;
        }
    }
}

// ---- gh pass + store: 6 recurrent gate dots (+bh) -> g_gh slice ----------
__device__ __forceinline__ void ghpass_store(
    int jbase, const float* __restrict__ Wh, const float* __restrict__ bh,
    const float* __restrict__ h, float* __restrict__ dst /* [3][32][512] */)
{
    const int lane = threadIdx.x & 31;
    const int w    = threadIdx.x >> 5;
    const int wg   = w & 7;
    const int jh   = w >> 3;
    const int b0   = wg * 4;
    const int jb2  = jbase + jh * 2;
    float acc[6][4];
    float dummy[2][4];
#pragma unroll
    for (int r = 0; r < 6; r++)
#pragma unroll
        for (int bi = 0; bi < 4; bi++) acc[r][bi] = 0.f;
    Part p{Wh, 512, 0, h};
    accum_js<4, false>(acc, dummy, p, jb2, b0, lane);
#pragma unroll
    for (int r = 0; r < 6; r++)
#pragma unroll
        for (int bi = 0; bi < 4; bi++)
#pragma unroll
            for (int o = 16; o; o >>= 1)
                acc[r][bi] += __shfl_xor_sync(0xffffffffu, acc[r][bi], o);
    if (lane < 2) {
        const int jl2 = lane, j = jb2 + jl2;
#pragma unroll
        for (int g = 0; g < 3; g++) {
            const float bb = bh[g * 512 + j];
#pragma unroll
            for (int bi = 0; bi < 4; bi++)
                dst[g * 16384 + (b0 + bi) * 512 + j] = acc[g * 2 + jl2][bi] + bb;
        }
    }
}

// ---- x-only GRU phase: x-part accum + gates using precomputed gh ---------
template<int MODE>  // 3: gi_pre + gh ; 4: bx + gh
__device__ __forceinline__ void gru_x_phase(
    int jbase, Part p1,
    const float* __restrict__ gi_pre, const float* __restrict__ bx,
    const float* __restrict__ gh /* [3][32][512] */,
    const float* __restrict__ hprev, float* __restrict__ hnext,
    float* __restrict__ yout, int yb)
{
    const int lane = threadIdx.x & 31;
    const int w    = threadIdx.x >> 5;
    const int wg   = w & 7;
    const int jh   = w >> 3;
    const int b0   = wg * 4;
    const int jb2  = jbase + jh * 2;
    float acc[6][4];
    float accx[2][4];
#pragma unroll
    for (int r = 0; r < 6; r++)
#pragma unroll
        for (int bi = 0; bi < 4; bi++) acc[r][bi] = 0.f;
#pragma unroll
    for (int r = 0; r < 2; r++)
#pragma unroll
        for (int bi = 0; bi < 4; bi++) accx[r][bi] = 0.f;

    accum_js<4, true>(acc, accx, p1, jb2, b0, lane);

#pragma unroll
    for (int r = 0; r < 4; r++)
#pragma unroll
        for (int bi = 0; bi < 4; bi++)
#pragma unroll
            for (int o = 16; o; o >>= 1)
                acc[r][bi] += __shfl_xor_sync(0xffffffffu, acc[r][bi], o);
#pragma unroll
    for (int r = 0; r < 2; r++)
#pragma unroll
        for (int bi = 0; bi < 4; bi++)
#pragma unroll
            for (int o = 16; o; o >>= 1)
                accx[r][bi] += __shfl_xor_sync(0xffffffffu, accx[r][bi], o);

    if (lane < 2) {
        const int jl2 = lane, j = jb2 + jl2;
#pragma unroll
        for (int bi = 0; bi < 4; bi++) {
            const int b = b0 + bi;
            const float ghr = __ldcg(gh + b * 512 + j);
            const float ghz = __ldcg(gh + 16384 + b * 512 + j);
            const float ghn = __ldcg(gh + 32768 + b * 512 + j);
            float pr, pz, gin;
            if (MODE == 3) {
                pr  = gi_pre[b * 1536 + j]        + acc[jl2][bi]     + ghr;
                pz  = gi_pre[b * 1536 + 512 + j]  + acc[2 + jl2][bi] + ghz;
                gin = gi_pre[b * 1536 + 1024 + j] + accx[jl2][bi];
            } else {
                pr  = bx[j]        + acc[jl2][bi]     + ghr;
                pz  = bx[512 + j]  + acc[2 + jl2][bi] + ghz;
                gin = bx[1024 + j] + accx[jl2][bi];
            }
            float r = sigm(pr);
            float z = sigm(pz);
            float n = tanhf(gin + r * ghn);
            float hp = __ldcg(hprev + b * 512 + j);
            float hn = (1.f - z) * n + z * hp;
            hnext[b * 512 + j] = hn;
            if (yout) yout[b * yb + j] = hn;
        }
    }
}

// ---------------- fused encoder: layer0 step s + layer1 step s-1 ---------
__global__ __launch_bounds__(TPB, 1)
void enc_fused_kernel(const float* __restrict__ Wh0, const float* __restrict__ bh0,
                      const float* __restrict__ gi0,
                      const float* __restrict__ Wh1, const float* __restrict__ Wx1,
                      const float* __restrict__ bx1, const float* __restrict__ bh1) {
    unsigned eps = 0;
    const int jbase = blockIdx.x * 4;
    Part pd{nullptr, 0, 0, nullptr};
    for (int s = 0; s < 65; s++) {
        if (s < 64) {
            const int p0 = s & 1;
            Part ph{Wh0, 512, 0, g_hA + p0 * 16384};
            gru_phase<4, 0, 0>(jbase, ph, pd, gi0 + (size_t)s * 49152, nullptr, bh0,
                               g_hA + p0 * 16384, g_hA + (p0 ^ 1) * 16384,
                               g_y0 + (size_t)s * 16384, 512);
        }
        if (s >= 1) {
            const int t1 = s - 1;
            const int p1 = t1 & 1;
            Part ph{Wh1, 512, 0, g_hB + p1 * 16384};
            Part px{Wx1, 512, 0, g_y0 + (size_t)t1 * 16384};
            gru_phase<4, 4, 2>(jbase, ph, px, nullptr, bx1, bh1,
                               g_hB + p1 * 16384, g_hB + (p1 ^ 1) * 16384,
                               g_enc + (size_t)t1 * 512, 32768);
        }
        grid_bar(eps);
    }
}

// ---------------- decoder phase A: q = h1 @ W_attn[:, :512]^T ------------
// 16 warps: wg = w&7 (4 batches), nh = w>>3 (2 of 4 n rows).
__device__ __forceinline__ void phaseA(const float* __restrict__ h1,
                                       const float* __restrict__ Wa) {
    const int lane = threadIdx.x & 31;
    const int w    = threadIdx.x >> 5;
    const int wg   = w & 7;
    const int nh   = w >> 3;
    const int b0   = wg * 4;
    const int nb2  = blockIdx.x * 4 + nh * 2;
    float acc[2][4];
#pragma unroll
    for (int r = 0; r < 2; r++)
#pragma unroll
        for (int bi = 0; bi < 4; bi++) acc[r][bi] = 0.f;
#pragma unroll
    for (int ps = 0; ps < 4; ps++) {
        const int k = ps * 128 + lane * 4;
        float4 s[4];
#pragma unroll
        for (int bi = 0; bi < 4; bi++)
            s[bi] = __ldcg((const float4*)(h1 + (b0 + bi) * 512 + k));
#pragma unroll
        for (int r = 0; r < 2; r++) {
            float4 wv = *(const float4*)(Wa + (size_t)(nb2 + r) * 1024 + k);
#pragma unroll
            for (int bi = 0; bi < 4; bi++) {
                acc[r][bi] = fmaf(s[bi].x, wv.x, acc[r][bi]);
                acc[r][bi] = fmaf(s[bi].y, wv.y, acc[r][bi]);
                acc[r][bi] = fmaf(s[bi].z, wv.z, acc[r][bi]);
                acc[r][bi] = fmaf(s[bi].w, wv.w, acc[r][bi]);
            }
        }
    }
#pragma unroll
    for (int r = 0; r < 2; r++)
#pragma unroll
        for (int bi = 0; bi < 4; bi++)
#pragma unroll
            for (int o = 16; o; o >>= 1)
                acc[r][bi] += __shfl_xor_sync(0xffffffffu, acc[r][bi], o);
    if (lane < 2) {
#pragma unroll
        for (int bi = 0; bi < 4; bi++)
            g_q[(b0 + bi) * 512 + nb2 + lane] = acc[lane][bi];
    }
}

// ---------------- decoder phase B: scores -> softmax -> context ----------
__device__ __forceinline__ void phaseB(const float* __restrict__ v_attn) {
    __shared__ float qv[512];
    __shared__ float vv[512];
    __shared__ float sc[64];
    __shared__ float aw[64];
    const int b = blockIdx.x;
    const int tid = threadIdx.x;
    if (tid < 512) {
        qv[tid] = __ldcg(g_q + b * 512 + tid);
        vv[tid] = v_attn[tid];
    }
    __syncthreads();
    const int w = tid >> 5, lane = tid & 31;
    for (int ss = 0; ss < 4; ss++) {
        const int s = w * 4 + ss;
        const float* Urow = g_U + (size_t)(b * 64 + s) * 512;
        float p = 0.f;
        for (int n = lane; n < 512; n += 32)
            p += vv[n] * tanhf(qv[n] + Urow[n]);
#pragma unroll
        for (int o = 16; o; o >>= 1) p += __shfl_xor_sync(0xffffffffu, p, o);
        if (lane == 0) sc[s] = p;
    }
    __syncthreads();
    if (w == 0) {
        float v0 = sc[lane], v1 = sc[lane + 32];
        float mx = fmaxf(v0, v1);
#pragma unroll
        for (int o = 16; o; o >>= 1) mx = fmaxf(mx, __shfl_xor_sync(0xffffffffu, mx, o));
        float e0 = expf(v0 - mx), e1 = expf(v1 - mx);
        float sm = e0 + e1;
#pragma unroll
        for (int o = 16; o; o >>= 1) sm += __shfl_xor_sync(0xffffffffu, sm, o);
        float inv = 1.f / sm;
        aw[lane]      = e0 * inv;
        aw[lane + 32] = e1 * inv;
    }
    __syncthreads();
    if (tid < 512) {
        const float* erow = g_enc + (size_t)b * 64 * 512 + tid;
        float acc = 0.f;
#pragma unroll 8
        for (int s = 0; s < 64; s++) acc = fmaf(aw[s], erow[s * 512], acc);
        g_ctx[b * 512 + tid] = acc;
    }
}

// ---------------- persistent decoder (64 steps, 4 phases each) -----------
__global__ __launch_bounds__(TPB, 1)
void dec_persist_kernel(const float* __restrict__ Wa, const float* __restrict__ v_attn,
                        const float* __restrict__ Wh0, const float* __restrict__ Wx0,
                        const float* __restrict__ bh0,
                        const float* __restrict__ Wh1, const float* __restrict__ Wx1,
                        const float* __restrict__ bx1, const float* __restrict__ bh1) {
    unsigned eps = 0;
    const int jbase = blockIdx.x * 4;
    for (int t = 0; t < 64; t++) {
        const int par = t & 1;
        const float* h0 = g_hA + par * 16384;
        const float* h1 = g_hB + par * 16384;
        float* h0n = g_hA + (par ^ 1) * 16384;
        float* h1n = g_hB + (par ^ 1) * 16384;

        phaseA(h1, Wa);
        grid_bar(eps);

        if (blockIdx.x < 32) {
            phaseB(v_attn);
        } else {
            for (int u = blockIdx.x - 32; u < 256; u += 96) {
                const int layer = u >> 7;
                const int jb = (u & 127) * 4;
                if (layer == 0)
                    ghpass_store(jb, Wh0, bh0, h0, g_gh);
                else
                    ghpass_store(jb, Wh1, bh1, h1, g_gh + 49152);
            }
        }
        grid_bar(eps);

        {   // GRU d0 (x-only): ctx via Wx_d0 cols [256,768), gh from g_gh[0]
            Part px{Wx0, 768, 256, g_ctx};
            gru_x_phase<3>(jbase, px, g_gi + (size_t)t * 49152, nullptr,
                           g_gh, h0, h0n, nullptr, 0);
        }
        grid_bar(eps);

        {   // GRU d1 (x-only): h0' via Wx_d1, gh from g_gh[1]
            Part px{Wx1, 512, 0, h0n};
            gru_x_phase<4>(jbase, px, nullptr, bx1,
                           g_gh + 49152, h1, h1n, g_H1 + (size_t)t * 16384, 512);
        }
        grid_bar(eps);
    }
}

// ---------------- host orchestration ----------------
extern "C" void kernel_launch(void* const* d_in, const int* in_sizes, int n_in,
                              void* d_out, int out_size) {
    (void)in_sizes; (void)n_in; (void)out_size;
    const int*   in_seq = (const int*)d_in[0];
    const int*   tg_seq = (const int*)d_in[1];
    const float* E_enc  = (const float*)d_in[2];
    const float* Wx_e0  = (const float*)d_in[3];
    const float* Wh_e0  = (const float*)d_in[4];
    const float* bx_e0  = (const float*)d_in[5];
    const float* bh_e0  = (const float*)d_in[6];
    const float* Wx_e1  = (const float*)d_in[7];
    const float* Wh_e1  = (const float*)d_in[8];
    const float* bx_e1  = (const float*)d_in[9];
    const float* bh_e1  = (const float*)d_in[10];
    const float* E_dec  = (const float*)d_in[11];
    const float* W_attn = (const float*)d_in[12];
    const float* b_attn = (const float*)d_in[13];
    const float* v_attn = (const float*)d_in[14];
    const float* Wx_d0  = (const float*)d_in[15];
    const float* Wh_d0  = (const float*)d_in[16];
    const float* bx_d0  = (const float*)d_in[17];
    const float* bh_d0  = (const float*)d_in[18];
    const float* Wx_d1  = (const float*)d_in[19];
    const float* Wh_d1  = (const float*)d_in[20];
    const float* bx_d1  = (const float*)d_in[21];
    const float* bh_d1  = (const float*)d_in[22];
    const float* W_out  = (const float*)d_in[23];
    const float* b_out  = (const float*)d_in[24];
    float* out = (float*)d_out;

    float *gi, *y0, *enc, *U, *H1, *hA, *hB;
    int* idx;
    unsigned* bar;
    char *wf, *af;
    cudaGetSymbolAddress((void**)&gi,  g_gi);
    cudaGetSymbolAddress((void**)&y0,  g_y0);
    cudaGetSymbolAddress((void**)&enc, g_enc);
    cudaGetSymbolAddress((void**)&U,   g_U);
    cudaGetSymbolAddress((void**)&H1,  g_H1);
    cudaGetSymbolAddress((void**)&hA,  g_hA);
    cudaGetSymbolAddress((void**)&hB,  g_hB);
    cudaGetSymbolAddress((void**)&idx, g_idx);
    cudaGetSymbolAddress((void**)&bar, g_cnt);
    cudaGetSymbolAddress((void**)&wf,  g_W_f16);
    cudaGetSymbolAddress((void**)&af,  g_A_f16);

    cudaFuncSetAttribute(logits_mma_kernel,
                         cudaFuncAttributeMaxDynamicSharedMemorySize, LM_TOT);

    cudaMemsetAsync(hA, 0, 2 * 32 * 512 * sizeof(float));
    cudaMemsetAsync(hB, 0, 2 * 32 * 512 * sizeof(float));

    // ---- pre-convert W_out to fp16 swizzled tiles (one-time) ----
    convert_single_f16_kernel<<<dim3(250, 8), 256>>>(W_out, wf);

    // ---- encoder: gi_e0 GEMM, then fused 2-layer persistent kernel ----
    build_idx_kernel<<<8, 256>>>(in_seq, tg_seq, idx, 0);
    gemm_nt_kernel<<<dim3(12, 16), 256>>>(E_enc, 256, Wx_e0, 256, bx_e0,
                                          gi, 1536, 256, idx, 0);
    cudaMemsetAsync(bar, 0, sizeof(unsigned));
    enc_fused_kernel<<<NBLK, TPB>>>(Wh_e0, bh_e0, gi,
                                    Wh_e1, Wx_e1, bx_e1, bh_e1);

    // U = enc_out @ W_attn[:, 512:]^T + b_attn
    gemm_nt_kernel<<<dim3(4, 16), 256>>>(enc, 512, W_attn + 512, 1024, b_attn,
                                         U, 512, 512, nullptr, 0);
    build_idx_kernel<<<8, 256>>>(in_seq, tg_seq, idx, 1);
    gemm_nt_kernel<<<dim3(12, 16), 256>>>(E_dec, 256, Wx_d0, 768, bx_d0,
                                          gi, 1536, 256, idx, 0);

    // ---- decoder persistent loop ----
    cudaMemsetAsync(bar, 0, sizeof(unsigned));
    dec_persist_kernel<<<NBLK, TPB>>>(W_attn, v_attn,
                                      Wh_d0, Wx_d0, bh_d0,
                                      Wh_d1, Wx_d1, bx_d1, bh_d1);

    // ---- convert H1 to fp16 tiles, then logits (single-pass fp16) ----
    convert_single_f16_kernel<<<dim3(16, 8), 256>>>(H1, af);
    logits_mma_kernel<<<dim3(250, 16), 256, LM_TOT>>>(af, wf, b_out, out);
}

// round 16
// speedup vs baseline: 1.2007x; 1.0232x over previous
#include <cuda_runtime.h>
#include <cuda_fp16.h>
#include <cstdint>

#define NBLK 128

// ---------------- device scratch (no allocations allowed) ----------------
__device__ float g_gi [2048 * 1536];   // reused: gi_e0 -> gi_dec_emb
__device__ float g_y0 [2048 * 512];    // encoder layer0 outputs [s][b][512]
__device__ float g_enc[2048 * 512];    // encoder outputs [b][s][512]
__device__ float g_U  [2048 * 512];    // enc part of attn energy [b][s][512]
__device__ float g_H1 [2048 * 512];    // decoder top hidden per step [t][b][512]
__device__ float g_hA [2 * 32 * 512];  // layer0 / decoder h0 (ping-pong)
__device__ float g_hB [2 * 32 * 512];  // layer1 / decoder h1 (ping-pong)
__device__ float g_q  [32 * 512];
__device__ float g_ctx[32 * 512];
__device__ float g_gh [2 * 3 * 32 * 512]; // decoder recurrent gates (+bh)
__device__ int   g_idx[2048];
__device__ unsigned g_cnt;             // grid barrier epoch counter
// pre-converted fp16 operand tiles (SW128-swizzled, 16KB per 128x64 tile)
__device__ __half g_W_f16[32000 * 512];   // W_out fp16
__device__ __half g_A_f16[2048 * 512];    // H1 fp16

// ---------------- grid-wide barrier (all NBLK blocks resident) ----------
__device__ __forceinline__ void grid_bar(unsigned &eps) {
    __syncthreads();
    if (threadIdx.x == 0) {
        eps += 1u;
        const unsigned need = eps * NBLK;
        __threadfence();
        atomicAdd(&g_cnt, 1u);
        unsigned v;
        do {
            asm volatile("ld.acquire.gpu.global.u32 %0, [%1];"
                         : "=r"(v) : "l"(&g_cnt));
        } while (v < need);
    }
    __syncthreads();
}

__device__ __forceinline__ float sigm(float x) { return 1.f / (1.f + expf(-x)); }

__device__ __forceinline__ uint32_t smem_u32(const void* p) {
    uint32_t a;
    asm("{ .reg .u64 t; cvta.to.shared.u64 t, %1; cvt.u32.u64 %0, t; }"
        : "=r"(a) : "l"(p));
    return a;
}
#define SWZ128(off) ((off) ^ (((off) >> 3) & 0x70))

__device__ __forceinline__ void ldmx4(uint32_t* t, uint32_t addr) {
    asm volatile("ldmatrix.sync.aligned.m8n8.x4.shared.b16 {%0,%1,%2,%3}, [%4];"
                 : "=r"(t[0]), "=r"(t[1]), "=r"(t[2]), "=r"(t[3]) : "r"(addr));
}
__device__ __forceinline__ void mma_f16(float* d, const uint32_t* a, const uint32_t* b) {
    asm volatile(
        "mma.sync.aligned.m16n8k16.row.col.f32.f16.f16.f32 "
        "{%0,%1,%2,%3}, {%4,%5,%6,%7}, {%8,%9}, {%0,%1,%2,%3};"
        : "+f"(d[0]), "+f"(d[1]), "+f"(d[2]), "+f"(d[3])
        : "r"(a[0]), "r"(a[1]), "r"(a[2]), "r"(a[3]), "r"(b[0]), "r"(b[1]));
}
__device__ __forceinline__ void cp_async16(uint32_t dst, const void* src) {
    asm volatile("cp.async.cg.shared.global [%0], [%1], 16;"
                 :: "r"(dst), "l"(src) : "memory");
}
__device__ __forceinline__ void cp_commit() {
    asm volatile("cp.async.commit_group;" ::: "memory");
}
template <int N>
__device__ __forceinline__ void cp_wait() {
    asm volatile("cp.async.wait_group %0;" :: "n"(N) : "memory");
}

// ---------------- gather index builder ----------------
__global__ void build_idx_kernel(const int* __restrict__ in_seq,
                                 const int* __restrict__ tg_seq,
                                 int* __restrict__ idx, int mode) {
    int m = blockIdx.x * 256 + threadIdx.x;
    if (m >= 2048) return;
    int b = m & 31, t = m >> 5;
    if (mode == 0) idx[m] = in_seq[b * 64 + t];
    else           idx[m] = (t == 0) ? 0 : tg_seq[b * 64 + t - 1];
}

// ------- f32 -> fp16 single into SW128 swizzled 128x64 tiles --------------
__global__ __launch_bounds__(256)
void convert_single_f16_kernel(const float* __restrict__ src,
                               char* __restrict__ dst) {
    const int tid = threadIdx.x;
    const int rb = blockIdx.x * 128;
    const int kc = blockIdx.y * 64;
    const size_t tb = ((size_t)blockIdx.x * 8 + blockIdx.y) * 16384;
#pragma unroll
    for (int it = 0; it < 8; it++) {
        const int idx = tid + it * 256;
        const int r  = idx >> 4;
        const int c4 = idx & 15;
        float4 v = *(const float4*)(src + (size_t)(rb + r) * 512 + kc + c4 * 4);
        __half2 h01 = __floats2half2_rn(v.x, v.y);
        __half2 h23 = __floats2half2_rn(v.z, v.w);
        const uint32_t sw = SWZ128((uint32_t)(r * 128 + (c4 >> 1) * 16)) + (c4 & 1) * 8;
        *(__half2*)(dst + tb + sw)     = h01;
        *(__half2*)(dst + tb + sw + 4) = h23;
    }
}

// ---------------- SGEMM-NT: C[M,N] = A[M,K] * B[N,K]^T (+bias) ------------
__global__ __launch_bounds__(256)
void gemm_nt_kernel(const float* __restrict__ A, int lda,
                    const float* __restrict__ Bm, int ldb,
                    const float* __restrict__ bias,
                    float* __restrict__ C, int N, int K,
                    const int* __restrict__ gidx, int outmode) {
    const int tid = threadIdx.x;
    const int bn = blockIdx.x * 128;
    const int bm = blockIdx.y * 128;
    __shared__ float As[2][16][132];
    __shared__ float Bs[2][16][132];
    const int tx = tid & 15, ty = tid >> 4;
    float acc[8][8];
#pragma unroll
    for (int i = 0; i < 8; i++)
#pragma unroll
        for (int j = 0; j < 8; j++) acc[i][j] = 0.f;

    const int lrow = tid >> 1;
    const int lk   = (tid & 1) * 8;
    int arow = gidx ? gidx[bm + lrow] : (bm + lrow);
    const float* Ap = A  + (size_t)arow        * lda + lk;
    const float* Bp = Bm + (size_t)(bn + lrow) * ldb + lk;

    {
        float4 a0 = *(const float4*)(Ap);
        float4 a1 = *(const float4*)(Ap + 4);
        float4 b0 = *(const float4*)(Bp);
        float4 b1 = *(const float4*)(Bp + 4);
        As[0][lk+0][lrow]=a0.x; As[0][lk+1][lrow]=a0.y; As[0][lk+2][lrow]=a0.z; As[0][lk+3][lrow]=a0.w;
        As[0][lk+4][lrow]=a1.x; As[0][lk+5][lrow]=a1.y; As[0][lk+6][lrow]=a1.z; As[0][lk+7][lrow]=a1.w;
        Bs[0][lk+0][lrow]=b0.x; Bs[0][lk+1][lrow]=b0.y; Bs[0][lk+2][lrow]=b0.z; Bs[0][lk+3][lrow]=b0.w;
        Bs[0][lk+4][lrow]=b1.x; Bs[0][lk+5][lrow]=b1.y; Bs[0][lk+6][lrow]=b1.z; Bs[0][lk+7][lrow]=b1.w;
    }
    __syncthreads();
    int buf = 0;
    for (int kc = 0; kc < K; kc += 16) {
        if (kc + 16 < K) {
            float4 a0 = *(const float4*)(Ap + kc + 16);
            float4 a1 = *(const float4*)(Ap + kc + 20);
            float4 b0 = *(const float4*)(Bp + kc + 16);
            float4 b1 = *(const float4*)(Bp + kc + 20);
            const int nb = buf ^ 1;
            As[nb][lk+0][lrow]=a0.x; As[nb][lk+1][lrow]=a0.y; As[nb][lk+2][lrow]=a0.z; As[nb][lk+3][lrow]=a0.w;
            As[nb][lk+4][lrow]=a1.x; As[nb][lk+5][lrow]=a1.y; As[nb][lk+6][lrow]=a1.z; As[nb][lk+7][lrow]=a1.w;
            Bs[nb][lk+0][lrow]=b0.x; Bs[nb][lk+1][lrow]=b0.y; Bs[nb][lk+2][lrow]=b0.z; Bs[nb][lk+3][lrow]=b0.w;
            Bs[nb][lk+4][lrow]=b1.x; Bs[nb][lk+5][lrow]=b1.y; Bs[nb][lk+6][lrow]=b1.z; Bs[nb][lk+7][lrow]=b1.w;
        }
#pragma unroll
        for (int kk = 0; kk < 16; kk++) {
            float4 alo = *(const float4*)&As[buf][kk][ty * 4];
            float4 ahi = *(const float4*)&As[buf][kk][64 + ty * 4];
            float4 blo = *(const float4*)&Bs[buf][kk][tx * 4];
            float4 bhi = *(const float4*)&Bs[buf][kk][64 + tx * 4];
            float a[8] = {alo.x, alo.y, alo.z, alo.w, ahi.x, ahi.y, ahi.z, ahi.w};
            float b[8] = {blo.x, blo.y, blo.z, blo.w, bhi.x, bhi.y, bhi.z, bhi.w};
#pragma unroll
            for (int i = 0; i < 8; i++)
#pragma unroll
                for (int j = 0; j < 8; j++)
                    acc[i][j] = fmaf(a[i], b[j], acc[i][j]);
        }
        __syncthreads();
        buf ^= 1;
    }
#pragma unroll
    for (int i = 0; i < 8; i++) {
        const int m = bm + ((i < 4) ? (ty * 4 + i) : (64 + ty * 4 + i - 4));
        const int orow = (outmode == 1) ? ((m & 31) * 64 + (m >> 5)) : m;
        float* crow = C + (size_t)orow * N;
#pragma unroll
        for (int j = 0; j < 8; j++) {
            const int n = bn + ((j < 4) ? (tx * 4 + j) : (64 + tx * 4 + j - 4));
            float v = acc[i][j];
            if (bias) v += bias[n];
            crow[n] = v;
        }
    }
}

// ====== logits GEMM: single-pass fp16 mma.sync ======
#define LM_TOT 65536

__global__ __launch_bounds__(256, 2)
void logits_mma_kernel(const char* __restrict__ Aw,
                       const char* __restrict__ Bw,
                       const float* __restrict__ bias,
                       float* __restrict__ out) {
    extern __shared__ char smem[];
    const uint32_t sb = smem_u32(smem);
    const int tid  = threadIdx.x;
    const int wid  = tid >> 5;
    const int lane = tid & 31;
    const int mt = blockIdx.y;
    const int nt = blockIdx.x;
    const int bm = mt * 128;
    const int bn = nt * 128;
    const int wm = (wid & 3) * 32;
    const int wn = (wid >> 2) * 64;

    float acc[2][8][4];
#pragma unroll
    for (int mi = 0; mi < 2; mi++)
#pragma unroll
        for (int ni = 0; ni < 8; ni++)
#pragma unroll
            for (int e = 0; e < 4; e++) acc[mi][ni][e] = 0.f;

    const int lrow = lane & 15;
    const int lcol16 = lane >> 4;

    auto prefetch = [&](int ch, int buf) {
        const char* srcs[2] = {
            Aw + ((size_t)mt * 8 + ch) * 16384,
            Bw + ((size_t)nt * 8 + ch) * 16384 };
#pragma unroll
        for (int t = 0; t < 2; t++) {
            const char* s = srcs[t] + tid * 16;
            const uint32_t d = sb + buf * 32768 + t * 16384 + tid * 16;
#pragma unroll
            for (int i = 0; i < 4; i++)
                cp_async16(d + i * 4096, s + i * 4096);
        }
        cp_commit();
    };

    prefetch(0, 0);
    int buf = 0;
    for (int ch = 0; ch < 8; ch++) {
        if (ch < 7) {
            prefetch(ch + 1, buf ^ 1);
            cp_wait<1>();
        } else {
            cp_wait<0>();
        }
        __syncthreads();

        const uint32_t base = sb + buf * 32768;
#pragma unroll
        for (int ks = 0; ks < 4; ks++) {
            uint32_t aw[2][4];
#pragma unroll
            for (int mi = 0; mi < 2; mi++) {
                const uint32_t off =
                    SWZ128((uint32_t)((wm + mi * 16 + lrow) * 128 + ks * 32 + lcol16 * 16));
                ldmx4(aw[mi], base + off);
            }
            uint32_t bw[8][2];
#pragma unroll
            for (int nj = 0; nj < 4; nj++) {
                const uint32_t off =
                    SWZ128((uint32_t)((wn + nj * 16 + lrow) * 128 + ks * 32 + lcol16 * 16));
                uint32_t t[4];
                ldmx4(t, base + 16384 + off);
                bw[nj*2][0] = t[0]; bw[nj*2+1][0] = t[1];
                bw[nj*2][1] = t[2]; bw[nj*2+1][1] = t[3];
            }
#pragma unroll
            for (int mi = 0; mi < 2; mi++)
#pragma unroll
                for (int ni = 0; ni < 8; ni++)
                    mma_f16(acc[mi][ni], aw[mi], bw[ni]);
        }
        __syncthreads();
        buf ^= 1;
    }

#pragma unroll
    for (int mi = 0; mi < 2; mi++) {
        const int m0 = bm + wm + mi * 16 + (lane >> 2);
        const int m1 = m0 + 8;
        const int or0 = (m0 & 31) * 64 + (m0 >> 5);
        const int or1 = (m1 & 31) * 64 + (m1 >> 5);
#pragma unroll
        for (int ni = 0; ni < 8; ni++) {
            const int n = bn + wn + ni * 8 + (lane & 3) * 2;
            const float b0 = bias[n], b1 = bias[n + 1];
            float2 v0 = make_float2(acc[mi][ni][0] + b0, acc[mi][ni][1] + b1);
            float2 v1 = make_float2(acc[mi][ni][2] + b0, acc[mi][ni][3] + b1);
            *(float2*)(out + (size_t)or0 * 32000 + n) = v0;
            *(float2*)(out + (size_t)or1 * 32000 + n) = v1;
        }
    }
}

// ================= encoder machinery (12-row, 256 threads) ================
struct Part {
    const float* W;
    int ldW;
    int wco;
    const float* src;
};

template<int NP, bool XSEC>
__device__ __forceinline__ void accum12(
    float (&acc)[12][4], float (&accx)[4][4],
    Part P, int jbase, int b0, int lane)
{
    const float* Wb = P.W + P.wco;
#pragma unroll
    for (int ps = 0; ps < NP; ps++) {
        const int k = ps * 128 + lane * 4;
        float4 s[4];
#pragma unroll
        for (int bi = 0; bi < 4; bi++)
            s[bi] = __ldcg((const float4*)(P.src + (b0 + bi) * 512 + k));
#pragma unroll
        for (int r = 0; r < 12; r++) {
            const int row = (r >> 2) * 512 + jbase + (r & 3);
            float4 wv = *(const float4*)(Wb + (size_t)row * P.ldW + k);
            float* a = (XSEC && r >= 8) ? accx[r - 8] : acc[r];
#pragma unroll
            for (int bi = 0; bi < 4; bi++) {
                a[bi] = fmaf(s[bi].x, wv.x, a[bi]);
                a[bi] = fmaf(s[bi].y, wv.y, a[bi]);
                a[bi] = fmaf(s[bi].z, wv.z, a[bi]);
                a[bi] = fmaf(s[bi].w, wv.w, a[bi]);
            }
        }
    }
}

template<int NP0, int NP1, int MODE>  // MODE: 0=enc(gi_pre), 2=bx+x
__device__ __forceinline__ void gru_phase12(
    int jbase, Part p0, Part p1,
    const float* __restrict__ gi_pre, const float* __restrict__ bx,
    const float* __restrict__ bh, const float* __restrict__ hprev,
    float* __restrict__ hnext, float* __restrict__ yout, int yb)
{
    const int lane = threadIdx.x & 31;
    const int w    = threadIdx.x >> 5;
    const int b0   = w * 4;
    float acc[12][4];
    float accx[4][4];
#pragma unroll
    for (int r = 0; r < 12; r++)
#pragma unroll
        for (int bi = 0; bi < 4; bi++) acc[r][bi] = 0.f;
#pragma unroll
    for (int r = 0; r < 4; r++)
#pragma unroll
        for (int bi = 0; bi < 4; bi++) accx[r][bi] = 0.f;

    accum12<NP0, false>(acc, accx, p0, jbase, b0, lane);
    if (NP1 > 0) accum12<NP1, true>(acc, accx, p1, jbase, b0, lane);

#pragma unroll
    for (int r = 0; r < 12; r++)
#pragma unroll
        for (int bi = 0; bi < 4; bi++)
#pragma unroll
            for (int o = 16; o; o >>= 1)
                acc[r][bi] += __shfl_xor_sync(0xffffffffu, acc[r][bi], o);
    if (NP1 > 0) {
#pragma unroll
        for (int r = 0; r < 4; r++)
#pragma unroll
            for (int bi = 0; bi < 4; bi++)
#pragma unroll
                for (int o = 16; o; o >>= 1)
                    accx[r][bi] += __shfl_xor_sync(0xffffffffu, accx[r][bi], o);
    }

    if (lane < 4) {
        const int jl = lane, j = jbase + jl;
        const float bh0 = bh[j], bh1 = bh[512 + j], bh2 = bh[1024 + j];
#pragma unroll
        for (int bi = 0; bi < 4; bi++) {
            const int b = b0 + bi;
            float pr, pz, gin, ghn;
            if (MODE == 0) {
                pr  = gi_pre[b * 1536 + j]        + acc[jl][bi]     + bh0;
                pz  = gi_pre[b * 1536 + 512 + j]  + acc[4 + jl][bi] + bh1;
                gin = gi_pre[b * 1536 + 1024 + j];
                ghn = acc[8 + jl][bi] + bh2;
            } else {
                pr  = bx[j]        + acc[jl][bi]     + bh0;
                pz  = bx[512 + j]  + acc[4 + jl][bi] + bh1;
                gin = bx[1024 + j] + accx[jl][bi];
                ghn = acc[8 + jl][bi] + bh2;
            }
            float r = sigm(pr);
            float z = sigm(pz);
            float n = tanhf(gin + r * ghn);
            float hp = __ldcg(hprev + b * 512 + j);
            float hn = (1.f - z) * n + z * hp;
            hnext[b * 512 + j] = hn;
            if (yout) yout[b * yb + j] = hn;
        }
    }
}

// ---------------- fused encoder: layer0 step s + layer1 step s-1 ---------
__global__ __launch_bounds__(256, 1)
void enc_fused_kernel(const float* __restrict__ Wh0, const float* __restrict__ bh0,
                      const float* __restrict__ gi0,
                      const float* __restrict__ Wh1, const float* __restrict__ Wx1,
                      const float* __restrict__ bx1, const float* __restrict__ bh1) {
    unsigned eps = 0;
    const int jbase = blockIdx.x * 4;
    Part pd{nullptr, 0, 0, nullptr};
    for (int s = 0; s < 65; s++) {
        if (s < 64) {
            const int p0 = s & 1;
            Part ph{Wh0, 512, 0, g_hA + p0 * 16384};
            gru_phase12<4, 0, 0>(jbase, ph, pd, gi0 + (size_t)s * 49152, nullptr, bh0,
                                 g_hA + p0 * 16384, g_hA + (p0 ^ 1) * 16384,
                                 g_y0 + (size_t)s * 16384, 512);
        }
        if (s >= 1) {
            const int t1 = s - 1;
            const int p1 = t1 & 1;
            Part ph{Wh1, 512, 0, g_hB + p1 * 16384};
            Part px{Wx1, 512, 0, g_y0 + (size_t)t1 * 16384};
            gru_phase12<4, 4, 2>(jbase, ph, px, nullptr, bx1, bh1,
                                 g_hB + p1 * 16384, g_hB + (p1 ^ 1) * 16384,
                                 g_enc + (size_t)t1 * 512, 32768);
        }
        grid_bar(eps);
    }
}

// ================= decoder machinery (j-split, 512 threads) ===============
// warp w -> wg = w&7 (4 batches), jh = w>>3 (2 of 4 j).
template<int NP, bool XSEC>
__device__ __forceinline__ void accum_js(
    float (&acc)[6][4], float (&accx)[2][4],
    Part P, int jb2, int b0, int lane)
{
    const float* Wb = P.W + P.wco;
#pragma unroll
    for (int ps = 0; ps < NP; ps++) {
        const int k = ps * 128 + lane * 4;
        float4 s[4];
#pragma unroll
        for (int bi = 0; bi < 4; bi++)
            s[bi] = __ldcg((const float4*)(P.src + (b0 + bi) * 512 + k));
#pragma unroll
        for (int r = 0; r < 6; r++) {
            const int row = (r >> 1) * 512 + jb2 + (r & 1);
            float4 wv = *(const float4*)(Wb + (size_t)row * P.ldW + k);
            float* a = (XSEC && r >= 4) ? accx[r - 4] : acc[r];
#pragma unroll
            for (int bi = 0; bi < 4; bi++) {
                a[bi] = fmaf(s[bi].x, wv.x, a[bi]);
                a[bi] = fmaf(s[bi].y, wv.y, a[bi]);
                a[bi] = fmaf(s[bi].z, wv.z, a[bi]);
                a[bi] = fmaf(s[bi].w, wv.w, a[bi]);
            }
        }
    }
}

// ---- gh pass + store: recurrent gate dots (+bh) -> g_gh slice ------------
__device__ __forceinline__ void ghpass_store(
    int jbase, const float* __restrict__ Wh, const float* __restrict__ bh,
    const float* __restrict__ h, float* __restrict__ dst /* [3][32][512] */)
{
    const int lane = threadIdx.x & 31;
    const int w    = threadIdx.x >> 5;
    const int wg   = w & 7;
    const int jh   = w >> 3;
    const int b0   = wg * 4;
    const int jb2  = jbase + jh * 2;
    float acc[6][4];
    float dummy[2][4];
#pragma unroll
    for (int r = 0; r < 6; r++)
#pragma unroll
        for (int bi = 0; bi < 4; bi++) acc[r][bi] = 0.f;
    Part p{Wh, 512, 0, h};
    accum_js<4, false>(acc, dummy, p, jb2, b0, lane);
#pragma unroll
    for (int r = 0; r < 6; r++)
#pragma unroll
        for (int bi = 0; bi < 4; bi++)
#pragma unroll
            for (int o = 16; o; o >>= 1)
                acc[r][bi] += __shfl_xor_sync(0xffffffffu, acc[r][bi], o);
    if (lane < 2) {
        const int jl2 = lane, j = jb2 + jl2;
#pragma unroll
        for (int g = 0; g < 3; g++) {
            const float bb = bh[g * 512 + j];
#pragma unroll
            for (int bi = 0; bi < 4; bi++)
                dst[g * 16384 + (b0 + bi) * 512 + j] = acc[g * 2 + jl2][bi] + bb;
        }
    }
}

// ---- x-only GRU phase: x-part accum + gates using precomputed gh ---------
template<int MODE>  // 3: gi_pre + gh ; 4: bx + gh
__device__ __forceinline__ void gru_x_phase(
    int jbase, Part p1,
    const float* __restrict__ gi_pre, const float* __restrict__ bx,
    const float* __restrict__ gh /* [3][32][512] */,
    const float* __restrict__ hprev, float* __restrict__ hnext,
    float* __restrict__ yout, int yb)
{
    const int lane = threadIdx.x & 31;
    const int w    = threadIdx.x >> 5;
    const int wg   = w & 7;
    const int jh   = w >> 3;
    const int b0   = wg * 4;
    const int jb2  = jbase + jh * 2;
    float acc[6][4];
    float accx[2][4];
#pragma unroll
    for (int r = 0; r < 6; r++)
#pragma unroll
        for (int bi = 0; bi < 4; bi++) acc[r][bi] = 0.f;
#pragma unroll
    for (int r = 0; r < 2; r++)
#pragma unroll
        for (int bi = 0; bi < 4; bi++) accx[r][bi] = 0.f;

    accum_js<4, true>(acc, accx, p1, jb2, b0, lane);

#pragma unroll
    for (int r = 0; r < 4; r++)
#pragma unroll
        for (int bi = 0; bi < 4; bi++)
#pragma unroll
            for (int o = 16; o; o >>= 1)
                acc[r][bi] += __shfl_xor_sync(0xffffffffu, acc[r][bi], o);
#pragma unroll
    for (int r = 0; r < 2; r++)
#pragma unroll
        for (int bi = 0; bi < 4; bi++)
#pragma unroll
            for (int o = 16; o; o >>= 1)
                accx[r][bi] += __shfl_xor_sync(0xffffffffu, accx[r][bi], o);

    if (lane < 2) {
        const int jl2 = lane, j = jb2 + jl2;
#pragma unroll
        for (int bi = 0; bi < 4; bi++) {
            const int b = b0 + bi;
            const float ghr = __ldcg(gh + b * 512 + j);
            const float ghz = __ldcg(gh + 16384 + b * 512 + j);
            const float ghn = __ldcg(gh + 32768 + b * 512 + j);
            float pr, pz, gin;
            if (MODE == 3) {
                pr  = gi_pre[b * 1536 + j]        + acc[jl2][bi]     + ghr;
                pz  = gi_pre[b * 1536 + 512 + j]  + acc[2 + jl2][bi] + ghz;
                gin = gi_pre[b * 1536 + 1024 + j] + accx[jl2][bi];
            } else {
                pr  = bx[j]        + acc[jl2][bi]     + ghr;
                pz  = bx[512 + j]  + acc[2 + jl2][bi] + ghz;
                gin = bx[1024 + j] + accx[jl2][bi];
            }
            float r = sigm(pr);
            float z = sigm(pz);
            float n = tanhf(gin + r * ghn);
            float hp = __ldcg(hprev + b * 512 + j);
            float hn = (1.f - z) * n + z * hp;
            hnext[b * 512 + j] = hn;
            if (yout) yout[b * yb + j] = hn;
        }
    }
}

// ---------------- decoder phase A: q = h1 @ W_attn[:, :512]^T ------------
__device__ __forceinline__ void phaseA(const float* __restrict__ h1,
                                       const float* __restrict__ Wa) {
    const int lane = threadIdx.x & 31;
    const int w    = threadIdx.x >> 5;
    const int wg   = w & 7;
    const int nh   = w >> 3;
    const int b0   = wg * 4;
    const int nb2  = blockIdx.x * 4 + nh * 2;
    float acc[2][4];
#pragma unroll
    for (int r = 0; r < 2; r++)
#pragma unroll
        for (int bi = 0; bi < 4; bi++) acc[r][bi] = 0.f;
#pragma unroll
    for (int ps = 0; ps < 4; ps++) {
        const int k = ps * 128 + lane * 4;
        float4 s[4];
#pragma unroll
        for (int bi = 0; bi < 4; bi++)
            s[bi] = __ldcg((const float4*)(h1 + (b0 + bi) * 512 + k));
#pragma unroll
        for (int r = 0; r < 2; r++) {
            float4 wv = *(const float4*)(Wa + (size_t)(nb2 + r) * 1024 + k);
#pragma unroll
            for (int bi = 0; bi < 4; bi++) {
                acc[r][bi] = fmaf(s[bi].x, wv.x, acc[r][bi]);
                acc[r][bi] = fmaf(s[bi].y, wv.y, acc[r][bi]);
                acc[r][bi] = fmaf(s[bi].z, wv.z, acc[r][bi]);
                acc[r][bi] = fmaf(s[bi].w, wv.w, acc[r][bi]);
            }
        }
    }
#pragma unroll
    for (int r = 0; r < 2; r++)
#pragma unroll
        for (int bi = 0; bi < 4; bi++)
#pragma unroll
            for (int o = 16; o; o >>= 1)
                acc[r][bi] += __shfl_xor_sync(0xffffffffu, acc[r][bi], o);
    if (lane < 2) {
#pragma unroll
        for (int bi = 0; bi < 4; bi++)
            g_q[(b0 + bi) * 512 + nb2 + lane] = acc[lane][bi];
    }
}

// ---------------- decoder phase B: scores -> softmax -> context ----------
__device__ __forceinline__ void phaseB(const float* __restrict__ v_attn) {
    __shared__ float qv[512];
    __shared__ float vv[512];
    __shared__ float sc[64];
    __shared__ float aw[64];
    const int b = blockIdx.x;
    const int tid = threadIdx.x;
    if (tid < 512) {
        qv[tid] = __ldcg(g_q + b * 512 + tid);
        vv[tid] = v_attn[tid];
    }
    __syncthreads();
    const int w = tid >> 5, lane = tid & 31;
    for (int ss = 0; ss < 4; ss++) {
        const int s = w * 4 + ss;
        const float* Urow = g_U + (size_t)(b * 64 + s) * 512;
        float p = 0.f;
        for (int n = lane; n < 512; n += 32)
            p += vv[n] * tanhf(qv[n] + Urow[n]);
#pragma unroll
        for (int o = 16; o; o >>= 1) p += __shfl_xor_sync(0xffffffffu, p, o);
        if (lane == 0) sc[s] = p;
    }
    __syncthreads();
    if (w == 0) {
        float v0 = sc[lane], v1 = sc[lane + 32];
        float mx = fmaxf(v0, v1);
#pragma unroll
        for (int o = 16; o; o >>= 1) mx = fmaxf(mx, __shfl_xor_sync(0xffffffffu, mx, o));
        float e0 = expf(v0 - mx), e1 = expf(v1 - mx);
        float sm = e0 + e1;
#pragma unroll
        for (int o = 16; o; o >>= 1) sm += __shfl_xor_sync(0xffffffffu, sm, o);
        float inv = 1.f / sm;
        aw[lane]      = e0 * inv;
        aw[lane + 32] = e1 * inv;
    }
    __syncthreads();
    if (tid < 512) {
        const float* erow = g_enc + (size_t)b * 64 * 512 + tid;
        float acc = 0.f;
#pragma unroll 8
        for (int s = 0; s < 64; s++) acc = fmaf(aw[s], erow[s * 512], acc);
        g_ctx[b * 512 + tid] = acc;
    }
}

// ---------------- persistent decoder (64 steps, 4 phases each) -----------
__global__ __launch_bounds__(512, 1)
void dec_persist_kernel(const float* __restrict__ Wa, const float* __restrict__ v_attn,
                        const float* __restrict__ Wh0, const float* __restrict__ Wx0,
                        const float* __restrict__ bh0,
                        const float* __restrict__ Wh1, const float* __restrict__ Wx1,
                        const float* __restrict__ bx1, const float* __restrict__ bh1) {
    unsigned eps = 0;
    const int jbase = blockIdx.x * 4;
    for (int t = 0; t < 64; t++) {
        const int par = t & 1;
        const float* h0 = g_hA + par * 16384;
        const float* h1 = g_hB + par * 16384;
        float* h0n = g_hA + (par ^ 1) * 16384;
        float* h1n = g_hB + (par ^ 1) * 16384;

        phaseA(h1, Wa);
        grid_bar(eps);

        if (blockIdx.x < 32) {
            phaseB(v_attn);
        } else {
            for (int u = blockIdx.x - 32; u < 256; u += 96) {
                const int layer = u >> 7;
                const int jb = (u & 127) * 4;
                if (layer == 0)
                    ghpass_store(jb, Wh0, bh0, h0, g_gh);
                else
                    ghpass_store(jb, Wh1, bh1, h1, g_gh + 49152);
            }
        }
        grid_bar(eps);

        {   // GRU d0 (x-only): ctx via Wx_d0 cols [256,768), gh from g_gh[0]
            Part px{Wx0, 768, 256, g_ctx};
            gru_x_phase<3>(jbase, px, g_gi + (size_t)t * 49152, nullptr,
                           g_gh, h0, h0n, nullptr, 0);
        }
        grid_bar(eps);

        {   // GRU d1 (x-only): h0' via Wx_d1, gh from g_gh[1]
            Part px{Wx1, 512, 0, h0n};
            gru_x_phase<4>(jbase, px, nullptr, bx1,
                           g_gh + 49152, h1, h1n, g_H1 + (size_t)t * 16384, 512);
        }
        grid_bar(eps);
    }
}

// ---------------- host orchestration ----------------
extern "C" void kernel_launch(void* const* d_in, const int* in_sizes, int n_in,
                              void* d_out, int out_size) {
    (void)in_sizes; (void)n_in; (void)out_size;
    const int*   in_seq = (const int*)d_in[0];
    const int*   tg_seq = (const int*)d_in[1];
    const float* E_enc  = (const float*)d_in[2];
    const float* Wx_e0  = (const float*)d_in[3];
    const float* Wh_e0  = (const float*)d_in[4];
    const float* bx_e0  = (const float*)d_in[5];
    const float* bh_e0  = (const float*)d_in[6];
    const float* Wx_e1  = (const float*)d_in[7];
    const float* Wh_e1  = (const float*)d_in[8];
    const float* bx_e1  = (const float*)d_in[9];
    const float* bh_e1  = (const float*)d_in[10];
    const float* E_dec  = (const float*)d_in[11];
    const float* W_attn = (const float*)d_in[12];
    const float* b_attn = (const float*)d_in[13];
    const float* v_attn = (const float*)d_in[14];
    const float* Wx_d0  = (const float*)d_in[15];
    const float* Wh_d0  = (const float*)d_in[16];
    const float* bx_d0  = (const float*)d_in[17];
    const float* bh_d0  = (const float*)d_in[18];
    const float* Wx_d1  = (const float*)d_in[19];
    const float* Wh_d1  = (const float*)d_in[20];
    const float* bx_d1  = (const float*)d_in[21];
    const float* bh_d1  = (const float*)d_in[22];
    const float* W_out  = (const float*)d_in[23];
    const float* b_out  = (const float*)d_in[24];
    float* out = (float*)d_out;

    float *gi, *y0, *enc, *U, *H1, *hA, *hB;
    int* idx;
    unsigned* bar;
    char *wf, *af;
    cudaGetSymbolAddress((void**)&gi,  g_gi);
    cudaGetSymbolAddress((void**)&y0,  g_y0);
    cudaGetSymbolAddress((void**)&enc, g_enc);
    cudaGetSymbolAddress((void**)&U,   g_U);
    cudaGetSymbolAddress((void**)&H1,  g_H1);
    cudaGetSymbolAddress((void**)&hA,  g_hA);
    cudaGetSymbolAddress((void**)&hB,  g_hB);
    cudaGetSymbolAddress((void**)&idx, g_idx);
    cudaGetSymbolAddress((void**)&bar, g_cnt);
    cudaGetSymbolAddress((void**)&wf,  g_W_f16);
    cudaGetSymbolAddress((void**)&af,  g_A_f16);

    cudaFuncSetAttribute(logits_mma_kernel,
                         cudaFuncAttributeMaxDynamicSharedMemorySize, LM_TOT);

    cudaMemsetAsync(hA, 0, 2 * 32 * 512 * sizeof(float));
    cudaMemsetAsync(hB, 0, 2 * 32 * 512 * sizeof(float));

    // ---- pre-convert W_out to fp16 swizzled tiles (one-time) ----
    convert_single_f16_kernel<<<dim3(250, 8), 256>>>(W_out, wf);

    // ---- encoder: gi_e0 GEMM, then fused 2-layer persistent kernel ----
    build_idx_kernel<<<8, 256>>>(in_seq, tg_seq, idx, 0);
    gemm_nt_kernel<<<dim3(12, 16), 256>>>(E_enc, 256, Wx_e0, 256, bx_e0,
                                          gi, 1536, 256, idx, 0);
    cudaMemsetAsync(bar, 0, sizeof(unsigned));
    enc_fused_kernel<<<NBLK, 256>>>(Wh_e0, bh_e0, gi,
                                    Wh_e1, Wx_e1, bx_e1, bh_e1);

    // U = enc_out @ W_attn[:, 512:]^T + b_attn
    gemm_nt_kernel<<<dim3(4, 16), 256>>>(enc, 512, W_attn + 512, 1024, b_attn,
                                         U, 512, 512, nullptr, 0);
    build_idx_kernel<<<8, 256>>>(in_seq, tg_seq, idx, 1);
    gemm_nt_kernel<<<dim3(12, 16), 256>>>(E_dec, 256, Wx_d0, 768, bx_d0,
                                          gi, 1536, 256, idx, 0);

    // ---- decoder persistent loop (512 threads, j-split) ----
    cudaMemsetAsync(bar, 0, sizeof(unsigned));
    dec_persist_kernel<<<NBLK, 512>>>(W_attn, v_attn,
                                      Wh_d0, Wx_d0, bh_d0,
                                      Wh_d1, Wx_d1, bx_d1, bh_d1);

    // ---- convert H1 to fp16 tiles, then logits (single-pass fp16) ----
    convert_single_f16_kernel<<<dim3(16, 8), 256>>>(H1, af);
    logits_mma_kernel<<<dim3(250, 16), 256, LM_TOT>>>(af, wf, b_out, out);
}

// round 17
// speedup vs baseline: 1.2468x; 1.0383x over previous
#include <cuda_runtime.h>
#include <cuda_fp16.h>
#include <cstdint>

#define NBLK 128

// ---------------- device scratch (no allocations allowed) ----------------
__device__ float g_gi [2048 * 1536];   // reused: gi_e0 -> gi_dec_emb
__device__ float g_y0 [2048 * 512];    // encoder layer0 outputs [s][b][512]
__device__ float g_enc[2048 * 512];    // encoder outputs [b][s][512]
__device__ float g_U  [2048 * 512];    // enc part of attn energy [b][s][512]
__device__ float g_H1 [2048 * 512];    // decoder top hidden per step [t][b][512]
__device__ float g_hA [2 * 32 * 512];  // layer0 / decoder h0 (ping-pong)
__device__ float g_hB [2 * 32 * 512];  // layer1 / decoder h1 (ping-pong)
__device__ float g_q  [32 * 512];
__device__ float g_ctx[32 * 512];
__device__ float g_gh [2 * 3 * 32 * 512]; // decoder recurrent gates (+bh)
__device__ int   g_idx[2048];
__device__ unsigned g_cnt;             // grid barrier epoch counter
// fp16 operand tiles (SW128-swizzled, 16KB per 128x64 tile)
__device__ __half g_W_f16[32000 * 512];   // W_out fp16 (single)
__device__ __half g_A_f16[2048 * 512];    // H1 fp16 (single)
__device__ __half g_AGh[2048 * 512],  g_AGl[2048 * 512];   // general A hi/lo
__device__ __half g_BGh[1536 * 256],  g_BGl[1536 * 256];   // general B hi/lo

// ---------------- grid-wide barrier (all NBLK blocks resident) ----------
__device__ __forceinline__ void grid_bar(unsigned &eps) {
    __syncthreads();
    if (threadIdx.x == 0) {
        eps += 1u;
        const unsigned need = eps * NBLK;
        __threadfence();
        atomicAdd(&g_cnt, 1u);
        unsigned v;
        do {
            asm volatile("ld.acquire.gpu.global.u32 %0, [%1];"
                         : "=r"(v) : "l"(&g_cnt));
        } while (v < need);
    }
    __syncthreads();
}

__device__ __forceinline__ float sigm(float x) { return 1.f / (1.f + expf(-x)); }

__device__ __forceinline__ uint32_t smem_u32(const void* p) {
    uint32_t a;
    asm("{ .reg .u64 t; cvta.to.shared.u64 t, %1; cvt.u32.u64 %0, t; }"
        : "=r"(a) : "l"(p));
    return a;
}
#define SWZ128(off) ((off) ^ (((off) >> 3) & 0x70))

__device__ __forceinline__ void ldmx4(uint32_t* t, uint32_t addr) {
    asm volatile("ldmatrix.sync.aligned.m8n8.x4.shared.b16 {%0,%1,%2,%3}, [%4];"
                 : "=r"(t[0]), "=r"(t[1]), "=r"(t[2]), "=r"(t[3]) : "r"(addr));
}
__device__ __forceinline__ void mma_f16(float* d, const uint32_t* a, const uint32_t* b) {
    asm volatile(
        "mma.sync.aligned.m16n8k16.row.col.f32.f16.f16.f32 "
        "{%0,%1,%2,%3}, {%4,%5,%6,%7}, {%8,%9}, {%0,%1,%2,%3};"
        : "+f"(d[0]), "+f"(d[1]), "+f"(d[2]), "+f"(d[3])
        : "r"(a[0]), "r"(a[1]), "r"(a[2]), "r"(a[3]), "r"(b[0]), "r"(b[1]));
}
__device__ __forceinline__ void cp_async16(uint32_t dst, const void* src) {
    asm volatile("cp.async.cg.shared.global [%0], [%1], 16;"
                 :: "r"(dst), "l"(src) : "memory");
}
__device__ __forceinline__ void cp_commit() {
    asm volatile("cp.async.commit_group;" ::: "memory");
}
template <int N>
__device__ __forceinline__ void cp_wait() {
    asm volatile("cp.async.wait_group %0;" :: "n"(N) : "memory");
}

// ---------------- gather index builder ----------------
__global__ void build_idx_kernel(const int* __restrict__ in_seq,
                                 const int* __restrict__ tg_seq,
                                 int* __restrict__ idx, int mode) {
    int m = blockIdx.x * 256 + threadIdx.x;
    if (m >= 2048) return;
    int b = m & 31, t = m >> 5;
    if (mode == 0) idx[m] = in_seq[b * 64 + t];
    else           idx[m] = (t == 0) ? 0 : tg_seq[b * 64 + t - 1];
}

// ------- f32 -> fp16 single into SW128 swizzled 128x64 tiles --------------
__global__ __launch_bounds__(256)
void convert_single_f16_kernel(const float* __restrict__ src,
                               char* __restrict__ dst) {
    const int tid = threadIdx.x;
    const int rb = blockIdx.x * 128;
    const int kc = blockIdx.y * 64;
    const size_t tb = ((size_t)blockIdx.x * 8 + blockIdx.y) * 16384;
#pragma unroll
    for (int it = 0; it < 8; it++) {
        const int idx = tid + it * 256;
        const int r  = idx >> 4;
        const int c4 = idx & 15;
        float4 v = *(const float4*)(src + (size_t)(rb + r) * 512 + kc + c4 * 4);
        __half2 h01 = __floats2half2_rn(v.x, v.y);
        __half2 h23 = __floats2half2_rn(v.z, v.w);
        const uint32_t sw = SWZ128((uint32_t)(r * 128 + (c4 >> 1) * 16)) + (c4 & 1) * 8;
        *(__half2*)(dst + tb + sw)     = h01;
        *(__half2*)(dst + tb + sw + 4) = h23;
    }
}

// ------- f32 -> fp16 hi/lo into SW128 tiles; optional gather; any lda -----
// grid: (rowtiles, KT). tile (rt, kt) stored at (rt*KT + kt)*16KB.
__global__ __launch_bounds__(256)
void convert_dual_kernel(const float* __restrict__ src, int lda,
                         const int* __restrict__ gidx,
                         char* __restrict__ dsthi, char* __restrict__ dstlo) {
    const int tid = threadIdx.x;
    const int rb = blockIdx.x * 128;
    const int kc = blockIdx.y * 64;
    const size_t tb = ((size_t)blockIdx.x * gridDim.y + blockIdx.y) * 16384;
#pragma unroll
    for (int it = 0; it < 8; it++) {
        const int idx = tid + it * 256;
        const int r  = idx >> 4;
        const int c4 = idx & 15;
        const int row = gidx ? gidx[rb + r] : (rb + r);
        float4 v = *(const float4*)(src + (size_t)row * lda + kc + c4 * 4);
        __half2 h01 = __floats2half2_rn(v.x, v.y);
        __half2 h23 = __floats2half2_rn(v.z, v.w);
        __half2 l01 = __floats2half2_rn(v.x - __half2float(h01.x),
                                        v.y - __half2float(h01.y));
        __half2 l23 = __floats2half2_rn(v.z - __half2float(h23.x),
                                        v.w - __half2float(h23.y));
        const uint32_t sw = SWZ128((uint32_t)(r * 128 + (c4 >> 1) * 16)) + (c4 & 1) * 8;
        *(__half2*)(dsthi + tb + sw)     = h01;
        *(__half2*)(dsthi + tb + sw + 4) = h23;
        *(__half2*)(dstlo + tb + sw)     = l01;
        *(__half2*)(dstlo + tb + sw + 4) = l23;
    }
}

// ====== mma3: C[M,N] = A@B^T + bias, fp16 hi/lo 3-pass (fp32-grade) ======
// Tiles pre-swizzled; grid (N/128, M/128); KT = K/64 chunks.
#define LM3_TOT 131072

__global__ __launch_bounds__(256, 1)
void mma3_nt_kernel(const char* __restrict__ Ah, const char* __restrict__ Al,
                    const char* __restrict__ Bh, const char* __restrict__ Bl,
                    const float* __restrict__ bias,
                    float* __restrict__ C, int N, int KT) {
    extern __shared__ char smem[];
    const uint32_t sb = smem_u32(smem);
    const int tid  = threadIdx.x;
    const int wid  = tid >> 5;
    const int lane = tid & 31;
    const int mt = blockIdx.y;
    const int nt = blockIdx.x;
    const int bm = mt * 128;
    const int bn = nt * 128;
    const int wm = (wid & 3) * 32;
    const int wn = (wid >> 2) * 64;

    float acc[2][8][4];
#pragma unroll
    for (int mi = 0; mi < 2; mi++)
#pragma unroll
        for (int ni = 0; ni < 8; ni++)
#pragma unroll
            for (int e = 0; e < 4; e++) acc[mi][ni][e] = 0.f;

    const int lrow = lane & 15;
    const int lcol16 = lane >> 4;

    auto prefetch = [&](int ch, int buf) {
        const char* srcs[4] = {
            Ah + ((size_t)mt * KT + ch) * 16384,
            Al + ((size_t)mt * KT + ch) * 16384,
            Bh + ((size_t)nt * KT + ch) * 16384,
            Bl + ((size_t)nt * KT + ch) * 16384 };
#pragma unroll
        for (int t = 0; t < 4; t++) {
            const char* s = srcs[t] + tid * 16;
            const uint32_t d = sb + buf * 65536 + t * 16384 + tid * 16;
#pragma unroll
            for (int i = 0; i < 4; i++)
                cp_async16(d + i * 4096, s + i * 4096);
        }
        cp_commit();
    };

    prefetch(0, 0);
    int buf = 0;
    for (int ch = 0; ch < KT; ch++) {
        if (ch + 1 < KT) {
            prefetch(ch + 1, buf ^ 1);
            cp_wait<1>();
        } else {
            cp_wait<0>();
        }
        __syncthreads();

        const uint32_t base = sb + buf * 65536;
#pragma unroll
        for (int ks = 0; ks < 4; ks++) {
            uint32_t ah[2][4], al[2][4];
#pragma unroll
            for (int mi = 0; mi < 2; mi++) {
                const uint32_t off =
                    SWZ128((uint32_t)((wm + mi * 16 + lrow) * 128 + ks * 32 + lcol16 * 16));
                ldmx4(ah[mi], base + off);
                ldmx4(al[mi], base + 16384 + off);
            }
            uint32_t bh[8][2], bl[8][2];
#pragma unroll
            for (int nj = 0; nj < 4; nj++) {
                const uint32_t off =
                    SWZ128((uint32_t)((wn + nj * 16 + lrow) * 128 + ks * 32 + lcol16 * 16));
                uint32_t t[4];
                ldmx4(t, base + 32768 + off);
                bh[nj*2][0] = t[0]; bh[nj*2+1][0] = t[1];
                bh[nj*2][1] = t[2]; bh[nj*2+1][1] = t[3];
                ldmx4(t, base + 49152 + off);
                bl[nj*2][0] = t[0]; bl[nj*2+1][0] = t[1];
                bl[nj*2][1] = t[2]; bl[nj*2+1][1] = t[3];
            }
#pragma unroll
            for (int mi = 0; mi < 2; mi++)
#pragma unroll
                for (int ni = 0; ni < 8; ni++) {
                    mma_f16(acc[mi][ni], ah[mi], bh[ni]);
                    mma_f16(acc[mi][ni], ah[mi], bl[ni]);
                    mma_f16(acc[mi][ni], al[mi], bh[ni]);
                }
        }
        __syncthreads();
        buf ^= 1;
    }

    // straight-layout epilogue with bias
#pragma unroll
    for (int mi = 0; mi < 2; mi++) {
        const int m0 = bm + wm + mi * 16 + (lane >> 2);
        const int m1 = m0 + 8;
#pragma unroll
        for (int ni = 0; ni < 8; ni++) {
            const int n = bn + wn + ni * 8 + (lane & 3) * 2;
            const float b0 = bias[n], b1 = bias[n + 1];
            float2 v0 = make_float2(acc[mi][ni][0] + b0, acc[mi][ni][1] + b1);
            float2 v1 = make_float2(acc[mi][ni][2] + b0, acc[mi][ni][3] + b1);
            *(float2*)(C + (size_t)m0 * N + n) = v0;
            *(float2*)(C + (size_t)m1 * N + n) = v1;
        }
    }
}

// ====== logits GEMM: single-pass fp16 mma.sync ======
#define LM_TOT 65536

__global__ __launch_bounds__(256, 2)
void logits_mma_kernel(const char* __restrict__ Aw,
                       const char* __restrict__ Bw,
                       const float* __restrict__ bias,
                       float* __restrict__ out) {
    extern __shared__ char smem[];
    const uint32_t sb = smem_u32(smem);
    const int tid  = threadIdx.x;
    const int wid  = tid >> 5;
    const int lane = tid & 31;
    const int mt = blockIdx.y;
    const int nt = blockIdx.x;
    const int bm = mt * 128;
    const int bn = nt * 128;
    const int wm = (wid & 3) * 32;
    const int wn = (wid >> 2) * 64;

    float acc[2][8][4];
#pragma unroll
    for (int mi = 0; mi < 2; mi++)
#pragma unroll
        for (int ni = 0; ni < 8; ni++)
#pragma unroll
            for (int e = 0; e < 4; e++) acc[mi][ni][e] = 0.f;

    const int lrow = lane & 15;
    const int lcol16 = lane >> 4;

    auto prefetch = [&](int ch, int buf) {
        const char* srcs[2] = {
            Aw + ((size_t)mt * 8 + ch) * 16384,
            Bw + ((size_t)nt * 8 + ch) * 16384 };
#pragma unroll
        for (int t = 0; t < 2; t++) {
            const char* s = srcs[t] + tid * 16;
            const uint32_t d = sb + buf * 32768 + t * 16384 + tid * 16;
#pragma unroll
            for (int i = 0; i < 4; i++)
                cp_async16(d + i * 4096, s + i * 4096);
        }
        cp_commit();
    };

    prefetch(0, 0);
    int buf = 0;
    for (int ch = 0; ch < 8; ch++) {
        if (ch < 7) {
            prefetch(ch + 1, buf ^ 1);
            cp_wait<1>();
        } else {
            cp_wait<0>();
        }
        __syncthreads();

        const uint32_t base = sb + buf * 32768;
#pragma unroll
        for (int ks = 0; ks < 4; ks++) {
            uint32_t aw[2][4];
#pragma unroll
            for (int mi = 0; mi < 2; mi++) {
                const uint32_t off =
                    SWZ128((uint32_t)((wm + mi * 16 + lrow) * 128 + ks * 32 + lcol16 * 16));
                ldmx4(aw[mi], base + off);
            }
            uint32_t bw[8][2];
#pragma unroll
            for (int nj = 0; nj < 4; nj++) {
                const uint32_t off =
                    SWZ128((uint32_t)((wn + nj * 16 + lrow) * 128 + ks * 32 + lcol16 * 16));
                uint32_t t[4];
                ldmx4(t, base + 16384 + off);
                bw[nj*2][0] = t[0]; bw[nj*2+1][0] = t[1];
                bw[nj*2][1] = t[2]; bw[nj*2+1][1] = t[3];
            }
#pragma unroll
            for (int mi = 0; mi < 2; mi++)
#pragma unroll
                for (int ni = 0; ni < 8; ni++)
                    mma_f16(acc[mi][ni], aw[mi], bw[ni]);
        }
        __syncthreads();
        buf ^= 1;
    }

#pragma unroll
    for (int mi = 0; mi < 2; mi++) {
        const int m0 = bm + wm + mi * 16 + (lane >> 2);
        const int m1 = m0 + 8;
        const int or0 = (m0 & 31) * 64 + (m0 >> 5);
        const int or1 = (m1 & 31) * 64 + (m1 >> 5);
#pragma unroll
        for (int ni = 0; ni < 8; ni++) {
            const int n = bn + wn + ni * 8 + (lane & 3) * 2;
            const float b0 = bias[n], b1 = bias[n + 1];
            float2 v0 = make_float2(acc[mi][ni][0] + b0, acc[mi][ni][1] + b1);
            float2 v1 = make_float2(acc[mi][ni][2] + b0, acc[mi][ni][3] + b1);
            *(float2*)(out + (size_t)or0 * 32000 + n) = v0;
            *(float2*)(out + (size_t)or1 * 32000 + n) = v1;
        }
    }
}

// ================= encoder machinery (12-row, 256 threads) ================
struct Part {
    const float* W;
    int ldW;
    int wco;
    const float* src;
};

template<int NP, bool XSEC>
__device__ __forceinline__ void accum12(
    float (&acc)[12][4], float (&accx)[4][4],
    Part P, int jbase, int b0, int lane)
{
    const float* Wb = P.W + P.wco;
#pragma unroll
    for (int ps = 0; ps < NP; ps++) {
        const int k = ps * 128 + lane * 4;
        float4 s[4];
#pragma unroll
        for (int bi = 0; bi < 4; bi++)
            s[bi] = __ldcg((const float4*)(P.src + (b0 + bi) * 512 + k));
#pragma unroll
        for (int r = 0; r < 12; r++) {
            const int row = (r >> 2) * 512 + jbase + (r & 3);
            float4 wv = *(const float4*)(Wb + (size_t)row * P.ldW + k);
            float* a = (XSEC && r >= 8) ? accx[r - 8] : acc[r];
#pragma unroll
            for (int bi = 0; bi < 4; bi++) {
                a[bi] = fmaf(s[bi].x, wv.x, a[bi]);
                a[bi] = fmaf(s[bi].y, wv.y, a[bi]);
                a[bi] = fmaf(s[bi].z, wv.z, a[bi]);
                a[bi] = fmaf(s[bi].w, wv.w, a[bi]);
            }
        }
    }
}

template<int NP0, int NP1, int MODE>  // MODE: 0=enc(gi_pre), 2=bx+x
__device__ __forceinline__ void gru_phase12(
    int jbase, Part p0, Part p1,
    const float* __restrict__ gi_pre, const float* __restrict__ bx,
    const float* __restrict__ bh, const float* __restrict__ hprev,
    float* __restrict__ hnext, float* __restrict__ yout, int yb)
{
    const int lane = threadIdx.x & 31;
    const int w    = threadIdx.x >> 5;
    const int b0   = w * 4;
    float acc[12][4];
    float accx[4][4];
#pragma unroll
    for (int r = 0; r < 12; r++)
#pragma unroll
        for (int bi = 0; bi < 4; bi++) acc[r][bi] = 0.f;
#pragma unroll
    for (int r = 0; r < 4; r++)
#pragma unroll
        for (int bi = 0; bi < 4; bi++) accx[r][bi] = 0.f;

    accum12<NP0, false>(acc, accx, p0, jbase, b0, lane);
    if (NP1 > 0) accum12<NP1, true>(acc, accx, p1, jbase, b0, lane);

#pragma unroll
    for (int r = 0; r < 12; r++)
#pragma unroll
        for (int bi = 0; bi < 4; bi++)
#pragma unroll
            for (int o = 16; o; o >>= 1)
                acc[r][bi] += __shfl_xor_sync(0xffffffffu, acc[r][bi], o);
    if (NP1 > 0) {
#pragma unroll
        for (int r = 0; r < 4; r++)
#pragma unroll
            for (int bi = 0; bi < 4; bi++)
#pragma unroll
                for (int o = 16; o; o >>= 1)
                    accx[r][bi] += __shfl_xor_sync(0xffffffffu, accx[r][bi], o);
    }

    if (lane < 4) {
        const int jl = lane, j = jbase + jl;
        const float bh0 = bh[j], bh1 = bh[512 + j], bh2 = bh[1024 + j];
#pragma unroll
        for (int bi = 0; bi < 4; bi++) {
            const int b = b0 + bi;
            float pr, pz, gin, ghn;
            if (MODE == 0) {
                pr  = gi_pre[b * 1536 + j]        + acc[jl][bi]     + bh0;
                pz  = gi_pre[b * 1536 + 512 + j]  + acc[4 + jl][bi] + bh1;
                gin = gi_pre[b * 1536 + 1024 + j];
                ghn = acc[8 + jl][bi] + bh2;
            } else {
                pr  = bx[j]        + acc[jl][bi]     + bh0;
                pz  = bx[512 + j]  + acc[4 + jl][bi] + bh1;
                gin = bx[1024 + j] + accx[jl][bi];
                ghn = acc[8 + jl][bi] + bh2;
            }
            float r = sigm(pr);
            float z = sigm(pz);
            float n = tanhf(gin + r * ghn);
            float hp = __ldcg(hprev + b * 512 + j);
            float hn = (1.f - z) * n + z * hp;
            hnext[b * 512 + j] = hn;
            if (yout) yout[b * yb + j] = hn;
        }
    }
}

// ---------------- fused encoder: layer0 step s + layer1 step s-1 ---------
__global__ __launch_bounds__(256, 1)
void enc_fused_kernel(const float* __restrict__ Wh0, const float* __restrict__ bh0,
                      const float* __restrict__ gi0,
                      const float* __restrict__ Wh1, const float* __restrict__ Wx1,
                      const float* __restrict__ bx1, const float* __restrict__ bh1) {
    unsigned eps = 0;
    const int jbase = blockIdx.x * 4;
    Part pd{nullptr, 0, 0, nullptr};
    for (int s = 0; s < 65; s++) {
        if (s < 64) {
            const int p0 = s & 1;
            Part ph{Wh0, 512, 0, g_hA + p0 * 16384};
            gru_phase12<4, 0, 0>(jbase, ph, pd, gi0 + (size_t)s * 49152, nullptr, bh0,
                                 g_hA + p0 * 16384, g_hA + (p0 ^ 1) * 16384,
                                 g_y0 + (size_t)s * 16384, 512);
        }
        if (s >= 1) {
            const int t1 = s - 1;
            const int p1 = t1 & 1;
            Part ph{Wh1, 512, 0, g_hB + p1 * 16384};
            Part px{Wx1, 512, 0, g_y0 + (size_t)t1 * 16384};
            gru_phase12<4, 4, 2>(jbase, ph, px, nullptr, bx1, bh1,
                                 g_hB + p1 * 16384, g_hB + (p1 ^ 1) * 16384,
                                 g_enc + (size_t)t1 * 512, 32768);
        }
        grid_bar(eps);
    }
}

// ================= decoder machinery (j-split, 512 threads) ===============
template<int NP, bool XSEC>
__device__ __forceinline__ void accum_js(
    float (&acc)[6][4], float (&accx)[2][4],
    Part P, int jb2, int b0, int lane)
{
    const float* Wb = P.W + P.wco;
#pragma unroll
    for (int ps = 0; ps < NP; ps++) {
        const int k = ps * 128 + lane * 4;
        float4 s[4];
#pragma unroll
        for (int bi = 0; bi < 4; bi++)
            s[bi] = __ldcg((const float4*)(P.src + (b0 + bi) * 512 + k));
#pragma unroll
        for (int r = 0; r < 6; r++) {
            const int row = (r >> 1) * 512 + jb2 + (r & 1);
            float4 wv = *(const float4*)(Wb + (size_t)row * P.ldW + k);
            float* a = (XSEC && r >= 4) ? accx[r - 4] : acc[r];
#pragma unroll
            for (int bi = 0; bi < 4; bi++) {
                a[bi] = fmaf(s[bi].x, wv.x, a[bi]);
                a[bi] = fmaf(s[bi].y, wv.y, a[bi]);
                a[bi] = fmaf(s[bi].z, wv.z, a[bi]);
                a[bi] = fmaf(s[bi].w, wv.w, a[bi]);
            }
        }
    }
}

__device__ __forceinline__ void ghpass_store(
    int jbase, const float* __restrict__ Wh, const float* __restrict__ bh,
    const float* __restrict__ h, float* __restrict__ dst /* [3][32][512] */)
{
    const int lane = threadIdx.x & 31;
    const int w    = threadIdx.x >> 5;
    const int wg   = w & 7;
    const int jh   = w >> 3;
    const int b0   = wg * 4;
    const int jb2  = jbase + jh * 2;
    float acc[6][4];
    float dummy[2][4];
#pragma unroll
    for (int r = 0; r < 6; r++)
#pragma unroll
        for (int bi = 0; bi < 4; bi++) acc[r][bi] = 0.f;
    Part p{Wh, 512, 0, h};
    accum_js<4, false>(acc, dummy, p, jb2, b0, lane);
#pragma unroll
    for (int r = 0; r < 6; r++)
#pragma unroll
        for (int bi = 0; bi < 4; bi++)
#pragma unroll
            for (int o = 16; o; o >>= 1)
                acc[r][bi] += __shfl_xor_sync(0xffffffffu, acc[r][bi], o);
    if (lane < 2) {
        const int jl2 = lane, j = jb2 + jl2;
#pragma unroll
        for (int g = 0; g < 3; g++) {
            const float bb = bh[g * 512 + j];
#pragma unroll
            for (int bi = 0; bi < 4; bi++)
                dst[g * 16384 + (b0 + bi) * 512 + j] = acc[g * 2 + jl2][bi] + bb;
        }
    }
}

template<int MODE>  // 3: gi_pre + gh ; 4: bx + gh
__device__ __forceinline__ void gru_x_phase(
    int jbase, Part p1,
    const float* __restrict__ gi_pre, const float* __restrict__ bx,
    const float* __restrict__ gh /* [3][32][512] */,
    const float* __restrict__ hprev, float* __restrict__ hnext,
    float* __restrict__ yout, int yb)
{
    const int lane = threadIdx.x & 31;
    const int w    = threadIdx.x >> 5;
    const int wg   = w & 7;
    const int jh   = w >> 3;
    const int b0   = wg * 4;
    const int jb2  = jbase + jh * 2;
    float acc[6][4];
    float accx[2][4];
#pragma unroll
    for (int r = 0; r < 6; r++)
#pragma unroll
        for (int bi = 0; bi < 4; bi++) acc[r][bi] = 0.f;
#pragma unroll
    for (int r = 0; r < 2; r++)
#pragma unroll
        for (int bi = 0; bi < 4; bi++) accx[r][bi] = 0.f;

    accum_js<4, true>(acc, accx, p1, jb2, b0, lane);

#pragma unroll
    for (int r = 0; r < 4; r++)
#pragma unroll
        for (int bi = 0; bi < 4; bi++)
#pragma unroll
            for (int o = 16; o; o >>= 1)
                acc[r][bi] += __shfl_xor_sync(0xffffffffu, acc[r][bi], o);
#pragma unroll
    for (int r = 0; r < 2; r++)
#pragma unroll
        for (int bi = 0; bi < 4; bi++)
#pragma unroll
            for (int o = 16; o; o >>= 1)
                accx[r][bi] += __shfl_xor_sync(0xffffffffu, accx[r][bi], o);

    if (lane < 2) {
        const int jl2 = lane, j = jb2 + jl2;
#pragma unroll
        for (int bi = 0; bi < 4; bi++) {
            const int b = b0 + bi;
            const float ghr = __ldcg(gh + b * 512 + j);
            const float ghz = __ldcg(gh + 16384 + b * 512 + j);
            const float ghn = __ldcg(gh + 32768 + b * 512 + j);
            float pr, pz, gin;
            if (MODE == 3) {
                pr  = gi_pre[b * 1536 + j]        + acc[jl2][bi]     + ghr;
                pz  = gi_pre[b * 1536 + 512 + j]  + acc[2 + jl2][bi] + ghz;
                gin = gi_pre[b * 1536 + 1024 + j] + accx[jl2][bi];
            } else {
                pr  = bx[j]        + acc[jl2][bi]     + ghr;
                pz  = bx[512 + j]  + acc[2 + jl2][bi] + ghz;
                gin = bx[1024 + j] + accx[jl2][bi];
            }
            float r = sigm(pr);
            float z = sigm(pz);
            float n = tanhf(gin + r * ghn);
            float hp = __ldcg(hprev + b * 512 + j);
            float hn = (1.f - z) * n + z * hp;
            hnext[b * 512 + j] = hn;
            if (yout) yout[b * yb + j] = hn;
        }
    }
}

// ---------------- decoder phase A: q = h1 @ W_attn[:, :512]^T ------------
__device__ __forceinline__ void phaseA(const float* __restrict__ h1,
                                       const float* __restrict__ Wa) {
    const int lane = threadIdx.x & 31;
    const int w    = threadIdx.x >> 5;
    const int wg   = w & 7;
    const int nh   = w >> 3;
    const int b0   = wg * 4;
    const int nb2  = blockIdx.x * 4 + nh * 2;
    float acc[2][4];
#pragma unroll
    for (int r = 0; r < 2; r++)
#pragma unroll
        for (int bi = 0; bi < 4; bi++) acc[r][bi] = 0.f;
#pragma unroll
    for (int ps = 0; ps < 4; ps++) {
        const int k = ps * 128 + lane * 4;
        float4 s[4];
#pragma unroll
        for (int bi = 0; bi < 4; bi++)
            s[bi] = __ldcg((const float4*)(h1 + (b0 + bi) * 512 + k));
#pragma unroll
        for (int r = 0; r < 2; r++) {
            float4 wv = *(const float4*)(Wa + (size_t)(nb2 + r) * 1024 + k);
#pragma unroll
            for (int bi = 0; bi < 4; bi++) {
                acc[r][bi] = fmaf(s[bi].x, wv.x, acc[r][bi]);
                acc[r][bi] = fmaf(s[bi].y, wv.y, acc[r][bi]);
                acc[r][bi] = fmaf(s[bi].z, wv.z, acc[r][bi]);
                acc[r][bi] = fmaf(s[bi].w, wv.w, acc[r][bi]);
            }
        }
    }
#pragma unroll
    for (int r = 0; r < 2; r++)
#pragma unroll
        for (int bi = 0; bi < 4; bi++)
#pragma unroll
            for (int o = 16; o; o >>= 1)
                acc[r][bi] += __shfl_xor_sync(0xffffffffu, acc[r][bi], o);
    if (lane < 2) {
#pragma unroll
        for (int bi = 0; bi < 4; bi++)
            g_q[(b0 + bi) * 512 + nb2 + lane] = acc[lane][bi];
    }
}

// ---------------- decoder phase B: scores -> softmax -> context ----------
__device__ __forceinline__ void phaseB(const float* __restrict__ v_attn) {
    __shared__ float qv[512];
    __shared__ float vv[512];
    __shared__ float sc[64];
    __shared__ float aw[64];
    const int b = blockIdx.x;
    const int tid = threadIdx.x;
    if (tid < 512) {
        qv[tid] = __ldcg(g_q + b * 512 + tid);
        vv[tid] = v_attn[tid];
    }
    __syncthreads();
    const int w = tid >> 5, lane = tid & 31;
    for (int ss = 0; ss < 4; ss++) {
        const int s = w * 4 + ss;
        const float* Urow = g_U + (size_t)(b * 64 + s) * 512;
        float p = 0.f;
        for (int n = lane; n < 512; n += 32)
            p += vv[n] * tanhf(qv[n] + Urow[n]);
#pragma unroll
        for (int o = 16; o; o >>= 1) p += __shfl_xor_sync(0xffffffffu, p, o);
        if (lane == 0) sc[s] = p;
    }
    __syncthreads();
    if (w == 0) {
        float v0 = sc[lane], v1 = sc[lane + 32];
        float mx = fmaxf(v0, v1);
#pragma unroll
        for (int o = 16; o; o >>= 1) mx = fmaxf(mx, __shfl_xor_sync(0xffffffffu, mx, o));
        float e0 = expf(v0 - mx), e1 = expf(v1 - mx);
        float sm = e0 + e1;
#pragma unroll
        for (int o = 16; o; o >>= 1) sm += __shfl_xor_sync(0xffffffffu, sm, o);
        float inv = 1.f / sm;
        aw[lane]      = e0 * inv;
        aw[lane + 32] = e1 * inv;
    }
    __syncthreads();
    if (tid < 512) {
        const float* erow = g_enc + (size_t)b * 64 * 512 + tid;
        float acc = 0.f;
#pragma unroll 8
        for (int s = 0; s < 64; s++) acc = fmaf(aw[s], erow[s * 512], acc);
        g_ctx[b * 512 + tid] = acc;
    }
}

// ---------------- persistent decoder (64 steps, 4 phases each) -----------
__global__ __launch_bounds__(512, 1)
void dec_persist_kernel(const float* __restrict__ Wa, const float* __restrict__ v_attn,
                        const float* __restrict__ Wh0, const float* __restrict__ Wx0,
                        const float* __restrict__ bh0,
                        const float* __restrict__ Wh1, const float* __restrict__ Wx1,
                        const float* __restrict__ bx1, const float* __restrict__ bh1) {
    unsigned eps = 0;
    const int jbase = blockIdx.x * 4;
    for (int t = 0; t < 64; t++) {
        const int par = t & 1;
        const float* h0 = g_hA + par * 16384;
        const float* h1 = g_hB + par * 16384;
        float* h0n = g_hA + (par ^ 1) * 16384;
        float* h1n = g_hB + (par ^ 1) * 16384;

        phaseA(h1, Wa);
        grid_bar(eps);

        if (blockIdx.x < 32) {
            phaseB(v_attn);
        } else {
            for (int u = blockIdx.x - 32; u < 256; u += 96) {
                const int layer = u >> 7;
                const int jb = (u & 127) * 4;
                if (layer == 0)
                    ghpass_store(jb, Wh0, bh0, h0, g_gh);
                else
                    ghpass_store(jb, Wh1, bh1, h1, g_gh + 49152);
            }
        }
        grid_bar(eps);

        {   // GRU d0 (x-only): ctx via Wx_d0 cols [256,768), gh from g_gh[0]
            Part px{Wx0, 768, 256, g_ctx};
            gru_x_phase<3>(jbase, px, g_gi + (size_t)t * 49152, nullptr,
                           g_gh, h0, h0n, nullptr, 0);
        }
        grid_bar(eps);

        {   // GRU d1 (x-only): h0' via Wx_d1, gh from g_gh[1]
            Part px{Wx1, 512, 0, h0n};
            gru_x_phase<4>(jbase, px, nullptr, bx1,
                           g_gh + 49152, h1, h1n, g_H1 + (size_t)t * 16384, 512);
        }
        grid_bar(eps);
    }
}

// ---------------- host orchestration ----------------
extern "C" void kernel_launch(void* const* d_in, const int* in_sizes, int n_in,
                              void* d_out, int out_size) {
    (void)in_sizes; (void)n_in; (void)out_size;
    const int*   in_seq = (const int*)d_in[0];
    const int*   tg_seq = (const int*)d_in[1];
    const float* E_enc  = (const float*)d_in[2];
    const float* Wx_e0  = (const float*)d_in[3];
    const float* Wh_e0  = (const float*)d_in[4];
    const float* bx_e0  = (const float*)d_in[5];
    const float* bh_e0  = (const float*)d_in[6];
    const float* Wx_e1  = (const float*)d_in[7];
    const float* Wh_e1  = (const float*)d_in[8];
    const float* bx_e1  = (const float*)d_in[9];
    const float* bh_e1  = (const float*)d_in[10];
    const float* E_dec  = (const float*)d_in[11];
    const float* W_attn = (const float*)d_in[12];
    const float* b_attn = (const float*)d_in[13];
    const float* v_attn = (const float*)d_in[14];
    const float* Wx_d0  = (const float*)d_in[15];
    const float* Wh_d0  = (const float*)d_in[16];
    const float* bx_d0  = (const float*)d_in[17];
    const float* bh_d0  = (const float*)d_in[18];
    const float* Wx_d1  = (const float*)d_in[19];
    const float* Wh_d1  = (const float*)d_in[20];
    const float* bx_d1  = (const float*)d_in[21];
    const float* bh_d1  = (const float*)d_in[22];
    const float* W_out  = (const float*)d_in[23];
    const float* b_out  = (const float*)d_in[24];
    float* out = (float*)d_out;

    float *gi, *enc, *U, *H1, *hA, *hB;
    int* idx;
    unsigned* bar;
    char *wf, *af, *agh, *agl, *bgh, *bgl;
    cudaGetSymbolAddress((void**)&gi,  g_gi);
    cudaGetSymbolAddress((void**)&enc, g_enc);
    cudaGetSymbolAddress((void**)&U,   g_U);
    cudaGetSymbolAddress((void**)&H1,  g_H1);
    cudaGetSymbolAddress((void**)&hA,  g_hA);
    cudaGetSymbolAddress((void**)&hB,  g_hB);
    cudaGetSymbolAddress((void**)&idx, g_idx);
    cudaGetSymbolAddress((void**)&bar, g_cnt);
    cudaGetSymbolAddress((void**)&wf,  g_W_f16);
    cudaGetSymbolAddress((void**)&af,  g_A_f16);
    cudaGetSymbolAddress((void**)&agh, g_AGh);
    cudaGetSymbolAddress((void**)&agl, g_AGl);
    cudaGetSymbolAddress((void**)&bgh, g_BGh);
    cudaGetSymbolAddress((void**)&bgl, g_BGl);

    cudaFuncSetAttribute(logits_mma_kernel,
                         cudaFuncAttributeMaxDynamicSharedMemorySize, LM_TOT);
    cudaFuncSetAttribute(mma3_nt_kernel,
                         cudaFuncAttributeMaxDynamicSharedMemorySize, LM3_TOT);

    cudaMemsetAsync(hA, 0, 2 * 32 * 512 * sizeof(float));
    cudaMemsetAsync(hB, 0, 2 * 32 * 512 * sizeof(float));

    // ---- pre-convert W_out to fp16 swizzled tiles (one-time) ----
    convert_single_f16_kernel<<<dim3(250, 8), 256>>>(W_out, wf);

    // ---- gi_e0 = gather(E_enc) @ Wx_e0^T + bx_e0 via mma3 ----
    build_idx_kernel<<<8, 256>>>(in_seq, tg_seq, idx, 0);
    convert_dual_kernel<<<dim3(16, 4), 256>>>(E_enc, 256, idx, agh, agl);
    convert_dual_kernel<<<dim3(12, 4), 256>>>(Wx_e0, 256, nullptr, bgh, bgl);
    mma3_nt_kernel<<<dim3(12, 16), 256, LM3_TOT>>>(agh, agl, bgh, bgl,
                                                   bx_e0, gi, 1536, 4);

    // ---- encoder persistent kernel ----
    cudaMemsetAsync(bar, 0, sizeof(unsigned));
    enc_fused_kernel<<<NBLK, 256>>>(Wh_e0, bh_e0, gi,
                                    Wh_e1, Wx_e1, bx_e1, bh_e1);

    // ---- U = enc @ W_attn[:, 512:]^T + b_attn via mma3 ----
    convert_dual_kernel<<<dim3(16, 8), 256>>>(enc, 512, nullptr, agh, agl);
    convert_dual_kernel<<<dim3(4, 8), 256>>>(W_attn + 512, 1024, nullptr, bgh, bgl);
    mma3_nt_kernel<<<dim3(4, 16), 256, LM3_TOT>>>(agh, agl, bgh, bgl,
                                                  b_attn, U, 512, 8);

    // ---- gi_dec = gather(E_dec) @ Wx_d0[:, :256]^T + bx_d0 via mma3 ----
    build_idx_kernel<<<8, 256>>>(in_seq, tg_seq, idx, 1);
    convert_dual_kernel<<<dim3(16, 4), 256>>>(E_dec, 256, idx, agh, agl);
    convert_dual_kernel<<<dim3(12, 4), 256>>>(Wx_d0, 768, nullptr, bgh, bgl);
    mma3_nt_kernel<<<dim3(12, 16), 256, LM3_TOT>>>(agh, agl, bgh, bgl,
                                                   bx_d0, gi, 1536, 4);

    // ---- decoder persistent loop (512 threads, j-split) ----
    cudaMemsetAsync(bar, 0, sizeof(unsigned));
    dec_persist_kernel<<<NBLK, 512>>>(W_attn, v_attn,
                                      Wh_d0, Wx_d0, bh_d0,
                                      Wh_d1, Wx_d1, bx_d1, bh_d1);

    // ---- convert H1 to fp16 tiles, then logits (single-pass fp16) ----
    convert_single_f16_kernel<<<dim3(16, 8), 256>>>(H1, af);
    logits_mma_kernel<<<dim3(250, 16), 256, LM_TOT>>>(af, wf, b_out, out);
}